// round 10
// baseline (speedup 1.0000x reference)
#include <cuda_runtime.h>
#include <math.h>
#include <float.h>

#define D_    1024
#define H_    16
#define HK_   8
#define HD_   64
#define FF_   3072
#define S_    1024
#define B_    4
#define TOK_  4096   // B*S
#define L_    4
#define WIN_  12

// ---------------- scratch (no allocations allowed) ----------------
__device__ float g_h   [TOK_ * D_];
__device__ float g_n   [TOK_ * D_];
__device__ float g_q   [TOK_ * H_  * HD_];
__device__ float g_k   [TOK_ * HK_ * HD_];
__device__ float g_v   [TOK_ * HK_ * HD_];
__device__ float g_att [TOK_ * H_  * HD_];
__device__ float g_gate[TOK_ * FF_];
__device__ float g_up  [TOK_ * FF_];

// ---------------- helpers ----------------
__device__ __forceinline__ unsigned f2tf(float x) {
    unsigned r;
    asm("cvt.rna.tf32.f32 %0, %1;" : "=r"(r) : "f"(x));
    return r;
}
__device__ __forceinline__ float tfr(float x) { return __uint_as_float(f2tf(x)); }
__device__ __forceinline__ void cpasync16(float* dst_smem, const float* src_gmem) {
    unsigned d = (unsigned)__cvta_generic_to_shared(dst_smem);
    asm volatile("cp.async.cg.shared.global [%0], [%1], 16;"
                 :: "r"(d), "l"(src_gmem));
}
#define CP_COMMIT()  asm volatile("cp.async.commit_group;")
#define CP_WAIT0()   asm volatile("cp.async.wait_group 0;")
#define CP_WAIT1()   asm volatile("cp.async.wait_group 1;")

#define MMA_TF32(acc, a, b)                                              \
    asm volatile(                                                        \
        "mma.sync.aligned.m16n8k8.row.col.f32.tf32.tf32.f32 "            \
        "{%0,%1,%2,%3}, {%4,%5,%6,%7}, {%8,%9}, {%0,%1,%2,%3};"          \
        : "+f"((acc)[0]), "+f"((acc)[1]), "+f"((acc)[2]), "+f"((acc)[3]) \
        : "r"((a)[0]), "r"((a)[1]), "r"((a)[2]), "r"((a)[3]),            \
          "r"((b)[0]), "r"((b)[1]))

// ---------------- rmsnorm over 1024 cols, 1 block per row ----------------
__global__ void rmsnorm_kernel(const float* __restrict__ x,
                               const float* __restrict__ w,
                               float* __restrict__ out) {
    int row = blockIdx.x;
    const float* xr = x + (size_t)row * D_;
    int t = threadIdx.x;               // 256 threads, 4 floats each
    float4 v = *(const float4*)(xr + t * 4);
    float ss = v.x * v.x + v.y * v.y + v.z * v.z + v.w * v.w;
    #pragma unroll
    for (int o = 16; o; o >>= 1) ss += __shfl_xor_sync(0xffffffffu, ss, o);
    __shared__ float sh[8];
    if ((t & 31) == 0) sh[t >> 5] = ss;
    __syncthreads();
    float tot = 0.f;
    #pragma unroll
    for (int i = 0; i < 8; i++) tot += sh[i];
    float scale = rsqrtf(tot * (1.0f / D_) + 1e-6f);
    float4 wv = *(const float4*)(w + t * 4);
    float4 o4;
    o4.x = v.x * scale * wv.x;
    o4.y = v.y * scale * wv.y;
    o4.z = v.z * scale * wv.z;
    o4.w = v.w * scale * wv.w;
    *(float4*)(out + (size_t)row * D_ + t * 4) = o4;
}

// ---------------- TF32 tensor-core GEMM (3-stage cp.async, BK=16, 8 warps) ----------------
#define AST_ 20
#define BST_ 136
#define STG_FLOATS (128 * AST_ + 16 * BST_)        // 4736 floats = 18944 B
#define GSMEM_BYTES (3 * STG_FLOATS * 4)           // 56832 B

template <bool ACC>
__device__ __forceinline__ void gemm_core(const float* __restrict__ A,
                                          const float* __restrict__ B,
                                          float* __restrict__ C,
                                          int N, int K, int bx, int by) {
    extern __shared__ float gsm[];

    int tid = threadIdx.x;
    int lane = tid & 31, wid = tid >> 5;
    int wr = wid >> 2;          // 0..1  (64-row slab)
    int wc = wid & 3;           // 0..3  (32-col slab)
    int tg = lane & 3;          // k index within fragment
    int grp = lane >> 2;        // m/n index within fragment

    const float* Ag = A + (size_t)(by * 128) * K;
    const float* Bg = B + bx * 128;

    int c0 = tid * 2, c1 = tid * 2 + 1;
    int ar0 = c0 >> 2, ac0 = (c0 & 3) << 2;
    int ar1 = c1 >> 2, ac1 = (c1 & 3) << 2;
    int br0 = c0 >> 5, bc0 = (c0 & 31) << 2;
    int br1 = c1 >> 5, bc1 = (c1 & 31) << 2;

    float acc[4][4][4];
    #pragma unroll
    for (int i = 0; i < 4; i++)
        #pragma unroll
        for (int j = 0; j < 4; j++)
            #pragma unroll
            for (int c = 0; c < 4; c++) acc[i][j][c] = 0.f;

    int nIter = K >> 4;

    // prologue: stages 0 and 1
    {
        float* As0 = gsm;
        float* Bs0 = gsm + 128 * AST_;
        cpasync16(&As0[ar0 * AST_ + ac0], Ag + (size_t)ar0 * K + ac0);
        cpasync16(&As0[ar1 * AST_ + ac1], Ag + (size_t)ar1 * K + ac1);
        cpasync16(&Bs0[br0 * BST_ + bc0], Bg + (size_t)br0 * N + bc0);
        cpasync16(&Bs0[br1 * BST_ + bc1], Bg + (size_t)br1 * N + bc1);
        CP_COMMIT();
        if (nIter > 1) {
            float* As1 = gsm + STG_FLOATS;
            float* Bs1 = As1 + 128 * AST_;
            cpasync16(&As1[ar0 * AST_ + ac0], Ag + (size_t)ar0 * K + 16 + ac0);
            cpasync16(&As1[ar1 * AST_ + ac1], Ag + (size_t)ar1 * K + 16 + ac1);
            cpasync16(&Bs1[br0 * BST_ + bc0], Bg + (size_t)(16 + br0) * N + bc0);
            cpasync16(&Bs1[br1 * BST_ + bc1], Bg + (size_t)(16 + br1) * N + bc1);
            CP_COMMIT();
        }
    }

    int cur = 0;
    for (int it = 0; it < nIter; it++) {
        if (it + 1 < nIter) { CP_WAIT1(); } else { CP_WAIT0(); }
        __syncthreads();   // stage `cur` ready; all warps done with stage loaded 3 ago

        if (it + 2 < nIter) {
            int nstg = cur + 2; if (nstg >= 3) nstg -= 3;
            float* Asn = gsm + nstg * STG_FLOATS;
            float* Bsn = Asn + 128 * AST_;
            int k0n = (it + 2) << 4;
            cpasync16(&Asn[ar0 * AST_ + ac0], Ag + (size_t)ar0 * K + k0n + ac0);
            cpasync16(&Asn[ar1 * AST_ + ac1], Ag + (size_t)ar1 * K + k0n + ac1);
            cpasync16(&Bsn[br0 * BST_ + bc0], Bg + (size_t)(k0n + br0) * N + bc0);
            cpasync16(&Bsn[br1 * BST_ + bc1], Bg + (size_t)(k0n + br1) * N + bc1);
            CP_COMMIT();
        }

        const float* Ac = gsm + cur * STG_FLOATS;
        const float* Bc = Ac + 128 * AST_;
        #pragma unroll
        for (int kk = 0; kk < 16; kk += 8) {
            unsigned afr[4][4], bfr[4][2];
            #pragma unroll
            for (int mt = 0; mt < 4; mt++) {
                int m = wr * 64 + mt * 16 + grp;
                afr[mt][0] = f2tf(Ac[m * AST_ + kk + tg]);
                afr[mt][1] = f2tf(Ac[(m + 8) * AST_ + kk + tg]);
                afr[mt][2] = f2tf(Ac[m * AST_ + kk + tg + 4]);
                afr[mt][3] = f2tf(Ac[(m + 8) * AST_ + kk + tg + 4]);
            }
            #pragma unroll
            for (int nt = 0; nt < 4; nt++) {
                int n = wc * 32 + nt * 8 + grp;
                bfr[nt][0] = f2tf(Bc[(kk + tg) * BST_ + n]);
                bfr[nt][1] = f2tf(Bc[(kk + tg + 4) * BST_ + n]);
            }
            #pragma unroll
            for (int mt = 0; mt < 4; mt++)
                #pragma unroll
                for (int nt = 0; nt < 4; nt++)
                    MMA_TF32(acc[mt][nt], afr[mt], bfr[nt]);
        }
        if (++cur == 3) cur = 0;
    }

    #pragma unroll
    for (int mt = 0; mt < 4; mt++) {
        int row0 = by * 128 + wr * 64 + mt * 16 + grp;
        #pragma unroll
        for (int nt = 0; nt < 4; nt++) {
            int col = bx * 128 + wc * 32 + nt * 8 + tg * 2;
            float* p0 = C + (size_t)row0 * N + col;
            float* p1 = C + (size_t)(row0 + 8) * N + col;
            if (ACC) {
                float2 cc0 = *(float2*)p0, cc1 = *(float2*)p1;
                cc0.x += acc[mt][nt][0]; cc0.y += acc[mt][nt][1];
                cc1.x += acc[mt][nt][2]; cc1.y += acc[mt][nt][3];
                *(float2*)p0 = cc0; *(float2*)p1 = cc1;
            } else {
                *(float2*)p0 = make_float2(acc[mt][nt][0], acc[mt][nt][1]);
                *(float2*)p1 = make_float2(acc[mt][nt][2], acc[mt][nt][3]);
            }
        }
    }
}

template <bool ACC>
__global__ void __launch_bounds__(256, 2)
gemm_tf32(const float* __restrict__ A, const float* __restrict__ B,
          float* __restrict__ C, int N, int K) {
    gemm_core<ACC>(A, B, C, N, K, blockIdx.x, blockIdx.y);
}

__global__ void __launch_bounds__(256, 2)
gemm_qkv(const float* __restrict__ A,
         const float* __restrict__ Wq, const float* __restrict__ Wk,
         const float* __restrict__ Wv,
         float* __restrict__ q, float* __restrict__ k, float* __restrict__ v) {
    int bx = blockIdx.x;
    if (bx < 8)       gemm_core<false>(A, Wq, q, 1024, D_, bx,      blockIdx.y);
    else if (bx < 12) gemm_core<false>(A, Wk, k,  512, D_, bx - 8,  blockIdx.y);
    else              gemm_core<false>(A, Wv, v,  512, D_, bx - 12, blockIdx.y);
}

__global__ void __launch_bounds__(256, 2)
gemm_gateup(const float* __restrict__ A,
            const float* __restrict__ Wg, const float* __restrict__ Wu,
            float* __restrict__ gate, float* __restrict__ up) {
    int bx = blockIdx.x;
    if (bx < 24) gemm_core<false>(A, Wg, gate, FF_, D_, bx,      blockIdx.y);
    else         gemm_core<false>(A, Wu, up,   FF_, D_, bx - 24, blockIdx.y);
}

// ---------------- fused per-head rmsnorm + RoPE for q AND k ----------------
#define LOG2_THETA 19.9315685693241741f
__global__ void qknorm_rope_kernel(float* __restrict__ q, float* __restrict__ k,
                                   const float* __restrict__ qw,
                                   const float* __restrict__ kw) {
    int warp = (blockIdx.x * blockDim.x + threadIdx.x) >> 5;
    int lane = threadIdx.x & 31;
    float* p; const float* w; int token;
    if (warp < TOK_ * H_) {
        p = q + (size_t)warp * HD_; w = qw; token = warp / H_;
    } else {
        int w2 = warp - TOK_ * H_;
        p = k + (size_t)w2 * HD_; w = kw; token = w2 / HK_;
    }
    int s = token & (S_ - 1);
    float a = p[lane], b = p[lane + 32];
    float ss = a * a + b * b;
    #pragma unroll
    for (int o = 16; o; o >>= 1) ss += __shfl_xor_sync(0xffffffffu, ss, o);
    float scale = rsqrtf(ss * (1.0f / HD_) + 1e-6f);
    a *= scale * w[lane];
    b *= scale * w[lane + 32];
    float inv = exp2f(-(float)lane * (LOG2_THETA / 32.0f));
    float ang = (float)s * inv;
    float c = cosf(ang), sn = sinf(ang);
    p[lane]      = a * c - b * sn;
    p[lane + 32] = b * c + a * sn;
}

// ---------------- tensor-core flash attention: 2 GQA heads per CTA ----------------
// 256 threads = 8 warps. Warps 0-3: head 2*kh, warps 4-7: head 2*kh+1.
// K/V tiles shared between head groups. Q frags register-hoisted.
#define QST 68
#define KST 68
#define VST 72
#define PST 36
#define ATT_SMEM ((2 * 64 * QST + 32 * KST + 32 * VST + 2 * 64 * PST + 32) * 4)
__global__ void __launch_bounds__(256, 2)
attn_mma_kernel(const float* __restrict__ q, const float* __restrict__ k,
                const float* __restrict__ v, const int* __restrict__ amask,
                float* __restrict__ out, int win) {
    extern __shared__ float asm_[];
    float* Qs = asm_;                       // 2 x 64 x QST
    float* Ks = Qs + 2 * 64 * QST;          // 32 x KST
    float* Vs = Ks + 32 * KST;              // 32 x VST
    float* Ps = Vs + 32 * VST;              // 2 x 64 x PST
    float* Mk = Ps + 2 * 64 * PST;          // 32

    int b = blockIdx.z, kh = blockIdx.y;
    int q0 = blockIdx.x * 64;
    int tid = threadIdx.x;
    int lane = tid & 31, wid = tid >> 5;
    int hg = wid >> 2;                      // head group 0/1
    int h = kh * 2 + hg;
    int m0 = (wid & 3) * 16;                // warp's q-row offset within 64-tile
    int tg = lane & 3, grp = lane >> 2;
    int qpos0 = q0 + m0 + grp;
    int qpos1 = qpos0 + 8;

    float* Qsh = Qs + hg * 64 * QST;
    float* Psh = Ps + hg * 64 * PST;

    // cooperative Q load for BOTH heads (tf32-rounded)
    for (int i = tid; i < 128 * 16; i += 256) {
        int r = i >> 4;                      // 0..127
        int hgi = r >> 6, rr = r & 63;
        int c4 = (i & 15) << 2;
        float4 f = *(const float4*)(q + (size_t)(b * S_ + q0 + rr) * (H_ * HD_)
                                      + (kh * 2 + hgi) * HD_ + c4);
        float* dst = Qs + hgi * 64 * QST + rr * QST + c4;
        dst[0] = tfr(f.x); dst[1] = tfr(f.y); dst[2] = tfr(f.z); dst[3] = tfr(f.w);
    }
    __syncthreads();

    // hoist Q fragments (invariant over K-tiles)
    unsigned qfr[8][4];
    #pragma unroll
    for (int s8 = 0; s8 < 8; s8++) {
        int k8 = s8 * 8;
        qfr[s8][0] = __float_as_uint(Qsh[(m0 + grp) * QST + k8 + tg]);
        qfr[s8][1] = __float_as_uint(Qsh[(m0 + grp + 8) * QST + k8 + tg]);
        qfr[s8][2] = __float_as_uint(Qsh[(m0 + grp) * QST + k8 + tg + 4]);
        qfr[s8][3] = __float_as_uint(Qsh[(m0 + grp + 8) * QST + k8 + tg + 4]);
    }

    float oacc[8][4];
    #pragma unroll
    for (int i = 0; i < 8; i++)
        #pragma unroll
        for (int j = 0; j < 4; j++) oacc[i][j] = 0.f;
    float mr0 = -1e30f, mr1 = -1e30f, l0 = 0.f, l1 = 0.f;

    int kt_lo = 0, kt_hi = (S_ / 32) - 1;
    if (win >= 0) {
        int lo = q0 - win; if (lo < 0) lo = 0;
        int hi = q0 + 63 + win; if (hi > S_ - 1) hi = S_ - 1;
        kt_lo = lo >> 5; kt_hi = hi >> 5;
    }
    const float scale = 0.125f;

    for (int kt = kt_lo; kt <= kt_hi; kt++) {
        // K/V tile load shared across both head groups (kv head = kh)
        for (int i = tid; i < 32 * 16; i += 256) {
            int r = i >> 4, c4 = (i & 15) << 2;
            size_t off = (size_t)(b * S_ + kt * 32 + r) * (HK_ * HD_) + kh * HD_ + c4;
            float4 fk = *(const float4*)(k + off);
            float4 fv = *(const float4*)(v + off);
            float* kd = Ks + r * KST + c4;
            float* vd = Vs + r * VST + c4;
            kd[0] = tfr(fk.x); kd[1] = tfr(fk.y); kd[2] = tfr(fk.z); kd[3] = tfr(fk.w);
            vd[0] = tfr(fv.x); vd[1] = tfr(fv.y); vd[2] = tfr(fv.z); vd[3] = tfr(fv.w);
        }
        if (tid < 32)
            Mk[tid] = (amask[b * S_ + kt * 32 + tid] != 0) ? 0.f : -1e30f;
        __syncthreads();

        // ---- QK^T ----
        float sc[4][4];
        #pragma unroll
        for (int i = 0; i < 4; i++)
            #pragma unroll
            for (int j = 0; j < 4; j++) sc[i][j] = 0.f;
        #pragma unroll
        for (int s8 = 0; s8 < 8; s8++) {
            int k8 = s8 * 8;
            #pragma unroll
            for (int nt = 0; nt < 4; nt++) {
                unsigned bb[2];
                bb[0] = __float_as_uint(Ks[(nt * 8 + grp) * KST + k8 + tg]);
                bb[1] = __float_as_uint(Ks[(nt * 8 + grp) * KST + k8 + tg + 4]);
                MMA_TF32(sc[nt], qfr[s8], bb);
            }
        }

        // ---- mask + online softmax ----
        float v0[8], v1[8];
        #pragma unroll
        for (int nt = 0; nt < 4; nt++) {
            int kc0 = nt * 8 + 2 * tg, kc1 = kc0 + 1;
            int kp0 = kt * 32 + kc0, kp1 = kt * 32 + kc1;
            float mk0 = Mk[kc0], mk1 = Mk[kc1];
            float a0 = sc[nt][0] * scale + mk0;
            float a1 = sc[nt][1] * scale + mk1;
            float b0 = sc[nt][2] * scale + mk0;
            float b1 = sc[nt][3] * scale + mk1;
            if (win >= 0) {
                if (abs(qpos0 - kp0) > win) a0 = -1e30f;
                if (abs(qpos0 - kp1) > win) a1 = -1e30f;
                if (abs(qpos1 - kp0) > win) b0 = -1e30f;
                if (abs(qpos1 - kp1) > win) b1 = -1e30f;
            }
            v0[nt * 2] = a0; v0[nt * 2 + 1] = a1;
            v1[nt * 2] = b0; v1[nt * 2 + 1] = b1;
        }
        float tm0 = -1e30f, tm1 = -1e30f;
        #pragma unroll
        for (int j = 0; j < 8; j++) { tm0 = fmaxf(tm0, v0[j]); tm1 = fmaxf(tm1, v1[j]); }
        tm0 = fmaxf(tm0, __shfl_xor_sync(0xffffffffu, tm0, 1));
        tm0 = fmaxf(tm0, __shfl_xor_sync(0xffffffffu, tm0, 2));
        tm1 = fmaxf(tm1, __shfl_xor_sync(0xffffffffu, tm1, 1));
        tm1 = fmaxf(tm1, __shfl_xor_sync(0xffffffffu, tm1, 2));
        float nm0 = fmaxf(mr0, tm0), nm1 = fmaxf(mr1, tm1);
        float al0 = __expf(mr0 - nm0), al1 = __expf(mr1 - nm1);
        mr0 = nm0; mr1 = nm1;
        float ps0 = 0.f, ps1 = 0.f;
        #pragma unroll
        for (int nt = 0; nt < 4; nt++) {
            float p00 = __expf(v0[nt * 2]     - nm0);
            float p01 = __expf(v0[nt * 2 + 1] - nm0);
            float p10 = __expf(v1[nt * 2]     - nm1);
            float p11 = __expf(v1[nt * 2 + 1] - nm1);
            ps0 += p00 + p01; ps1 += p10 + p11;
            int col = nt * 8 + 2 * tg;
            *(float2*)&Psh[(m0 + grp) * PST + col]     = make_float2(tfr(p00), tfr(p01));
            *(float2*)&Psh[(m0 + grp + 8) * PST + col] = make_float2(tfr(p10), tfr(p11));
        }
        ps0 += __shfl_xor_sync(0xffffffffu, ps0, 1);
        ps0 += __shfl_xor_sync(0xffffffffu, ps0, 2);
        ps1 += __shfl_xor_sync(0xffffffffu, ps1, 1);
        ps1 += __shfl_xor_sync(0xffffffffu, ps1, 2);
        l0 = l0 * al0 + ps0;
        l1 = l1 * al1 + ps1;
        #pragma unroll
        for (int nt = 0; nt < 8; nt++) {
            oacc[nt][0] *= al0; oacc[nt][1] *= al0;
            oacc[nt][2] *= al1; oacc[nt][3] *= al1;
        }
        __syncwarp();

        // ---- P @ V ----
        #pragma unroll
        for (int k8 = 0; k8 < 32; k8 += 8) {
            unsigned a[4];
            a[0] = __float_as_uint(Psh[(m0 + grp) * PST + k8 + tg]);
            a[1] = __float_as_uint(Psh[(m0 + grp + 8) * PST + k8 + tg]);
            a[2] = __float_as_uint(Psh[(m0 + grp) * PST + k8 + tg + 4]);
            a[3] = __float_as_uint(Psh[(m0 + grp + 8) * PST + k8 + tg + 4]);
            #pragma unroll
            for (int nt = 0; nt < 8; nt++) {
                unsigned bb[2];
                bb[0] = __float_as_uint(Vs[(k8 + tg) * VST + nt * 8 + grp]);
                bb[1] = __float_as_uint(Vs[(k8 + tg + 4) * VST + nt * 8 + grp]);
                MMA_TF32(oacc[nt], a, bb);
            }
        }
        __syncthreads();
    }

    float il0 = 1.0f / l0, il1 = 1.0f / l1;
    #pragma unroll
    for (int nt = 0; nt < 8; nt++) {
        int col = h * HD_ + nt * 8 + 2 * tg;
        float* p0 = out + (size_t)(b * S_ + qpos0) * (H_ * HD_) + col;
        float* p1 = out + (size_t)(b * S_ + qpos1) * (H_ * HD_) + col;
        *(float2*)p0 = make_float2(oacc[nt][0] * il0, oacc[nt][1] * il0);
        *(float2*)p1 = make_float2(oacc[nt][2] * il1, oacc[nt][3] * il1);
    }
}

// ---------------- SwiGLU elementwise (vectorized x4) ----------------
__global__ void silu_mul_kernel(float* __restrict__ gate,
                                const float* __restrict__ up, int n4) {
    int i = blockIdx.x * blockDim.x + threadIdx.x;
    if (i < n4) {
        float4 g = *(float4*)(gate + i * 4);
        float4 u = *(const float4*)(up + i * 4);
        g.x = g.x / (1.0f + __expf(-g.x)) * u.x;
        g.y = g.y / (1.0f + __expf(-g.y)) * u.y;
        g.z = g.z / (1.0f + __expf(-g.z)) * u.z;
        g.w = g.w / (1.0f + __expf(-g.w)) * u.w;
        *(float4*)(gate + i * 4) = g;
    }
}

// ---------------- host orchestration ----------------
extern "C" void kernel_launch(void* const* d_in, const int* in_sizes, int n_in,
                              void* d_out, int out_size) {
    const float* x      = (const float*)d_in[0];
    const float* wq     = (const float*)d_in[1];
    const float* wk     = (const float*)d_in[2];
    const float* wv     = (const float*)d_in[3];
    const float* wo     = (const float*)d_in[4];
    const float* qnw    = (const float*)d_in[5];
    const float* knw    = (const float*)d_in[6];
    const float* ln1    = (const float*)d_in[7];
    const float* ln2    = (const float*)d_in[8];
    const float* wg     = (const float*)d_in[9];
    const float* wu     = (const float*)d_in[10];
    const float* wd     = (const float*)d_in[11];
    const float* normw  = (const float*)d_in[12];
    const int*   amask  = (const int*)d_in[13];

    float *h, *n, *q, *k, *v, *att, *gate, *up;
    cudaGetSymbolAddress((void**)&h,    g_h);
    cudaGetSymbolAddress((void**)&n,    g_n);
    cudaGetSymbolAddress((void**)&q,    g_q);
    cudaGetSymbolAddress((void**)&k,    g_k);
    cudaGetSymbolAddress((void**)&v,    g_v);
    cudaGetSymbolAddress((void**)&att,  g_att);
    cudaGetSymbolAddress((void**)&gate, g_gate);
    cudaGetSymbolAddress((void**)&up,   g_up);

    cudaFuncSetAttribute(gemm_tf32<true>,
        cudaFuncAttributeMaxDynamicSharedMemorySize, GSMEM_BYTES);
    cudaFuncSetAttribute(gemm_tf32<false>,
        cudaFuncAttributeMaxDynamicSharedMemorySize, GSMEM_BYTES);
    cudaFuncSetAttribute(gemm_qkv,
        cudaFuncAttributeMaxDynamicSharedMemorySize, GSMEM_BYTES);
    cudaFuncSetAttribute(gemm_gateup,
        cudaFuncAttributeMaxDynamicSharedMemorySize, GSMEM_BYTES);
    cudaFuncSetAttribute(attn_mma_kernel,
        cudaFuncAttributeMaxDynamicSharedMemorySize, ATT_SMEM);

    cudaMemcpyAsync(h, x, (size_t)TOK_ * D_ * sizeof(float),
                    cudaMemcpyDeviceToDevice, 0);

    dim3 gQKV (16, TOK_ / 128);              // 512 blocks
    dim3 gGU  (48, TOK_ / 128);              // 1536 blocks
    dim3 g1024(D_ / 128, TOK_ / 128);        // 256 blocks
    int ropeWarps = TOK_ * (H_ + HK_);       // 98304 warps

    for (int l = 0; l < L_; l++) {
        const float* wq_l = wq + (size_t)l * D_ * H_ * HD_;
        const float* wk_l = wk + (size_t)l * D_ * HK_ * HD_;
        const float* wv_l = wv + (size_t)l * D_ * HK_ * HD_;
        const float* wo_l = wo + (size_t)l * H_ * HD_ * D_;
        const float* wg_l = wg + (size_t)l * D_ * FF_;
        const float* wu_l = wu + (size_t)l * D_ * FF_;
        const float* wd_l = wd + (size_t)l * FF_ * D_;

        rmsnorm_kernel<<<TOK_, 256>>>(h, ln1 + l * D_, n);

        gemm_qkv<<<gQKV, 256, GSMEM_BYTES>>>(n, wq_l, wk_l, wv_l, q, k, v);

        qknorm_rope_kernel<<<ropeWarps / 4, 128>>>(q, k, qnw + l * HD_, knw + l * HD_);

        attn_mma_kernel<<<dim3(S_ / 64, HK_, B_), 256, ATT_SMEM>>>(
            q, k, v, amask, att, (l & 1) ? WIN_ : -1);

        gemm_tf32<true><<<g1024, 256, GSMEM_BYTES>>>(att, wo_l, h, D_, H_ * HD_);

        rmsnorm_kernel<<<TOK_, 256>>>(h, ln2 + l * D_, n);

        gemm_gateup<<<gGU, 256, GSMEM_BYTES>>>(n, wg_l, wu_l, gate, up);

        int n4 = TOK_ * FF_ / 4;
        silu_mul_kernel<<<(n4 + 255) / 256, 256>>>(gate, up, n4);

        gemm_tf32<true><<<g1024, 256, GSMEM_BYTES>>>(gate, wd_l, h, D_, FF_);
    }

    rmsnorm_kernel<<<TOK_, 256>>>(h, normw, (float*)d_out);
}

// round 11
// speedup vs baseline: 1.1036x; 1.1036x over previous
#include <cuda_runtime.h>
#include <math.h>
#include <float.h>

#define D_    1024
#define H_    16
#define HK_   8
#define HD_   64
#define FF_   3072
#define S_    1024
#define B_    4
#define TOK_  4096   // B*S
#define L_    4
#define WIN_  12

// ---------------- scratch (no allocations allowed) ----------------
__device__ float g_h   [TOK_ * D_];
__device__ float g_n   [TOK_ * D_];
__device__ float g_q   [TOK_ * H_  * HD_];
__device__ float g_k   [TOK_ * HK_ * HD_];
__device__ float g_v   [TOK_ * HK_ * HD_];
__device__ float g_att [TOK_ * H_  * HD_];
__device__ float g_gate[TOK_ * FF_];
__device__ float g_up  [TOK_ * FF_];

// ---------------- helpers ----------------
__device__ __forceinline__ unsigned f2tf(float x) {
    unsigned r;
    asm("cvt.rna.tf32.f32 %0, %1;" : "=r"(r) : "f"(x));
    return r;
}
__device__ __forceinline__ float tfr(float x) { return __uint_as_float(f2tf(x)); }
__device__ __forceinline__ void cpasync16(float* dst_smem, const float* src_gmem) {
    unsigned d = (unsigned)__cvta_generic_to_shared(dst_smem);
    asm volatile("cp.async.cg.shared.global [%0], [%1], 16;"
                 :: "r"(d), "l"(src_gmem));
}
#define CP_COMMIT()  asm volatile("cp.async.commit_group;")
#define CP_WAIT0()   asm volatile("cp.async.wait_group 0;")
#define CP_WAIT1()   asm volatile("cp.async.wait_group 1;")

#define MMA_TF32(acc, a, b)                                              \
    asm volatile(                                                        \
        "mma.sync.aligned.m16n8k8.row.col.f32.tf32.tf32.f32 "            \
        "{%0,%1,%2,%3}, {%4,%5,%6,%7}, {%8,%9}, {%0,%1,%2,%3};"          \
        : "+f"((acc)[0]), "+f"((acc)[1]), "+f"((acc)[2]), "+f"((acc)[3]) \
        : "r"((a)[0]), "r"((a)[1]), "r"((a)[2]), "r"((a)[3]),            \
          "r"((b)[0]), "r"((b)[1]))

// ---------------- rmsnorm over 1024 cols, 1 block per row ----------------
__global__ void rmsnorm_kernel(const float* __restrict__ x,
                               const float* __restrict__ w,
                               float* __restrict__ out) {
    int row = blockIdx.x;
    const float* xr = x + (size_t)row * D_;
    int t = threadIdx.x;               // 256 threads, 4 floats each
    float4 v = *(const float4*)(xr + t * 4);
    float ss = v.x * v.x + v.y * v.y + v.z * v.z + v.w * v.w;
    #pragma unroll
    for (int o = 16; o; o >>= 1) ss += __shfl_xor_sync(0xffffffffu, ss, o);
    __shared__ float sh[8];
    if ((t & 31) == 0) sh[t >> 5] = ss;
    __syncthreads();
    float tot = 0.f;
    #pragma unroll
    for (int i = 0; i < 8; i++) tot += sh[i];
    float scale = rsqrtf(tot * (1.0f / D_) + 1e-6f);
    float4 wv = *(const float4*)(w + t * 4);
    float4 o4;
    o4.x = v.x * scale * wv.x;
    o4.y = v.y * scale * wv.y;
    o4.z = v.z * scale * wv.z;
    o4.w = v.w * scale * wv.w;
    *(float4*)(out + (size_t)row * D_ + t * 4) = o4;
}

// ---------------- TF32 tensor-core GEMM (R7 config: 2-stage cp.async, BK=16) ----------------
#define AST_ 20
#define BST_ 136
template <bool ACC>
__device__ __forceinline__ void gemm_core(const float* __restrict__ A,
                                          const float* __restrict__ B,
                                          float* __restrict__ C,
                                          int N, int K, int bx, int by) {
    __shared__ float As[2][128 * AST_];
    __shared__ float Bs[2][16 * BST_];

    int tid = threadIdx.x;
    int lane = tid & 31, wid = tid >> 5;
    int wr = wid >> 2;          // 0..1  (64-row slab)
    int wc = wid & 3;           // 0..3  (32-col slab)
    int tg = lane & 3;          // k index within fragment
    int grp = lane >> 2;        // m/n index within fragment

    const float* Ag = A + (size_t)(by * 128) * K;
    const float* Bg = B + bx * 128;

    int c0 = tid * 2, c1 = tid * 2 + 1;
    int ar0 = c0 >> 2, ac0 = (c0 & 3) << 2;
    int ar1 = c1 >> 2, ac1 = (c1 & 3) << 2;
    int br0 = c0 >> 5, bc0 = (c0 & 31) << 2;
    int br1 = c1 >> 5, bc1 = (c1 & 31) << 2;

    float acc[4][4][4];
    #pragma unroll
    for (int i = 0; i < 4; i++)
        #pragma unroll
        for (int j = 0; j < 4; j++)
            #pragma unroll
            for (int c = 0; c < 4; c++) acc[i][j][c] = 0.f;

    cpasync16(&As[0][ar0 * AST_ + ac0], Ag + (size_t)ar0 * K + ac0);
    cpasync16(&As[0][ar1 * AST_ + ac1], Ag + (size_t)ar1 * K + ac1);
    cpasync16(&Bs[0][br0 * BST_ + bc0], Bg + (size_t)br0 * N + bc0);
    cpasync16(&Bs[0][br1 * BST_ + bc1], Bg + (size_t)br1 * N + bc1);
    CP_COMMIT();

    int nIter = K >> 4;
    for (int it = 0; it < nIter; it++) {
        int cur = it & 1;
        CP_WAIT0();
        __syncthreads();
        if (it + 1 < nIter) {
            int nxt = cur ^ 1;
            int k0n = (it + 1) << 4;
            cpasync16(&As[nxt][ar0 * AST_ + ac0], Ag + (size_t)ar0 * K + k0n + ac0);
            cpasync16(&As[nxt][ar1 * AST_ + ac1], Ag + (size_t)ar1 * K + k0n + ac1);
            cpasync16(&Bs[nxt][br0 * BST_ + bc0], Bg + (size_t)(k0n + br0) * N + bc0);
            cpasync16(&Bs[nxt][br1 * BST_ + bc1], Bg + (size_t)(k0n + br1) * N + bc1);
            CP_COMMIT();
        }

        #pragma unroll
        for (int kk = 0; kk < 16; kk += 8) {
            unsigned afr[4][4], bfr[4][2];
            #pragma unroll
            for (int mt = 0; mt < 4; mt++) {
                int m = wr * 64 + mt * 16 + grp;
                afr[mt][0] = f2tf(As[cur][m * AST_ + kk + tg]);
                afr[mt][1] = f2tf(As[cur][(m + 8) * AST_ + kk + tg]);
                afr[mt][2] = f2tf(As[cur][m * AST_ + kk + tg + 4]);
                afr[mt][3] = f2tf(As[cur][(m + 8) * AST_ + kk + tg + 4]);
            }
            #pragma unroll
            for (int nt = 0; nt < 4; nt++) {
                int n = wc * 32 + nt * 8 + grp;
                bfr[nt][0] = f2tf(Bs[cur][(kk + tg) * BST_ + n]);
                bfr[nt][1] = f2tf(Bs[cur][(kk + tg + 4) * BST_ + n]);
            }
            #pragma unroll
            for (int mt = 0; mt < 4; mt++)
                #pragma unroll
                for (int nt = 0; nt < 4; nt++)
                    MMA_TF32(acc[mt][nt], afr[mt], bfr[nt]);
        }
        __syncthreads();
    }

    #pragma unroll
    for (int mt = 0; mt < 4; mt++) {
        int row0 = by * 128 + wr * 64 + mt * 16 + grp;
        #pragma unroll
        for (int nt = 0; nt < 4; nt++) {
            int col = bx * 128 + wc * 32 + nt * 8 + tg * 2;
            float* p0 = C + (size_t)row0 * N + col;
            float* p1 = C + (size_t)(row0 + 8) * N + col;
            if (ACC) {
                float2 cc0 = *(float2*)p0, cc1 = *(float2*)p1;
                cc0.x += acc[mt][nt][0]; cc0.y += acc[mt][nt][1];
                cc1.x += acc[mt][nt][2]; cc1.y += acc[mt][nt][3];
                *(float2*)p0 = cc0; *(float2*)p1 = cc1;
            } else {
                *(float2*)p0 = make_float2(acc[mt][nt][0], acc[mt][nt][1]);
                *(float2*)p1 = make_float2(acc[mt][nt][2], acc[mt][nt][3]);
            }
        }
    }
}

template <bool ACC>
__global__ void __launch_bounds__(256, 2)
gemm_tf32(const float* __restrict__ A, const float* __restrict__ B,
          float* __restrict__ C, int N, int K) {
    gemm_core<ACC>(A, B, C, N, K, blockIdx.x, blockIdx.y);
}

__global__ void __launch_bounds__(256, 2)
gemm_qkv(const float* __restrict__ A,
         const float* __restrict__ Wq, const float* __restrict__ Wk,
         const float* __restrict__ Wv,
         float* __restrict__ q, float* __restrict__ k, float* __restrict__ v) {
    int bx = blockIdx.x;
    if (bx < 8)       gemm_core<false>(A, Wq, q, 1024, D_, bx,      blockIdx.y);
    else if (bx < 12) gemm_core<false>(A, Wk, k,  512, D_, bx - 8,  blockIdx.y);
    else              gemm_core<false>(A, Wv, v,  512, D_, bx - 12, blockIdx.y);
}

__global__ void __launch_bounds__(256, 2)
gemm_gateup(const float* __restrict__ A,
            const float* __restrict__ Wg, const float* __restrict__ Wu,
            float* __restrict__ gate, float* __restrict__ up) {
    int bx = blockIdx.x;
    if (bx < 24) gemm_core<false>(A, Wg, gate, FF_, D_, bx,      blockIdx.y);
    else         gemm_core<false>(A, Wu, up,   FF_, D_, bx - 24, blockIdx.y);
}

// ---------------- fused per-head rmsnorm + RoPE for q AND k ----------------
#define LOG2_THETA 19.9315685693241741f
__global__ void qknorm_rope_kernel(float* __restrict__ q, float* __restrict__ k,
                                   const float* __restrict__ qw,
                                   const float* __restrict__ kw) {
    int warp = (blockIdx.x * blockDim.x + threadIdx.x) >> 5;
    int lane = threadIdx.x & 31;
    float* p; const float* w; int token;
    if (warp < TOK_ * H_) {
        p = q + (size_t)warp * HD_; w = qw; token = warp / H_;
    } else {
        int w2 = warp - TOK_ * H_;
        p = k + (size_t)w2 * HD_; w = kw; token = w2 / HK_;
    }
    int s = token & (S_ - 1);
    float a = p[lane], b = p[lane + 32];
    float ss = a * a + b * b;
    #pragma unroll
    for (int o = 16; o; o >>= 1) ss += __shfl_xor_sync(0xffffffffu, ss, o);
    float scale = rsqrtf(ss * (1.0f / HD_) + 1e-6f);
    a *= scale * w[lane];
    b *= scale * w[lane + 32];
    float inv = exp2f(-(float)lane * (LOG2_THETA / 32.0f));
    float ang = (float)s * inv;
    float c = cosf(ang), sn = sinf(ang);
    p[lane]      = a * c - b * sn;
    p[lane + 32] = b * c + a * sn;
}

// ---------------- tensor-core flash attention: 2 GQA heads/CTA, cp.async K/V ----------------
// 256 threads = 8 warps. Warps 0-3: head 2*kh, warps 4-7: head 2*kh+1.
// K/V double-buffered via cp.async; tf32 rounding applied at fragment load.
#define QST 68
#define KST 68
#define VST 72
#define PST 36
#define KVBUF (32 * KST + 32 * VST)     // floats per K/V stage
#define ATT_SMEM ((2 * 64 * QST + 2 * KVBUF + 2 * 64 * PST) * 4)
__global__ void __launch_bounds__(256, 2)
attn_mma_kernel(const float* __restrict__ q, const float* __restrict__ k,
                const float* __restrict__ v, const int* __restrict__ amask,
                float* __restrict__ out, int win) {
    extern __shared__ float asm_[];
    float* Qs  = asm_;                      // 2 x 64 x QST
    float* KV0 = Qs + 2 * 64 * QST;         // stage 0: K then V
    float* KV1 = KV0 + KVBUF;               // stage 1
    float* Ps  = KV1 + KVBUF;               // 2 x 64 x PST

    int b = blockIdx.z, kh = blockIdx.y;
    int q0 = blockIdx.x * 64;
    int tid = threadIdx.x;
    int lane = tid & 31, wid = tid >> 5;
    int hg = wid >> 2;                      // head group 0/1
    int h = kh * 2 + hg;
    int m0 = (wid & 3) * 16;                // warp's q-row offset within 64-tile
    int tg = lane & 3, grp = lane >> 2;
    int qpos0 = q0 + m0 + grp;
    int qpos1 = qpos0 + 8;

    float* Qsh = Qs + hg * 64 * QST;
    float* Psh = Ps + hg * 64 * PST;

    // cooperative Q load for BOTH heads (tf32-rounded at store)
    for (int i = tid; i < 128 * 16; i += 256) {
        int r = i >> 4;
        int hgi = r >> 6, rr = r & 63;
        int c4 = (i & 15) << 2;
        float4 f = *(const float4*)(q + (size_t)(b * S_ + q0 + rr) * (H_ * HD_)
                                      + (kh * 2 + hgi) * HD_ + c4);
        float* dst = Qs + hgi * 64 * QST + rr * QST + c4;
        dst[0] = tfr(f.x); dst[1] = tfr(f.y); dst[2] = tfr(f.z); dst[3] = tfr(f.w);
    }
    __syncthreads();

    // hoist Q fragments (invariant over K-tiles)
    unsigned qfr[8][4];
    #pragma unroll
    for (int s8 = 0; s8 < 8; s8++) {
        int k8 = s8 * 8;
        qfr[s8][0] = __float_as_uint(Qsh[(m0 + grp) * QST + k8 + tg]);
        qfr[s8][1] = __float_as_uint(Qsh[(m0 + grp + 8) * QST + k8 + tg]);
        qfr[s8][2] = __float_as_uint(Qsh[(m0 + grp) * QST + k8 + tg + 4]);
        qfr[s8][3] = __float_as_uint(Qsh[(m0 + grp + 8) * QST + k8 + tg + 4]);
    }

    float oacc[8][4];
    #pragma unroll
    for (int i = 0; i < 8; i++)
        #pragma unroll
        for (int j = 0; j < 4; j++) oacc[i][j] = 0.f;
    float mr0 = -1e30f, mr1 = -1e30f, l0 = 0.f, l1 = 0.f;

    int kt_lo = 0, kt_hi = (S_ / 32) - 1;
    if (win >= 0) {
        int lo = q0 - win; if (lo < 0) lo = 0;
        int hi = q0 + 63 + win; if (hi > S_ - 1) hi = S_ - 1;
        kt_lo = lo >> 5; kt_hi = hi >> 5;
    }
    const float scale = 0.125f;

    // cp.async K/V loader: 512 16B chunks per matrix; each thread 2 chunks of K + 2 of V
    // chunk idx: r = idx>>4 (row 0..31), c4 = (idx&15)*4
    int i0 = tid, i1 = tid + 256;
    int r0c = i0 >> 4, c40 = (i0 & 15) << 2;
    int r1c = i1 >> 4, c41 = (i1 & 15) << 2;

    #define ISSUE_KV(kt_, buf_) {                                                    \
        float* kb = (buf_) ? KV1 : KV0;                                              \
        float* vb = kb + 32 * KST;                                                   \
        size_t o0 = (size_t)(b * S_ + (kt_) * 32 + r0c) * (HK_ * HD_) + kh * HD_ + c40; \
        size_t o1 = (size_t)(b * S_ + (kt_) * 32 + r1c) * (HK_ * HD_) + kh * HD_ + c41; \
        cpasync16(&kb[r0c * KST + c40], k + o0);                                     \
        cpasync16(&kb[r1c * KST + c41], k + o1);                                     \
        cpasync16(&vb[r0c * VST + c40], v + o0);                                     \
        cpasync16(&vb[r1c * VST + c41], v + o1);                                     \
        CP_COMMIT();                                                                 \
    }

    ISSUE_KV(kt_lo, 0);

    for (int kt = kt_lo; kt <= kt_hi; kt++) {
        int cur = (kt - kt_lo) & 1;
        __syncthreads();                    // all warps done reading buffer cur^1
        if (kt + 1 <= kt_hi) {
            ISSUE_KV(kt + 1, cur ^ 1);
            CP_WAIT1();                     // current tile's group complete
        } else {
            CP_WAIT0();
        }
        __syncthreads();                    // cp.async data visible to all warps

        const float* Kc = (cur ? KV1 : KV0);
        const float* Vc = Kc + 32 * KST;

        // ---- QK^T ----
        float sc[4][4];
        #pragma unroll
        for (int i = 0; i < 4; i++)
            #pragma unroll
            for (int j = 0; j < 4; j++) sc[i][j] = 0.f;
        #pragma unroll
        for (int s8 = 0; s8 < 8; s8++) {
            int k8 = s8 * 8;
            #pragma unroll
            for (int nt = 0; nt < 4; nt++) {
                unsigned bb[2];
                bb[0] = f2tf(Kc[(nt * 8 + grp) * KST + k8 + tg]);
                bb[1] = f2tf(Kc[(nt * 8 + grp) * KST + k8 + tg + 4]);
                MMA_TF32(sc[nt], qfr[s8], bb);
            }
        }

        // ---- mask + online softmax ----
        const int* am = amask + b * S_ + kt * 32;
        float v0[8], v1[8];
        #pragma unroll
        for (int nt = 0; nt < 4; nt++) {
            int kc0 = nt * 8 + 2 * tg, kc1 = kc0 + 1;
            int kp0 = kt * 32 + kc0, kp1 = kt * 32 + kc1;
            float mk0 = (am[kc0] != 0) ? 0.f : -1e30f;
            float mk1 = (am[kc1] != 0) ? 0.f : -1e30f;
            float a0 = sc[nt][0] * scale + mk0;
            float a1 = sc[nt][1] * scale + mk1;
            float b0 = sc[nt][2] * scale + mk0;
            float b1 = sc[nt][3] * scale + mk1;
            if (win >= 0) {
                if (abs(qpos0 - kp0) > win) a0 = -1e30f;
                if (abs(qpos0 - kp1) > win) a1 = -1e30f;
                if (abs(qpos1 - kp0) > win) b0 = -1e30f;
                if (abs(qpos1 - kp1) > win) b1 = -1e30f;
            }
            v0[nt * 2] = a0; v0[nt * 2 + 1] = a1;
            v1[nt * 2] = b0; v1[nt * 2 + 1] = b1;
        }
        float tm0 = -1e30f, tm1 = -1e30f;
        #pragma unroll
        for (int j = 0; j < 8; j++) { tm0 = fmaxf(tm0, v0[j]); tm1 = fmaxf(tm1, v1[j]); }
        tm0 = fmaxf(tm0, __shfl_xor_sync(0xffffffffu, tm0, 1));
        tm0 = fmaxf(tm0, __shfl_xor_sync(0xffffffffu, tm0, 2));
        tm1 = fmaxf(tm1, __shfl_xor_sync(0xffffffffu, tm1, 1));
        tm1 = fmaxf(tm1, __shfl_xor_sync(0xffffffffu, tm1, 2));
        float nm0 = fmaxf(mr0, tm0), nm1 = fmaxf(mr1, tm1);
        float al0 = __expf(mr0 - nm0), al1 = __expf(mr1 - nm1);
        mr0 = nm0; mr1 = nm1;
        float ps0 = 0.f, ps1 = 0.f;
        #pragma unroll
        for (int nt = 0; nt < 4; nt++) {
            float p00 = __expf(v0[nt * 2]     - nm0);
            float p01 = __expf(v0[nt * 2 + 1] - nm0);
            float p10 = __expf(v1[nt * 2]     - nm1);
            float p11 = __expf(v1[nt * 2 + 1] - nm1);
            ps0 += p00 + p01; ps1 += p10 + p11;
            int col = nt * 8 + 2 * tg;
            *(float2*)&Psh[(m0 + grp) * PST + col]     = make_float2(tfr(p00), tfr(p01));
            *(float2*)&Psh[(m0 + grp + 8) * PST + col] = make_float2(tfr(p10), tfr(p11));
        }
        ps0 += __shfl_xor_sync(0xffffffffu, ps0, 1);
        ps0 += __shfl_xor_sync(0xffffffffu, ps0, 2);
        ps1 += __shfl_xor_sync(0xffffffffu, ps1, 1);
        ps1 += __shfl_xor_sync(0xffffffffu, ps1, 2);
        l0 = l0 * al0 + ps0;
        l1 = l1 * al1 + ps1;
        #pragma unroll
        for (int nt = 0; nt < 8; nt++) {
            oacc[nt][0] *= al0; oacc[nt][1] *= al0;
            oacc[nt][2] *= al1; oacc[nt][3] *= al1;
        }
        __syncwarp();

        // ---- P @ V ----
        #pragma unroll
        for (int k8 = 0; k8 < 32; k8 += 8) {
            unsigned a[4];
            a[0] = __float_as_uint(Psh[(m0 + grp) * PST + k8 + tg]);
            a[1] = __float_as_uint(Psh[(m0 + grp + 8) * PST + k8 + tg]);
            a[2] = __float_as_uint(Psh[(m0 + grp) * PST + k8 + tg + 4]);
            a[3] = __float_as_uint(Psh[(m0 + grp + 8) * PST + k8 + tg + 4]);
            #pragma unroll
            for (int nt = 0; nt < 8; nt++) {
                unsigned bb[2];
                bb[0] = f2tf(Vc[(k8 + tg) * VST + nt * 8 + grp]);
                bb[1] = f2tf(Vc[(k8 + tg + 4) * VST + nt * 8 + grp]);
                MMA_TF32(oacc[nt], a, bb);
            }
        }
    }

    float il0 = 1.0f / l0, il1 = 1.0f / l1;
    #pragma unroll
    for (int nt = 0; nt < 8; nt++) {
        int col = h * HD_ + nt * 8 + 2 * tg;
        float* p0 = out + (size_t)(b * S_ + qpos0) * (H_ * HD_) + col;
        float* p1 = out + (size_t)(b * S_ + qpos1) * (H_ * HD_) + col;
        *(float2*)p0 = make_float2(oacc[nt][0] * il0, oacc[nt][1] * il0);
        *(float2*)p1 = make_float2(oacc[nt][2] * il1, oacc[nt][3] * il1);
    }
}

// ---------------- SwiGLU elementwise (vectorized x4) ----------------
__global__ void silu_mul_kernel(float* __restrict__ gate,
                                const float* __restrict__ up, int n4) {
    int i = blockIdx.x * blockDim.x + threadIdx.x;
    if (i < n4) {
        float4 g = *(float4*)(gate + i * 4);
        float4 u = *(const float4*)(up + i * 4);
        g.x = g.x / (1.0f + __expf(-g.x)) * u.x;
        g.y = g.y / (1.0f + __expf(-g.y)) * u.y;
        g.z = g.z / (1.0f + __expf(-g.z)) * u.z;
        g.w = g.w / (1.0f + __expf(-g.w)) * u.w;
        *(float4*)(gate + i * 4) = g;
    }
}

// ---------------- host orchestration ----------------
extern "C" void kernel_launch(void* const* d_in, const int* in_sizes, int n_in,
                              void* d_out, int out_size) {
    const float* x      = (const float*)d_in[0];
    const float* wq     = (const float*)d_in[1];
    const float* wk     = (const float*)d_in[2];
    const float* wv     = (const float*)d_in[3];
    const float* wo     = (const float*)d_in[4];
    const float* qnw    = (const float*)d_in[5];
    const float* knw    = (const float*)d_in[6];
    const float* ln1    = (const float*)d_in[7];
    const float* ln2    = (const float*)d_in[8];
    const float* wg     = (const float*)d_in[9];
    const float* wu     = (const float*)d_in[10];
    const float* wd     = (const float*)d_in[11];
    const float* normw  = (const float*)d_in[12];
    const int*   amask  = (const int*)d_in[13];

    float *h, *n, *q, *k, *v, *att, *gate, *up;
    cudaGetSymbolAddress((void**)&h,    g_h);
    cudaGetSymbolAddress((void**)&n,    g_n);
    cudaGetSymbolAddress((void**)&q,    g_q);
    cudaGetSymbolAddress((void**)&k,    g_k);
    cudaGetSymbolAddress((void**)&v,    g_v);
    cudaGetSymbolAddress((void**)&att,  g_att);
    cudaGetSymbolAddress((void**)&gate, g_gate);
    cudaGetSymbolAddress((void**)&up,   g_up);

    cudaFuncSetAttribute(attn_mma_kernel,
        cudaFuncAttributeMaxDynamicSharedMemorySize, ATT_SMEM);

    cudaMemcpyAsync(h, x, (size_t)TOK_ * D_ * sizeof(float),
                    cudaMemcpyDeviceToDevice, 0);

    dim3 gQKV (16, TOK_ / 128);              // 512 blocks
    dim3 gGU  (48, TOK_ / 128);              // 1536 blocks
    dim3 g1024(D_ / 128, TOK_ / 128);        // 256 blocks
    int ropeWarps = TOK_ * (H_ + HK_);       // 98304 warps

    for (int l = 0; l < L_; l++) {
        const float* wq_l = wq + (size_t)l * D_ * H_ * HD_;
        const float* wk_l = wk + (size_t)l * D_ * HK_ * HD_;
        const float* wv_l = wv + (size_t)l * D_ * HK_ * HD_;
        const float* wo_l = wo + (size_t)l * H_ * HD_ * D_;
        const float* wg_l = wg + (size_t)l * D_ * FF_;
        const float* wu_l = wu + (size_t)l * D_ * FF_;
        const float* wd_l = wd + (size_t)l * FF_ * D_;

        rmsnorm_kernel<<<TOK_, 256>>>(h, ln1 + l * D_, n);

        gemm_qkv<<<gQKV, 256>>>(n, wq_l, wk_l, wv_l, q, k, v);

        qknorm_rope_kernel<<<ropeWarps / 4, 128>>>(q, k, qnw + l * HD_, knw + l * HD_);

        attn_mma_kernel<<<dim3(S_ / 64, HK_, B_), 256, ATT_SMEM>>>(
            q, k, v, amask, att, (l & 1) ? WIN_ : -1);

        gemm_tf32<true><<<g1024, 256>>>(att, wo_l, h, D_, H_ * HD_);

        rmsnorm_kernel<<<TOK_, 256>>>(h, ln2 + l * D_, n);

        gemm_gateup<<<gGU, 256>>>(n, wg_l, wu_l, gate, up);

        int n4 = TOK_ * FF_ / 4;
        silu_mul_kernel<<<(n4 + 255) / 256, 256>>>(gate, up, n4);

        gemm_tf32<true><<<g1024, 256>>>(gate, wd_l, h, D_, FF_);
    }

    rmsnorm_kernel<<<TOK_, 256>>>(h, normw, (float*)d_out);
}

// round 12
// speedup vs baseline: 1.6180x; 1.4661x over previous
#include <cuda_runtime.h>
#include <cuda_fp16.h>
#include <math.h>
#include <float.h>

#define D_    1024
#define H_    16
#define HK_   8
#define HD_   64
#define FF_   3072
#define S_    1024
#define B_    4
#define TOK_  4096   // B*S
#define L_    4
#define WIN_  12

// ---------------- scratch (no allocations allowed) ----------------
__device__ float  g_h   [TOK_ * D_];
__device__ float  g_q   [TOK_ * H_  * HD_];
__device__ float  g_k   [TOK_ * HK_ * HD_];
__device__ float  g_v   [TOK_ * HK_ * HD_];
__device__ float  g_gate[TOK_ * FF_];
__device__ float  g_up  [TOK_ * FF_];
// fp16 activation buffers
__device__ __half g_nh   [TOK_ * D_];
__device__ __half g_atth [TOK_ * H_ * HD_];
__device__ __half g_gateh[TOK_ * FF_];
// fp16 transposed weights [N][K]
__device__ __half g_wqt[L_ * D_ * H_ * HD_];
__device__ __half g_wkt[L_ * D_ * HK_ * HD_];
__device__ __half g_wvt[L_ * D_ * HK_ * HD_];
__device__ __half g_wot[L_ * H_ * HD_ * D_];
__device__ __half g_wgt[L_ * D_ * FF_];
__device__ __half g_wut[L_ * D_ * FF_];
__device__ __half g_wdt[L_ * FF_ * D_];

// ---------------- helpers ----------------
__device__ __forceinline__ unsigned f2tf(float x) {
    unsigned r;
    asm("cvt.rna.tf32.f32 %0, %1;" : "=r"(r) : "f"(x));
    return r;
}
__device__ __forceinline__ float tfr(float x) { return __uint_as_float(f2tf(x)); }
__device__ __forceinline__ void cpa16(void* dst_smem, const void* src_gmem) {
    unsigned d = (unsigned)__cvta_generic_to_shared(dst_smem);
    asm volatile("cp.async.cg.shared.global [%0], [%1], 16;"
                 :: "r"(d), "l"(src_gmem));
}
#define CP_COMMIT()  asm volatile("cp.async.commit_group;")
#define CP_WAIT0()   asm volatile("cp.async.wait_group 0;")
#define CP_WAIT1()   asm volatile("cp.async.wait_group 1;")

#define MMA_TF32(acc, a, b)                                              \
    asm volatile(                                                        \
        "mma.sync.aligned.m16n8k8.row.col.f32.tf32.tf32.f32 "            \
        "{%0,%1,%2,%3}, {%4,%5,%6,%7}, {%8,%9}, {%0,%1,%2,%3};"          \
        : "+f"((acc)[0]), "+f"((acc)[1]), "+f"((acc)[2]), "+f"((acc)[3]) \
        : "r"((a)[0]), "r"((a)[1]), "r"((a)[2]), "r"((a)[3]),            \
          "r"((b)[0]), "r"((b)[1]))

#define MMA_F16(acc, a, b)                                               \
    asm volatile(                                                        \
        "mma.sync.aligned.m16n8k16.row.col.f32.f16.f16.f32 "             \
        "{%0,%1,%2,%3}, {%4,%5,%6,%7}, {%8,%9}, {%0,%1,%2,%3};"          \
        : "+f"((acc)[0]), "+f"((acc)[1]), "+f"((acc)[2]), "+f"((acc)[3]) \
        : "r"((a)[0]), "r"((a)[1]), "r"((a)[2]), "r"((a)[3]),            \
          "r"((b)[0]), "r"((b)[1]))

// ---------------- weight fp32[K][N] -> fp16 transposed [N][K] ----------------
__global__ void convT_kernel(const float* __restrict__ src, __half* __restrict__ dst,
                             int K, int N) {
    __shared__ float tile[32][33];
    size_t lofs = (size_t)blockIdx.z * K * N;
    src += lofs; dst += lofs;
    int k0 = blockIdx.x * 32, n0 = blockIdx.y * 32;
    for (int i = threadIdx.y; i < 32; i += 8)
        tile[i][threadIdx.x] = src[(size_t)(k0 + i) * N + n0 + threadIdx.x];
    __syncthreads();
    for (int i = threadIdx.y; i < 32; i += 8)
        dst[(size_t)(n0 + i) * K + k0 + threadIdx.x] = __float2half(tile[threadIdx.x][i]);
}

// ---------------- rmsnorm (fp32 out, for final) ----------------
__global__ void rmsnorm_kernel(const float* __restrict__ x,
                               const float* __restrict__ w,
                               float* __restrict__ out) {
    int row = blockIdx.x;
    const float* xr = x + (size_t)row * D_;
    int t = threadIdx.x;
    float4 v = *(const float4*)(xr + t * 4);
    float ss = v.x * v.x + v.y * v.y + v.z * v.z + v.w * v.w;
    #pragma unroll
    for (int o = 16; o; o >>= 1) ss += __shfl_xor_sync(0xffffffffu, ss, o);
    __shared__ float sh[8];
    if ((t & 31) == 0) sh[t >> 5] = ss;
    __syncthreads();
    float tot = 0.f;
    #pragma unroll
    for (int i = 0; i < 8; i++) tot += sh[i];
    float scale = rsqrtf(tot * (1.0f / D_) + 1e-6f);
    float4 wv = *(const float4*)(w + t * 4);
    float4 o4;
    o4.x = v.x * scale * wv.x;
    o4.y = v.y * scale * wv.y;
    o4.z = v.z * scale * wv.z;
    o4.w = v.w * scale * wv.w;
    *(float4*)(out + (size_t)row * D_ + t * 4) = o4;
}

// ---------------- rmsnorm (fp16 out, feeds GEMMs) ----------------
__global__ void rmsnorm_h_kernel(const float* __restrict__ x,
                                 const float* __restrict__ w,
                                 __half* __restrict__ out) {
    int row = blockIdx.x;
    const float* xr = x + (size_t)row * D_;
    int t = threadIdx.x;
    float4 v = *(const float4*)(xr + t * 4);
    float ss = v.x * v.x + v.y * v.y + v.z * v.z + v.w * v.w;
    #pragma unroll
    for (int o = 16; o; o >>= 1) ss += __shfl_xor_sync(0xffffffffu, ss, o);
    __shared__ float sh[8];
    if ((t & 31) == 0) sh[t >> 5] = ss;
    __syncthreads();
    float tot = 0.f;
    #pragma unroll
    for (int i = 0; i < 8; i++) tot += sh[i];
    float scale = rsqrtf(tot * (1.0f / D_) + 1e-6f);
    float4 wv = *(const float4*)(w + t * 4);
    __half2 h0 = __floats2half2_rn(v.x * scale * wv.x, v.y * scale * wv.y);
    __half2 h1 = __floats2half2_rn(v.z * scale * wv.z, v.w * scale * wv.w);
    __half2* dst = (__half2*)(out + (size_t)row * D_ + t * 4);
    dst[0] = h0; dst[1] = h1;
}

// ---------------- FP16 tensor-core GEMM (2-stage cp.async, BK=32, 8 warps) ----------------
// C[M,N](+)= A[M,K] @ B[K,N], with A fp16 row-major and BT fp16 [N][K].
// Smem row stride 40 halves (20 words) -> conflict-free fragment LDS.
#define HAW 20   // words per smem row (40 halves)
template <bool ACC>
__device__ __forceinline__ void gemm_h_core(const __half* __restrict__ A,
                                            const __half* __restrict__ BT,
                                            float* __restrict__ C,
                                            int N, int K, int bx, int by) {
    __shared__ unsigned As[2][128 * HAW];
    __shared__ unsigned Bs[2][128 * HAW];

    int tid = threadIdx.x;
    int lane = tid & 31, wid = tid >> 5;
    int wr = wid >> 2;          // 0..1  (64-row slab)
    int wc = wid & 3;           // 0..3  (32-col slab)
    int tg = lane & 3;
    int grp = lane >> 2;

    const __half* Ag = A + (size_t)(by * 128) * K;
    const __half* Bg = BT + (size_t)(bx * 128) * K;

    // cp.async plan: 2 chunks (16B = 8 halves) per thread for each of A and B
    int c0 = tid * 2, c1 = c0 + 1;
    int r0 = c0 >> 2, kc0 = (c0 & 3) << 3;   // halves
    int r1 = c1 >> 2, kc1 = (c1 & 3) << 3;
    int w0 = kc0 >> 1, w1 = kc1 >> 1;        // words

    float acc[4][4][4];
    #pragma unroll
    for (int i = 0; i < 4; i++)
        #pragma unroll
        for (int j = 0; j < 4; j++)
            #pragma unroll
            for (int c = 0; c < 4; c++) acc[i][j][c] = 0.f;

    // prologue: stage 0
    cpa16(&As[0][r0 * HAW + w0], Ag + (size_t)r0 * K + kc0);
    cpa16(&As[0][r1 * HAW + w1], Ag + (size_t)r1 * K + kc1);
    cpa16(&Bs[0][r0 * HAW + w0], Bg + (size_t)r0 * K + kc0);
    cpa16(&Bs[0][r1 * HAW + w1], Bg + (size_t)r1 * K + kc1);
    CP_COMMIT();

    int nIter = K >> 5;
    for (int it = 0; it < nIter; it++) {
        int cur = it & 1;
        CP_WAIT0();
        __syncthreads();
        if (it + 1 < nIter) {
            int nxt = cur ^ 1;
            int k0n = (it + 1) << 5;
            cpa16(&As[nxt][r0 * HAW + w0], Ag + (size_t)r0 * K + k0n + kc0);
            cpa16(&As[nxt][r1 * HAW + w1], Ag + (size_t)r1 * K + k0n + kc1);
            cpa16(&Bs[nxt][r0 * HAW + w0], Bg + (size_t)r0 * K + k0n + kc0);
            cpa16(&Bs[nxt][r1 * HAW + w1], Bg + (size_t)r1 * K + k0n + kc1);
            CP_COMMIT();
        }

        #pragma unroll
        for (int kk8 = 0; kk8 < 16; kk8 += 8) {   // two k16 sub-slices
            unsigned afr[4][4], bfr[4][2];
            #pragma unroll
            for (int mt = 0; mt < 4; mt++) {
                int m = wr * 64 + mt * 16 + grp;
                afr[mt][0] = As[cur][m * HAW + tg + kk8];
                afr[mt][1] = As[cur][(m + 8) * HAW + tg + kk8];
                afr[mt][2] = As[cur][m * HAW + tg + 4 + kk8];
                afr[mt][3] = As[cur][(m + 8) * HAW + tg + 4 + kk8];
            }
            #pragma unroll
            for (int nt = 0; nt < 4; nt++) {
                int n = wc * 32 + nt * 8 + grp;
                bfr[nt][0] = Bs[cur][n * HAW + tg + kk8];
                bfr[nt][1] = Bs[cur][n * HAW + tg + 4 + kk8];
            }
            #pragma unroll
            for (int mt = 0; mt < 4; mt++)
                #pragma unroll
                for (int nt = 0; nt < 4; nt++)
                    MMA_F16(acc[mt][nt], afr[mt], bfr[nt]);
        }
        __syncthreads();
    }

    #pragma unroll
    for (int mt = 0; mt < 4; mt++) {
        int row0 = by * 128 + wr * 64 + mt * 16 + grp;
        #pragma unroll
        for (int nt = 0; nt < 4; nt++) {
            int col = bx * 128 + wc * 32 + nt * 8 + tg * 2;
            float* p0 = C + (size_t)row0 * N + col;
            float* p1 = C + (size_t)(row0 + 8) * N + col;
            if (ACC) {
                float2 cc0 = *(float2*)p0, cc1 = *(float2*)p1;
                cc0.x += acc[mt][nt][0]; cc0.y += acc[mt][nt][1];
                cc1.x += acc[mt][nt][2]; cc1.y += acc[mt][nt][3];
                *(float2*)p0 = cc0; *(float2*)p1 = cc1;
            } else {
                *(float2*)p0 = make_float2(acc[mt][nt][0], acc[mt][nt][1]);
                *(float2*)p1 = make_float2(acc[mt][nt][2], acc[mt][nt][3]);
            }
        }
    }
}

template <bool ACC>
__global__ void __launch_bounds__(256, 2)
gemm_h(const __half* __restrict__ A, const __half* __restrict__ BT,
       float* __restrict__ C, int N, int K) {
    gemm_h_core<ACC>(A, BT, C, N, K, blockIdx.x, blockIdx.y);
}

__global__ void __launch_bounds__(256, 2)
gemm_qkv_h(const __half* __restrict__ A,
           const __half* __restrict__ WqT, const __half* __restrict__ WkT,
           const __half* __restrict__ WvT,
           float* __restrict__ q, float* __restrict__ k, float* __restrict__ v) {
    int bx = blockIdx.x;
    if (bx < 8)       gemm_h_core<false>(A, WqT, q, 1024, D_, bx,      blockIdx.y);
    else if (bx < 12) gemm_h_core<false>(A, WkT, k,  512, D_, bx - 8,  blockIdx.y);
    else              gemm_h_core<false>(A, WvT, v,  512, D_, bx - 12, blockIdx.y);
}

__global__ void __launch_bounds__(256, 2)
gemm_gateup_h(const __half* __restrict__ A,
              const __half* __restrict__ WgT, const __half* __restrict__ WuT,
              float* __restrict__ gate, float* __restrict__ up) {
    int bx = blockIdx.x;
    if (bx < 24) gemm_h_core<false>(A, WgT, gate, FF_, D_, bx,      blockIdx.y);
    else         gemm_h_core<false>(A, WuT, up,   FF_, D_, bx - 24, blockIdx.y);
}

// ---------------- fused per-head rmsnorm + RoPE for q AND k (fp32) ----------------
#define LOG2_THETA 19.9315685693241741f
__global__ void qknorm_rope_kernel(float* __restrict__ q, float* __restrict__ k,
                                   const float* __restrict__ qw,
                                   const float* __restrict__ kw) {
    int warp = (blockIdx.x * blockDim.x + threadIdx.x) >> 5;
    int lane = threadIdx.x & 31;
    float* p; const float* w; int token;
    if (warp < TOK_ * H_) {
        p = q + (size_t)warp * HD_; w = qw; token = warp / H_;
    } else {
        int w2 = warp - TOK_ * H_;
        p = k + (size_t)w2 * HD_; w = kw; token = w2 / HK_;
    }
    int s = token & (S_ - 1);
    float a = p[lane], b = p[lane + 32];
    float ss = a * a + b * b;
    #pragma unroll
    for (int o = 16; o; o >>= 1) ss += __shfl_xor_sync(0xffffffffu, ss, o);
    float scale = rsqrtf(ss * (1.0f / HD_) + 1e-6f);
    a *= scale * w[lane];
    b *= scale * w[lane + 32];
    float inv = exp2f(-(float)lane * (LOG2_THETA / 32.0f));
    float ang = (float)s * inv;
    float c = cosf(ang), sn = sinf(ang);
    p[lane]      = a * c - b * sn;
    p[lane + 32] = b * c + a * sn;
}

// ---------------- tensor-core flash attention: 2 GQA heads/CTA, cp.async K/V ----------------
// Output written as fp16 (feeds o-proj GEMM).
#define QST 68
#define KST 68
#define VST 72
#define PST 36
#define KVBUF (32 * KST + 32 * VST)
#define ATT_SMEM ((2 * 64 * QST + 2 * KVBUF + 2 * 64 * PST) * 4)
__global__ void __launch_bounds__(256, 2)
attn_mma_kernel(const float* __restrict__ q, const float* __restrict__ k,
                const float* __restrict__ v, const int* __restrict__ amask,
                __half* __restrict__ out, int win) {
    extern __shared__ float asm_[];
    float* Qs  = asm_;
    float* KV0 = Qs + 2 * 64 * QST;
    float* KV1 = KV0 + KVBUF;
    float* Ps  = KV1 + KVBUF;

    int b = blockIdx.z, kh = blockIdx.y;
    int q0 = blockIdx.x * 64;
    int tid = threadIdx.x;
    int lane = tid & 31, wid = tid >> 5;
    int hg = wid >> 2;
    int h = kh * 2 + hg;
    int m0 = (wid & 3) * 16;
    int tg = lane & 3, grp = lane >> 2;
    int qpos0 = q0 + m0 + grp;
    int qpos1 = qpos0 + 8;

    float* Qsh = Qs + hg * 64 * QST;
    float* Psh = Ps + hg * 64 * PST;

    for (int i = tid; i < 128 * 16; i += 256) {
        int r = i >> 4;
        int hgi = r >> 6, rr = r & 63;
        int c4 = (i & 15) << 2;
        float4 f = *(const float4*)(q + (size_t)(b * S_ + q0 + rr) * (H_ * HD_)
                                      + (kh * 2 + hgi) * HD_ + c4);
        float* dst = Qs + hgi * 64 * QST + rr * QST + c4;
        dst[0] = tfr(f.x); dst[1] = tfr(f.y); dst[2] = tfr(f.z); dst[3] = tfr(f.w);
    }
    __syncthreads();

    unsigned qfr[8][4];
    #pragma unroll
    for (int s8 = 0; s8 < 8; s8++) {
        int k8 = s8 * 8;
        qfr[s8][0] = __float_as_uint(Qsh[(m0 + grp) * QST + k8 + tg]);
        qfr[s8][1] = __float_as_uint(Qsh[(m0 + grp + 8) * QST + k8 + tg]);
        qfr[s8][2] = __float_as_uint(Qsh[(m0 + grp) * QST + k8 + tg + 4]);
        qfr[s8][3] = __float_as_uint(Qsh[(m0 + grp + 8) * QST + k8 + tg + 4]);
    }

    float oacc[8][4];
    #pragma unroll
    for (int i = 0; i < 8; i++)
        #pragma unroll
        for (int j = 0; j < 4; j++) oacc[i][j] = 0.f;
    float mr0 = -1e30f, mr1 = -1e30f, l0 = 0.f, l1 = 0.f;

    int kt_lo = 0, kt_hi = (S_ / 32) - 1;
    if (win >= 0) {
        int lo = q0 - win; if (lo < 0) lo = 0;
        int hi = q0 + 63 + win; if (hi > S_ - 1) hi = S_ - 1;
        kt_lo = lo >> 5; kt_hi = hi >> 5;
    }
    const float scale = 0.125f;

    int i0 = tid, i1 = tid + 256;
    int r0c = i0 >> 4, c40 = (i0 & 15) << 2;
    int r1c = i1 >> 4, c41 = (i1 & 15) << 2;

    #define ISSUE_KV(kt_, buf_) {                                                    \
        float* kb = (buf_) ? KV1 : KV0;                                              \
        float* vb = kb + 32 * KST;                                                   \
        size_t o0 = (size_t)(b * S_ + (kt_) * 32 + r0c) * (HK_ * HD_) + kh * HD_ + c40; \
        size_t o1 = (size_t)(b * S_ + (kt_) * 32 + r1c) * (HK_ * HD_) + kh * HD_ + c41; \
        cpa16(&kb[r0c * KST + c40], k + o0);                                         \
        cpa16(&kb[r1c * KST + c41], k + o1);                                         \
        cpa16(&vb[r0c * VST + c40], v + o0);                                         \
        cpa16(&vb[r1c * VST + c41], v + o1);                                         \
        CP_COMMIT();                                                                 \
    }

    ISSUE_KV(kt_lo, 0);

    for (int kt = kt_lo; kt <= kt_hi; kt++) {
        int cur = (kt - kt_lo) & 1;
        __syncthreads();
        if (kt + 1 <= kt_hi) {
            ISSUE_KV(kt + 1, cur ^ 1);
            CP_WAIT1();
        } else {
            CP_WAIT0();
        }
        __syncthreads();

        const float* Kc = (cur ? KV1 : KV0);
        const float* Vc = Kc + 32 * KST;

        float sc[4][4];
        #pragma unroll
        for (int i = 0; i < 4; i++)
            #pragma unroll
            for (int j = 0; j < 4; j++) sc[i][j] = 0.f;
        #pragma unroll
        for (int s8 = 0; s8 < 8; s8++) {
            int k8 = s8 * 8;
            #pragma unroll
            for (int nt = 0; nt < 4; nt++) {
                unsigned bb[2];
                bb[0] = f2tf(Kc[(nt * 8 + grp) * KST + k8 + tg]);
                bb[1] = f2tf(Kc[(nt * 8 + grp) * KST + k8 + tg + 4]);
                MMA_TF32(sc[nt], qfr[s8], bb);
            }
        }

        const int* am = amask + b * S_ + kt * 32;
        float v0[8], v1[8];
        #pragma unroll
        for (int nt = 0; nt < 4; nt++) {
            int kc0 = nt * 8 + 2 * tg, kc1 = kc0 + 1;
            int kp0 = kt * 32 + kc0, kp1 = kt * 32 + kc1;
            float mk0 = (am[kc0] != 0) ? 0.f : -1e30f;
            float mk1 = (am[kc1] != 0) ? 0.f : -1e30f;
            float a0 = sc[nt][0] * scale + mk0;
            float a1 = sc[nt][1] * scale + mk1;
            float b0 = sc[nt][2] * scale + mk0;
            float b1 = sc[nt][3] * scale + mk1;
            if (win >= 0) {
                if (abs(qpos0 - kp0) > win) a0 = -1e30f;
                if (abs(qpos0 - kp1) > win) a1 = -1e30f;
                if (abs(qpos1 - kp0) > win) b0 = -1e30f;
                if (abs(qpos1 - kp1) > win) b1 = -1e30f;
            }
            v0[nt * 2] = a0; v0[nt * 2 + 1] = a1;
            v1[nt * 2] = b0; v1[nt * 2 + 1] = b1;
        }
        float tm0 = -1e30f, tm1 = -1e30f;
        #pragma unroll
        for (int j = 0; j < 8; j++) { tm0 = fmaxf(tm0, v0[j]); tm1 = fmaxf(tm1, v1[j]); }
        tm0 = fmaxf(tm0, __shfl_xor_sync(0xffffffffu, tm0, 1));
        tm0 = fmaxf(tm0, __shfl_xor_sync(0xffffffffu, tm0, 2));
        tm1 = fmaxf(tm1, __shfl_xor_sync(0xffffffffu, tm1, 1));
        tm1 = fmaxf(tm1, __shfl_xor_sync(0xffffffffu, tm1, 2));
        float nm0 = fmaxf(mr0, tm0), nm1 = fmaxf(mr1, tm1);
        float al0 = __expf(mr0 - nm0), al1 = __expf(mr1 - nm1);
        mr0 = nm0; mr1 = nm1;
        float ps0 = 0.f, ps1 = 0.f;
        #pragma unroll
        for (int nt = 0; nt < 4; nt++) {
            float p00 = __expf(v0[nt * 2]     - nm0);
            float p01 = __expf(v0[nt * 2 + 1] - nm0);
            float p10 = __expf(v1[nt * 2]     - nm1);
            float p11 = __expf(v1[nt * 2 + 1] - nm1);
            ps0 += p00 + p01; ps1 += p10 + p11;
            int col = nt * 8 + 2 * tg;
            *(float2*)&Psh[(m0 + grp) * PST + col]     = make_float2(tfr(p00), tfr(p01));
            *(float2*)&Psh[(m0 + grp + 8) * PST + col] = make_float2(tfr(p10), tfr(p11));
        }
        ps0 += __shfl_xor_sync(0xffffffffu, ps0, 1);
        ps0 += __shfl_xor_sync(0xffffffffu, ps0, 2);
        ps1 += __shfl_xor_sync(0xffffffffu, ps1, 1);
        ps1 += __shfl_xor_sync(0xffffffffu, ps1, 2);
        l0 = l0 * al0 + ps0;
        l1 = l1 * al1 + ps1;
        #pragma unroll
        for (int nt = 0; nt < 8; nt++) {
            oacc[nt][0] *= al0; oacc[nt][1] *= al0;
            oacc[nt][2] *= al1; oacc[nt][3] *= al1;
        }
        __syncwarp();

        #pragma unroll
        for (int k8 = 0; k8 < 32; k8 += 8) {
            unsigned a[4];
            a[0] = __float_as_uint(Psh[(m0 + grp) * PST + k8 + tg]);
            a[1] = __float_as_uint(Psh[(m0 + grp + 8) * PST + k8 + tg]);
            a[2] = __float_as_uint(Psh[(m0 + grp) * PST + k8 + tg + 4]);
            a[3] = __float_as_uint(Psh[(m0 + grp + 8) * PST + k8 + tg + 4]);
            #pragma unroll
            for (int nt = 0; nt < 8; nt++) {
                unsigned bb[2];
                bb[0] = f2tf(Vc[(k8 + tg) * VST + nt * 8 + grp]);
                bb[1] = f2tf(Vc[(k8 + tg + 4) * VST + nt * 8 + grp]);
                MMA_TF32(oacc[nt], a, bb);
            }
        }
    }

    float il0 = 1.0f / l0, il1 = 1.0f / l1;
    #pragma unroll
    for (int nt = 0; nt < 8; nt++) {
        int col = h * HD_ + nt * 8 + 2 * tg;
        __half2* p0 = (__half2*)(out + (size_t)(b * S_ + qpos0) * (H_ * HD_) + col);
        __half2* p1 = (__half2*)(out + (size_t)(b * S_ + qpos1) * (H_ * HD_) + col);
        *p0 = __floats2half2_rn(oacc[nt][0] * il0, oacc[nt][1] * il0);
        *p1 = __floats2half2_rn(oacc[nt][2] * il1, oacc[nt][3] * il1);
    }
}

// ---------------- SwiGLU elementwise: gateh = fp16(silu(gate) * up) ----------------
__global__ void silu_mul_kernel(const float* __restrict__ gate,
                                const float* __restrict__ up,
                                __half* __restrict__ outh, int n4) {
    int i = blockIdx.x * blockDim.x + threadIdx.x;
    if (i < n4) {
        float4 g = *(const float4*)(gate + i * 4);
        float4 u = *(const float4*)(up + i * 4);
        float r0 = g.x / (1.0f + __expf(-g.x)) * u.x;
        float r1 = g.y / (1.0f + __expf(-g.y)) * u.y;
        float r2 = g.z / (1.0f + __expf(-g.z)) * u.z;
        float r3 = g.w / (1.0f + __expf(-g.w)) * u.w;
        __half2* dst = (__half2*)(outh + (size_t)i * 4);
        dst[0] = __floats2half2_rn(r0, r1);
        dst[1] = __floats2half2_rn(r2, r3);
    }
}

// ---------------- host orchestration ----------------
extern "C" void kernel_launch(void* const* d_in, const int* in_sizes, int n_in,
                              void* d_out, int out_size) {
    const float* x      = (const float*)d_in[0];
    const float* wq     = (const float*)d_in[1];
    const float* wk     = (const float*)d_in[2];
    const float* wv     = (const float*)d_in[3];
    const float* wo     = (const float*)d_in[4];
    const float* qnw    = (const float*)d_in[5];
    const float* knw    = (const float*)d_in[6];
    const float* ln1    = (const float*)d_in[7];
    const float* ln2    = (const float*)d_in[8];
    const float* wg     = (const float*)d_in[9];
    const float* wu     = (const float*)d_in[10];
    const float* wd     = (const float*)d_in[11];
    const float* normw  = (const float*)d_in[12];
    const int*   amask  = (const int*)d_in[13];

    float *h, *q, *k, *v, *gate, *up;
    __half *nh, *atth, *gateh;
    __half *wqt, *wkt, *wvt, *wot, *wgt, *wut, *wdt;
    cudaGetSymbolAddress((void**)&h,     g_h);
    cudaGetSymbolAddress((void**)&q,     g_q);
    cudaGetSymbolAddress((void**)&k,     g_k);
    cudaGetSymbolAddress((void**)&v,     g_v);
    cudaGetSymbolAddress((void**)&gate,  g_gate);
    cudaGetSymbolAddress((void**)&up,    g_up);
    cudaGetSymbolAddress((void**)&nh,    g_nh);
    cudaGetSymbolAddress((void**)&atth,  g_atth);
    cudaGetSymbolAddress((void**)&gateh, g_gateh);
    cudaGetSymbolAddress((void**)&wqt,   g_wqt);
    cudaGetSymbolAddress((void**)&wkt,   g_wkt);
    cudaGetSymbolAddress((void**)&wvt,   g_wvt);
    cudaGetSymbolAddress((void**)&wot,   g_wot);
    cudaGetSymbolAddress((void**)&wgt,   g_wgt);
    cudaGetSymbolAddress((void**)&wut,   g_wut);
    cudaGetSymbolAddress((void**)&wdt,   g_wdt);

    cudaFuncSetAttribute(attn_mma_kernel,
        cudaFuncAttributeMaxDynamicSharedMemorySize, ATT_SMEM);

    // per-call weight convert + transpose: fp32 [K][N] -> fp16 [N][K]
    dim3 tb(32, 8);
    convT_kernel<<<dim3(D_ / 32, (H_ * HD_) / 32, L_), tb>>>(wq, wqt, D_, H_ * HD_);
    convT_kernel<<<dim3(D_ / 32, (HK_ * HD_) / 32, L_), tb>>>(wk, wkt, D_, HK_ * HD_);
    convT_kernel<<<dim3(D_ / 32, (HK_ * HD_) / 32, L_), tb>>>(wv, wvt, D_, HK_ * HD_);
    convT_kernel<<<dim3((H_ * HD_) / 32, D_ / 32, L_), tb>>>(wo, wot, H_ * HD_, D_);
    convT_kernel<<<dim3(D_ / 32, FF_ / 32, L_), tb>>>(wg, wgt, D_, FF_);
    convT_kernel<<<dim3(D_ / 32, FF_ / 32, L_), tb>>>(wu, wut, D_, FF_);
    convT_kernel<<<dim3(FF_ / 32, D_ / 32, L_), tb>>>(wd, wdt, FF_, D_);

    cudaMemcpyAsync(h, x, (size_t)TOK_ * D_ * sizeof(float),
                    cudaMemcpyDeviceToDevice, 0);

    dim3 gQKV (16, TOK_ / 128);              // 512 blocks
    dim3 gGU  (48, TOK_ / 128);              // 1536 blocks
    dim3 g1024(D_ / 128, TOK_ / 128);        // 256 blocks
    int ropeWarps = TOK_ * (H_ + HK_);

    for (int l = 0; l < L_; l++) {
        const __half* wqt_l = wqt + (size_t)l * D_ * H_ * HD_;
        const __half* wkt_l = wkt + (size_t)l * D_ * HK_ * HD_;
        const __half* wvt_l = wvt + (size_t)l * D_ * HK_ * HD_;
        const __half* wot_l = wot + (size_t)l * H_ * HD_ * D_;
        const __half* wgt_l = wgt + (size_t)l * D_ * FF_;
        const __half* wut_l = wut + (size_t)l * D_ * FF_;
        const __half* wdt_l = wdt + (size_t)l * FF_ * D_;

        rmsnorm_h_kernel<<<TOK_, 256>>>(h, ln1 + l * D_, nh);

        gemm_qkv_h<<<gQKV, 256>>>(nh, wqt_l, wkt_l, wvt_l, q, k, v);

        qknorm_rope_kernel<<<ropeWarps / 4, 128>>>(q, k, qnw + l * HD_, knw + l * HD_);

        attn_mma_kernel<<<dim3(S_ / 64, HK_, B_), 256, ATT_SMEM>>>(
            q, k, v, amask, atth, (l & 1) ? WIN_ : -1);

        gemm_h<true><<<g1024, 256>>>(atth, wot_l, h, D_, H_ * HD_);

        rmsnorm_h_kernel<<<TOK_, 256>>>(h, ln2 + l * D_, nh);

        gemm_gateup_h<<<gGU, 256>>>(nh, wgt_l, wut_l, gate, up);

        int n4 = TOK_ * FF_ / 4;
        silu_mul_kernel<<<(n4 + 255) / 256, 256>>>(gate, up, gateh, n4);

        gemm_h<true><<<g1024, 256>>>(gateh, wdt_l, h, D_, FF_);
    }

    rmsnorm_kernel<<<TOK_, 256>>>(h, normw, (float*)d_out);
}

// round 14
// speedup vs baseline: 1.6710x; 1.0328x over previous
#include <cuda_runtime.h>
#include <cuda_fp16.h>
#include <math.h>
#include <float.h>

#define D_    1024
#define H_    16
#define HK_   8
#define HD_   64
#define FF_   3072
#define S_    1024
#define B_    4
#define TOK_  4096   // B*S
#define L_    4
#define WIN_  12

// ---------------- scratch (no allocations allowed) ----------------
__device__ float  g_h   [TOK_ * D_];
__device__ float  g_q   [TOK_ * H_  * HD_];
__device__ float  g_k   [TOK_ * HK_ * HD_];
__device__ float  g_v   [TOK_ * HK_ * HD_];
__device__ float  g_gate[TOK_ * FF_];
__device__ float  g_up  [TOK_ * FF_];
// fp16 activation buffers
__device__ __half g_nh   [TOK_ * D_];
__device__ __half g_atth [TOK_ * H_ * HD_];
__device__ __half g_gateh[TOK_ * FF_];
// fp16 transposed weights [N][K]
__device__ __half g_wqt[L_ * D_ * H_ * HD_];
__device__ __half g_wkt[L_ * D_ * HK_ * HD_];
__device__ __half g_wvt[L_ * D_ * HK_ * HD_];
__device__ __half g_wot[L_ * H_ * HD_ * D_];
__device__ __half g_wgt[L_ * D_ * FF_];
__device__ __half g_wut[L_ * D_ * FF_];
__device__ __half g_wdt[L_ * FF_ * D_];

// ---------------- helpers ----------------
__device__ __forceinline__ unsigned f2tf(float x) {
    unsigned r;
    asm("cvt.rna.tf32.f32 %0, %1;" : "=r"(r) : "f"(x));
    return r;
}
__device__ __forceinline__ float tfr(float x) { return __uint_as_float(f2tf(x)); }
__device__ __forceinline__ void cpa16(void* dst_smem, const void* src_gmem) {
    unsigned d = (unsigned)__cvta_generic_to_shared(dst_smem);
    asm volatile("cp.async.cg.shared.global [%0], [%1], 16;"
                 :: "r"(d), "l"(src_gmem));
}
#define CP_COMMIT()  asm volatile("cp.async.commit_group;")
#define CP_WAIT0()   asm volatile("cp.async.wait_group 0;")
#define CP_WAIT1()   asm volatile("cp.async.wait_group 1;")

#define MMA_TF32(acc, a, b)                                              \
    asm volatile(                                                        \
        "mma.sync.aligned.m16n8k8.row.col.f32.tf32.tf32.f32 "            \
        "{%0,%1,%2,%3}, {%4,%5,%6,%7}, {%8,%9}, {%0,%1,%2,%3};"          \
        : "+f"((acc)[0]), "+f"((acc)[1]), "+f"((acc)[2]), "+f"((acc)[3]) \
        : "r"((a)[0]), "r"((a)[1]), "r"((a)[2]), "r"((a)[3]),            \
          "r"((b)[0]), "r"((b)[1]))

#define MMA_F16(acc, a, b)                                               \
    asm volatile(                                                        \
        "mma.sync.aligned.m16n8k16.row.col.f32.f16.f16.f32 "             \
        "{%0,%1,%2,%3}, {%4,%5,%6,%7}, {%8,%9}, {%0,%1,%2,%3};"          \
        : "+f"((acc)[0]), "+f"((acc)[1]), "+f"((acc)[2]), "+f"((acc)[3]) \
        : "r"((a)[0]), "r"((a)[1]), "r"((a)[2]), "r"((a)[3]),            \
          "r"((b)[0]), "r"((b)[1]))

#define LDSM4(r, addr)                                                   \
    asm volatile("ldmatrix.sync.aligned.m8n8.x4.shared.b16 "             \
                 "{%0,%1,%2,%3}, [%4];"                                  \
                 : "=r"((r)[0]), "=r"((r)[1]), "=r"((r)[2]), "=r"((r)[3])\
                 : "r"(addr))

// ---------------- weight fp32[K][N] -> fp16 transposed [N][K] ----------------
__global__ void convT_kernel(const float* __restrict__ src, __half* __restrict__ dst,
                             int K, int N) {
    __shared__ float tile[32][33];
    size_t lofs = (size_t)blockIdx.z * K * N;
    src += lofs; dst += lofs;
    int k0 = blockIdx.x * 32, n0 = blockIdx.y * 32;
    for (int i = threadIdx.y; i < 32; i += 8)
        tile[i][threadIdx.x] = src[(size_t)(k0 + i) * N + n0 + threadIdx.x];
    __syncthreads();
    for (int i = threadIdx.y; i < 32; i += 8)
        dst[(size_t)(n0 + i) * K + k0 + threadIdx.x] = __float2half(tile[threadIdx.x][i]);
}

// ---------------- rmsnorm (fp32 out, for final) ----------------
__global__ void rmsnorm_kernel(const float* __restrict__ x,
                               const float* __restrict__ w,
                               float* __restrict__ out) {
    int row = blockIdx.x;
    const float* xr = x + (size_t)row * D_;
    int t = threadIdx.x;
    float4 v = *(const float4*)(xr + t * 4);
    float ss = v.x * v.x + v.y * v.y + v.z * v.z + v.w * v.w;
    #pragma unroll
    for (int o = 16; o; o >>= 1) ss += __shfl_xor_sync(0xffffffffu, ss, o);
    __shared__ float sh[8];
    if ((t & 31) == 0) sh[t >> 5] = ss;
    __syncthreads();
    float tot = 0.f;
    #pragma unroll
    for (int i = 0; i < 8; i++) tot += sh[i];
    float scale = rsqrtf(tot * (1.0f / D_) + 1e-6f);
    float4 wv = *(const float4*)(w + t * 4);
    float4 o4;
    o4.x = v.x * scale * wv.x;
    o4.y = v.y * scale * wv.y;
    o4.z = v.z * scale * wv.z;
    o4.w = v.w * scale * wv.w;
    *(float4*)(out + (size_t)row * D_ + t * 4) = o4;
}

// ---------------- rmsnorm (fp16 out, feeds GEMMs) ----------------
__global__ void rmsnorm_h_kernel(const float* __restrict__ x,
                                 const float* __restrict__ w,
                                 __half* __restrict__ out) {
    int row = blockIdx.x;
    const float* xr = x + (size_t)row * D_;
    int t = threadIdx.x;
    float4 v = *(const float4*)(xr + t * 4);
    float ss = v.x * v.x + v.y * v.y + v.z * v.z + v.w * v.w;
    #pragma unroll
    for (int o = 16; o; o >>= 1) ss += __shfl_xor_sync(0xffffffffu, ss, o);
    __shared__ float sh[8];
    if ((t & 31) == 0) sh[t >> 5] = ss;
    __syncthreads();
    float tot = 0.f;
    #pragma unroll
    for (int i = 0; i < 8; i++) tot += sh[i];
    float scale = rsqrtf(tot * (1.0f / D_) + 1e-6f);
    float4 wv = *(const float4*)(w + t * 4);
    __half2 h0 = __floats2half2_rn(v.x * scale * wv.x, v.y * scale * wv.y);
    __half2 h1 = __floats2half2_rn(v.z * scale * wv.z, v.w * scale * wv.w);
    __half2* dst = (__half2*)(out + (size_t)row * D_ + t * 4);
    dst[0] = h0; dst[1] = h1;
}

// ---------------- FP16 tensor-core GEMM (2-stage cp.async, BK=32, ldmatrix) ----------------
// C[M,N](+)= A[M,K] @ B[K,N], A fp16 row-major, BT fp16 [N][K].
// Smem rows: 32 halves padded to 40 (80 bytes) -> LDSM conflict-free.
#define HAW 20                       // words per smem row
#define HSTG_B (128 * HAW * 4)       // bytes per stage per matrix (10240)
template <bool ACC>
__device__ __forceinline__ void gemm_h_core(const __half* __restrict__ A,
                                            const __half* __restrict__ BT,
                                            float* __restrict__ C,
                                            int N, int K, int bx, int by) {
    __shared__ unsigned As[2][128 * HAW];
    __shared__ unsigned Bs[2][128 * HAW];

    int tid = threadIdx.x;
    int lane = tid & 31, wid = tid >> 5;
    int wr = wid >> 2;          // 0..1  (64-row slab)
    int wc = wid & 3;           // 0..3  (32-col slab)
    int tg = lane & 3;
    int grp = lane >> 2;

    const __half* Ag = A + (size_t)(by * 128) * K;
    const __half* Bg = BT + (size_t)(bx * 128) * K;

    // cp.async plan: 2 chunks (16B = 8 halves) per thread for each of A and B
    int c0 = tid * 2, c1 = c0 + 1;
    int r0 = c0 >> 2, kc0 = (c0 & 3) << 3;
    int r1 = c1 >> 2, kc1 = (c1 & 3) << 3;
    int w0 = kc0 >> 1, w1 = kc1 >> 1;

    // ldmatrix per-lane base addresses (bytes)
    unsigned aSm = (unsigned)__cvta_generic_to_shared(&As[0][0]);
    unsigned bSm = (unsigned)__cvta_generic_to_shared(&Bs[0][0]);
    int lrow = lane & 15;
    int lkof = (lane >> 4) * 16;              // +8 halves for lanes 16-31
    unsigned aAddr[4], bAddr[2];
    #pragma unroll
    for (int mt = 0; mt < 4; mt++)
        aAddr[mt] = aSm + (unsigned)((wr * 64 + mt * 16 + lrow) * 80 + lkof);
    #pragma unroll
    for (int np = 0; np < 2; np++)
        bAddr[np] = bSm + (unsigned)((wc * 32 + np * 16 + lrow) * 80 + lkof);

    float acc[4][4][4];
    #pragma unroll
    for (int i = 0; i < 4; i++)
        #pragma unroll
        for (int j = 0; j < 4; j++)
            #pragma unroll
            for (int c = 0; c < 4; c++) acc[i][j][c] = 0.f;

    // prologue: stage 0
    cpa16(&As[0][r0 * HAW + w0], Ag + (size_t)r0 * K + kc0);
    cpa16(&As[0][r1 * HAW + w1], Ag + (size_t)r1 * K + kc1);
    cpa16(&Bs[0][r0 * HAW + w0], Bg + (size_t)r0 * K + kc0);
    cpa16(&Bs[0][r1 * HAW + w1], Bg + (size_t)r1 * K + kc1);
    CP_COMMIT();

    int nIter = K >> 5;
    for (int it = 0; it < nIter; it++) {
        int cur = it & 1;
        CP_WAIT0();
        __syncthreads();
        if (it + 1 < nIter) {
            int nxt = cur ^ 1;
            int k0n = (it + 1) << 5;
            cpa16(&As[nxt][r0 * HAW + w0], Ag + (size_t)r0 * K + k0n + kc0);
            cpa16(&As[nxt][r1 * HAW + w1], Ag + (size_t)r1 * K + k0n + kc1);
            cpa16(&Bs[nxt][r0 * HAW + w0], Bg + (size_t)r0 * K + k0n + kc0);
            cpa16(&Bs[nxt][r1 * HAW + w1], Bg + (size_t)r1 * K + k0n + kc1);
            CP_COMMIT();
        }

        unsigned stOfs = (unsigned)(cur * HSTG_B);
        #pragma unroll
        for (int kk8 = 0; kk8 < 16; kk8 += 8) {   // two k16 sub-slices (word units)
            unsigned kOfs = stOfs + (unsigned)(kk8 * 4);   // FIX: words -> bytes
            unsigned afr[4][4], bq[2][4], bfr[4][2];
            #pragma unroll
            for (int mt = 0; mt < 4; mt++)
                LDSM4(afr[mt], aAddr[mt] + kOfs);
            #pragma unroll
            for (int np = 0; np < 2; np++)
                LDSM4(bq[np], bAddr[np] + kOfs);
            // unpack B quads: mat0 = n0-7 k0-7, mat1 = n8-15 k0-7, mat2/3 = k8-15
            #pragma unroll
            for (int np = 0; np < 2; np++) {
                bfr[np * 2][0]     = bq[np][0];
                bfr[np * 2][1]     = bq[np][2];
                bfr[np * 2 + 1][0] = bq[np][1];
                bfr[np * 2 + 1][1] = bq[np][3];
            }
            #pragma unroll
            for (int mt = 0; mt < 4; mt++)
                #pragma unroll
                for (int nt = 0; nt < 4; nt++)
                    MMA_F16(acc[mt][nt], afr[mt], bfr[nt]);
        }
        __syncthreads();
    }

    #pragma unroll
    for (int mt = 0; mt < 4; mt++) {
        int row0 = by * 128 + wr * 64 + mt * 16 + grp;
        #pragma unroll
        for (int nt = 0; nt < 4; nt++) {
            int col = bx * 128 + wc * 32 + nt * 8 + tg * 2;
            float* p0 = C + (size_t)row0 * N + col;
            float* p1 = C + (size_t)(row0 + 8) * N + col;
            if (ACC) {
                float2 cc0 = *(float2*)p0, cc1 = *(float2*)p1;
                cc0.x += acc[mt][nt][0]; cc0.y += acc[mt][nt][1];
                cc1.x += acc[mt][nt][2]; cc1.y += acc[mt][nt][3];
                *(float2*)p0 = cc0; *(float2*)p1 = cc1;
            } else {
                *(float2*)p0 = make_float2(acc[mt][nt][0], acc[mt][nt][1]);
                *(float2*)p1 = make_float2(acc[mt][nt][2], acc[mt][nt][3]);
            }
        }
    }
}

template <bool ACC>
__global__ void __launch_bounds__(256, 2)
gemm_h(const __half* __restrict__ A, const __half* __restrict__ BT,
       float* __restrict__ C, int N, int K) {
    gemm_h_core<ACC>(A, BT, C, N, K, blockIdx.x, blockIdx.y);
}

__global__ void __launch_bounds__(256, 2)
gemm_qkv_h(const __half* __restrict__ A,
           const __half* __restrict__ WqT, const __half* __restrict__ WkT,
           const __half* __restrict__ WvT,
           float* __restrict__ q, float* __restrict__ k, float* __restrict__ v) {
    int bx = blockIdx.x;
    if (bx < 8)       gemm_h_core<false>(A, WqT, q, 1024, D_, bx,      blockIdx.y);
    else if (bx < 12) gemm_h_core<false>(A, WkT, k,  512, D_, bx - 8,  blockIdx.y);
    else              gemm_h_core<false>(A, WvT, v,  512, D_, bx - 12, blockIdx.y);
}

__global__ void __launch_bounds__(256, 2)
gemm_gateup_h(const __half* __restrict__ A,
              const __half* __restrict__ WgT, const __half* __restrict__ WuT,
              float* __restrict__ gate, float* __restrict__ up) {
    int bx = blockIdx.x;
    if (bx < 24) gemm_h_core<false>(A, WgT, gate, FF_, D_, bx,      blockIdx.y);
    else         gemm_h_core<false>(A, WuT, up,   FF_, D_, bx - 24, blockIdx.y);
}

// ---------------- fused per-head rmsnorm + RoPE for q AND k (fp32) ----------------
#define LOG2_THETA 19.9315685693241741f
__global__ void qknorm_rope_kernel(float* __restrict__ q, float* __restrict__ k,
                                   const float* __restrict__ qw,
                                   const float* __restrict__ kw) {
    int warp = (blockIdx.x * blockDim.x + threadIdx.x) >> 5;
    int lane = threadIdx.x & 31;
    float* p; const float* w; int token;
    if (warp < TOK_ * H_) {
        p = q + (size_t)warp * HD_; w = qw; token = warp / H_;
    } else {
        int w2 = warp - TOK_ * H_;
        p = k + (size_t)w2 * HD_; w = kw; token = w2 / HK_;
    }
    int s = token & (S_ - 1);
    float a = p[lane], b = p[lane + 32];
    float ss = a * a + b * b;
    #pragma unroll
    for (int o = 16; o; o >>= 1) ss += __shfl_xor_sync(0xffffffffu, ss, o);
    float scale = rsqrtf(ss * (1.0f / HD_) + 1e-6f);
    a *= scale * w[lane];
    b *= scale * w[lane + 32];
    float inv = exp2f(-(float)lane * (LOG2_THETA / 32.0f));
    float ang = (float)s * inv;
    float c = cosf(ang), sn = sinf(ang);
    p[lane]      = a * c - b * sn;
    p[lane + 32] = b * c + a * sn;
}

// ---------------- tensor-core flash attention: 2 GQA heads/CTA, cp.async K/V ----------------
#define QST 68
#define KST 68
#define VST 72
#define PST 36
#define KVBUF (32 * KST + 32 * VST)
#define ATT_SMEM ((2 * 64 * QST + 2 * KVBUF + 2 * 64 * PST) * 4)
__global__ void __launch_bounds__(256, 2)
attn_mma_kernel(const float* __restrict__ q, const float* __restrict__ k,
                const float* __restrict__ v, const int* __restrict__ amask,
                __half* __restrict__ out, int win) {
    extern __shared__ float asm_[];
    float* Qs  = asm_;
    float* KV0 = Qs + 2 * 64 * QST;
    float* KV1 = KV0 + KVBUF;
    float* Ps  = KV1 + KVBUF;

    int b = blockIdx.z, kh = blockIdx.y;
    int q0 = blockIdx.x * 64;
    int tid = threadIdx.x;
    int lane = tid & 31, wid = tid >> 5;
    int hg = wid >> 2;
    int h = kh * 2 + hg;
    int m0 = (wid & 3) * 16;
    int tg = lane & 3, grp = lane >> 2;
    int qpos0 = q0 + m0 + grp;
    int qpos1 = qpos0 + 8;

    float* Qsh = Qs + hg * 64 * QST;
    float* Psh = Ps + hg * 64 * PST;

    for (int i = tid; i < 128 * 16; i += 256) {
        int r = i >> 4;
        int hgi = r >> 6, rr = r & 63;
        int c4 = (i & 15) << 2;
        float4 f = *(const float4*)(q + (size_t)(b * S_ + q0 + rr) * (H_ * HD_)
                                      + (kh * 2 + hgi) * HD_ + c4);
        float* dst = Qs + hgi * 64 * QST + rr * QST + c4;
        dst[0] = tfr(f.x); dst[1] = tfr(f.y); dst[2] = tfr(f.z); dst[3] = tfr(f.w);
    }
    __syncthreads();

    unsigned qfr[8][4];
    #pragma unroll
    for (int s8 = 0; s8 < 8; s8++) {
        int k8 = s8 * 8;
        qfr[s8][0] = __float_as_uint(Qsh[(m0 + grp) * QST + k8 + tg]);
        qfr[s8][1] = __float_as_uint(Qsh[(m0 + grp + 8) * QST + k8 + tg]);
        qfr[s8][2] = __float_as_uint(Qsh[(m0 + grp) * QST + k8 + tg + 4]);
        qfr[s8][3] = __float_as_uint(Qsh[(m0 + grp + 8) * QST + k8 + tg + 4]);
    }

    float oacc[8][4];
    #pragma unroll
    for (int i = 0; i < 8; i++)
        #pragma unroll
        for (int j = 0; j < 4; j++) oacc[i][j] = 0.f;
    float mr0 = -1e30f, mr1 = -1e30f, l0 = 0.f, l1 = 0.f;

    int kt_lo = 0, kt_hi = (S_ / 32) - 1;
    if (win >= 0) {
        int lo = q0 - win; if (lo < 0) lo = 0;
        int hi = q0 + 63 + win; if (hi > S_ - 1) hi = S_ - 1;
        kt_lo = lo >> 5; kt_hi = hi >> 5;
    }
    const float scale = 0.125f;

    int i0 = tid, i1 = tid + 256;
    int r0c = i0 >> 4, c40 = (i0 & 15) << 2;
    int r1c = i1 >> 4, c41 = (i1 & 15) << 2;

    #define ISSUE_KV(kt_, buf_) {                                                    \
        float* kb = (buf_) ? KV1 : KV0;                                              \
        float* vb = kb + 32 * KST;                                                   \
        size_t o0 = (size_t)(b * S_ + (kt_) * 32 + r0c) * (HK_ * HD_) + kh * HD_ + c40; \
        size_t o1 = (size_t)(b * S_ + (kt_) * 32 + r1c) * (HK_ * HD_) + kh * HD_ + c41; \
        cpa16(&kb[r0c * KST + c40], k + o0);                                         \
        cpa16(&kb[r1c * KST + c41], k + o1);                                         \
        cpa16(&vb[r0c * VST + c40], v + o0);                                         \
        cpa16(&vb[r1c * VST + c41], v + o1);                                         \
        CP_COMMIT();                                                                 \
    }

    ISSUE_KV(kt_lo, 0);

    for (int kt = kt_lo; kt <= kt_hi; kt++) {
        int cur = (kt - kt_lo) & 1;
        __syncthreads();
        if (kt + 1 <= kt_hi) {
            ISSUE_KV(kt + 1, cur ^ 1);
            CP_WAIT1();
        } else {
            CP_WAIT0();
        }
        __syncthreads();

        const float* Kc = (cur ? KV1 : KV0);
        const float* Vc = Kc + 32 * KST;

        float sc[4][4];
        #pragma unroll
        for (int i = 0; i < 4; i++)
            #pragma unroll
            for (int j = 0; j < 4; j++) sc[i][j] = 0.f;
        #pragma unroll
        for (int s8 = 0; s8 < 8; s8++) {
            int k8 = s8 * 8;
            #pragma unroll
            for (int nt = 0; nt < 4; nt++) {
                unsigned bb[2];
                bb[0] = f2tf(Kc[(nt * 8 + grp) * KST + k8 + tg]);
                bb[1] = f2tf(Kc[(nt * 8 + grp) * KST + k8 + tg + 4]);
                MMA_TF32(sc[nt], qfr[s8], bb);
            }
        }

        const int* am = amask + b * S_ + kt * 32;
        float v0[8], v1[8];
        #pragma unroll
        for (int nt = 0; nt < 4; nt++) {
            int kc0 = nt * 8 + 2 * tg, kc1 = kc0 + 1;
            int kp0 = kt * 32 + kc0, kp1 = kt * 32 + kc1;
            float mk0 = (am[kc0] != 0) ? 0.f : -1e30f;
            float mk1 = (am[kc1] != 0) ? 0.f : -1e30f;
            float a0 = sc[nt][0] * scale + mk0;
            float a1 = sc[nt][1] * scale + mk1;
            float b0 = sc[nt][2] * scale + mk0;
            float b1 = sc[nt][3] * scale + mk1;
            if (win >= 0) {
                if (abs(qpos0 - kp0) > win) a0 = -1e30f;
                if (abs(qpos0 - kp1) > win) a1 = -1e30f;
                if (abs(qpos1 - kp0) > win) b0 = -1e30f;
                if (abs(qpos1 - kp1) > win) b1 = -1e30f;
            }
            v0[nt * 2] = a0; v0[nt * 2 + 1] = a1;
            v1[nt * 2] = b0; v1[nt * 2 + 1] = b1;
        }
        float tm0 = -1e30f, tm1 = -1e30f;
        #pragma unroll
        for (int j = 0; j < 8; j++) { tm0 = fmaxf(tm0, v0[j]); tm1 = fmaxf(tm1, v1[j]); }
        tm0 = fmaxf(tm0, __shfl_xor_sync(0xffffffffu, tm0, 1));
        tm0 = fmaxf(tm0, __shfl_xor_sync(0xffffffffu, tm0, 2));
        tm1 = fmaxf(tm1, __shfl_xor_sync(0xffffffffu, tm1, 1));
        tm1 = fmaxf(tm1, __shfl_xor_sync(0xffffffffu, tm1, 2));
        float nm0 = fmaxf(mr0, tm0), nm1 = fmaxf(mr1, tm1);
        float al0 = __expf(mr0 - nm0), al1 = __expf(mr1 - nm1);
        mr0 = nm0; mr1 = nm1;
        float ps0 = 0.f, ps1 = 0.f;
        #pragma unroll
        for (int nt = 0; nt < 4; nt++) {
            float p00 = __expf(v0[nt * 2]     - nm0);
            float p01 = __expf(v0[nt * 2 + 1] - nm0);
            float p10 = __expf(v1[nt * 2]     - nm1);
            float p11 = __expf(v1[nt * 2 + 1] - nm1);
            ps0 += p00 + p01; ps1 += p10 + p11;
            int col = nt * 8 + 2 * tg;
            *(float2*)&Psh[(m0 + grp) * PST + col]     = make_float2(tfr(p00), tfr(p01));
            *(float2*)&Psh[(m0 + grp + 8) * PST + col] = make_float2(tfr(p10), tfr(p11));
        }
        ps0 += __shfl_xor_sync(0xffffffffu, ps0, 1);
        ps0 += __shfl_xor_sync(0xffffffffu, ps0, 2);
        ps1 += __shfl_xor_sync(0xffffffffu, ps1, 1);
        ps1 += __shfl_xor_sync(0xffffffffu, ps1, 2);
        l0 = l0 * al0 + ps0;
        l1 = l1 * al1 + ps1;
        #pragma unroll
        for (int nt = 0; nt < 8; nt++) {
            oacc[nt][0] *= al0; oacc[nt][1] *= al0;
            oacc[nt][2] *= al1; oacc[nt][3] *= al1;
        }
        __syncwarp();

        #pragma unroll
        for (int k8 = 0; k8 < 32; k8 += 8) {
            unsigned a[4];
            a[0] = __float_as_uint(Psh[(m0 + grp) * PST + k8 + tg]);
            a[1] = __float_as_uint(Psh[(m0 + grp + 8) * PST + k8 + tg]);
            a[2] = __float_as_uint(Psh[(m0 + grp) * PST + k8 + tg + 4]);
            a[3] = __float_as_uint(Psh[(m0 + grp + 8) * PST + k8 + tg + 4]);
            #pragma unroll
            for (int nt = 0; nt < 8; nt++) {
                unsigned bb[2];
                bb[0] = f2tf(Vc[(k8 + tg) * VST + nt * 8 + grp]);
                bb[1] = f2tf(Vc[(k8 + tg + 4) * VST + nt * 8 + grp]);
                MMA_TF32(oacc[nt], a, bb);
            }
        }
    }

    float il0 = 1.0f / l0, il1 = 1.0f / l1;
    #pragma unroll
    for (int nt = 0; nt < 8; nt++) {
        int col = h * HD_ + nt * 8 + 2 * tg;
        __half2* p0 = (__half2*)(out + (size_t)(b * S_ + qpos0) * (H_ * HD_) + col);
        __half2* p1 = (__half2*)(out + (size_t)(b * S_ + qpos1) * (H_ * HD_) + col);
        *p0 = __floats2half2_rn(oacc[nt][0] * il0, oacc[nt][1] * il0);
        *p1 = __floats2half2_rn(oacc[nt][2] * il1, oacc[nt][3] * il1);
    }
}

// ---------------- SwiGLU elementwise: gateh = fp16(silu(gate) * up) ----------------
__global__ void silu_mul_kernel(const float* __restrict__ gate,
                                const float* __restrict__ up,
                                __half* __restrict__ outh, int n4) {
    int i = blockIdx.x * blockDim.x + threadIdx.x;
    if (i < n4) {
        float4 g = *(const float4*)(gate + i * 4);
        float4 u = *(const float4*)(up + i * 4);
        float r0 = g.x / (1.0f + __expf(-g.x)) * u.x;
        float r1 = g.y / (1.0f + __expf(-g.y)) * u.y;
        float r2 = g.z / (1.0f + __expf(-g.z)) * u.z;
        float r3 = g.w / (1.0f + __expf(-g.w)) * u.w;
        __half2* dst = (__half2*)(outh + (size_t)i * 4);
        dst[0] = __floats2half2_rn(r0, r1);
        dst[1] = __floats2half2_rn(r2, r3);
    }
}

// ---------------- host orchestration ----------------
extern "C" void kernel_launch(void* const* d_in, const int* in_sizes, int n_in,
                              void* d_out, int out_size) {
    const float* x      = (const float*)d_in[0];
    const float* wq     = (const float*)d_in[1];
    const float* wk     = (const float*)d_in[2];
    const float* wv     = (const float*)d_in[3];
    const float* wo     = (const float*)d_in[4];
    const float* qnw    = (const float*)d_in[5];
    const float* knw    = (const float*)d_in[6];
    const float* ln1    = (const float*)d_in[7];
    const float* ln2    = (const float*)d_in[8];
    const float* wg     = (const float*)d_in[9];
    const float* wu     = (const float*)d_in[10];
    const float* wd     = (const float*)d_in[11];
    const float* normw  = (const float*)d_in[12];
    const int*   amask  = (const int*)d_in[13];

    float *h, *q, *k, *v, *gate, *up;
    __half *nh, *atth, *gateh;
    __half *wqt, *wkt, *wvt, *wot, *wgt, *wut, *wdt;
    cudaGetSymbolAddress((void**)&h,     g_h);
    cudaGetSymbolAddress((void**)&q,     g_q);
    cudaGetSymbolAddress((void**)&k,     g_k);
    cudaGetSymbolAddress((void**)&v,     g_v);
    cudaGetSymbolAddress((void**)&gate,  g_gate);
    cudaGetSymbolAddress((void**)&up,    g_up);
    cudaGetSymbolAddress((void**)&nh,    g_nh);
    cudaGetSymbolAddress((void**)&atth,  g_atth);
    cudaGetSymbolAddress((void**)&gateh, g_gateh);
    cudaGetSymbolAddress((void**)&wqt,   g_wqt);
    cudaGetSymbolAddress((void**)&wkt,   g_wkt);
    cudaGetSymbolAddress((void**)&wvt,   g_wvt);
    cudaGetSymbolAddress((void**)&wot,   g_wot);
    cudaGetSymbolAddress((void**)&wgt,   g_wgt);
    cudaGetSymbolAddress((void**)&wut,   g_wut);
    cudaGetSymbolAddress((void**)&wdt,   g_wdt);

    cudaFuncSetAttribute(attn_mma_kernel,
        cudaFuncAttributeMaxDynamicSharedMemorySize, ATT_SMEM);

    // per-call weight convert + transpose: fp32 [K][N] -> fp16 [N][K]
    dim3 tb(32, 8);
    convT_kernel<<<dim3(D_ / 32, (H_ * HD_) / 32, L_), tb>>>(wq, wqt, D_, H_ * HD_);
    convT_kernel<<<dim3(D_ / 32, (HK_ * HD_) / 32, L_), tb>>>(wk, wkt, D_, HK_ * HD_);
    convT_kernel<<<dim3(D_ / 32, (HK_ * HD_) / 32, L_), tb>>>(wv, wvt, D_, HK_ * HD_);
    convT_kernel<<<dim3((H_ * HD_) / 32, D_ / 32, L_), tb>>>(wo, wot, H_ * HD_, D_);
    convT_kernel<<<dim3(D_ / 32, FF_ / 32, L_), tb>>>(wg, wgt, D_, FF_);
    convT_kernel<<<dim3(D_ / 32, FF_ / 32, L_), tb>>>(wu, wut, D_, FF_);
    convT_kernel<<<dim3(FF_ / 32, D_ / 32, L_), tb>>>(wd, wdt, FF_, D_);

    cudaMemcpyAsync(h, x, (size_t)TOK_ * D_ * sizeof(float),
                    cudaMemcpyDeviceToDevice, 0);

    dim3 gQKV (16, TOK_ / 128);              // 512 blocks
    dim3 gGU  (48, TOK_ / 128);              // 1536 blocks
    dim3 g1024(D_ / 128, TOK_ / 128);        // 256 blocks
    int ropeWarps = TOK_ * (H_ + HK_);

    for (int l = 0; l < L_; l++) {
        const __half* wqt_l = wqt + (size_t)l * D_ * H_ * HD_;
        const __half* wkt_l = wkt + (size_t)l * D_ * HK_ * HD_;
        const __half* wvt_l = wvt + (size_t)l * D_ * HK_ * HD_;
        const __half* wot_l = wot + (size_t)l * H_ * HD_ * D_;
        const __half* wgt_l = wgt + (size_t)l * D_ * FF_;
        const __half* wut_l = wut + (size_t)l * D_ * FF_;
        const __half* wdt_l = wdt + (size_t)l * FF_ * D_;

        rmsnorm_h_kernel<<<TOK_, 256>>>(h, ln1 + l * D_, nh);

        gemm_qkv_h<<<gQKV, 256>>>(nh, wqt_l, wkt_l, wvt_l, q, k, v);

        qknorm_rope_kernel<<<ropeWarps / 4, 128>>>(q, k, qnw + l * HD_, knw + l * HD_);

        attn_mma_kernel<<<dim3(S_ / 64, HK_, B_), 256, ATT_SMEM>>>(
            q, k, v, amask, atth, (l & 1) ? WIN_ : -1);

        gemm_h<true><<<g1024, 256>>>(atth, wot_l, h, D_, H_ * HD_);

        rmsnorm_h_kernel<<<TOK_, 256>>>(h, ln2 + l * D_, nh);

        gemm_gateup_h<<<gGU, 256>>>(nh, wgt_l, wut_l, gate, up);

        int n4 = TOK_ * FF_ / 4;
        silu_mul_kernel<<<(n4 + 255) / 256, 256>>>(gate, up, gateh, n4);

        gemm_h<true><<<g1024, 256>>>(gateh, wdt_l, h, D_, FF_);
    }

    rmsnorm_kernel<<<TOK_, 256>>>(h, normw, (float*)d_out);
}

// round 15
// speedup vs baseline: 1.7182x; 1.0283x over previous
#include <cuda_runtime.h>
#include <cuda_fp16.h>
#include <math.h>
#include <float.h>

#define D_    1024
#define H_    16
#define HK_   8
#define HD_   64
#define FF_   3072
#define S_    1024
#define B_    4
#define TOK_  4096   // B*S
#define L_    4
#define WIN_  12

// ---------------- scratch (no allocations allowed) ----------------
__device__ float  g_h   [TOK_ * D_];
__device__ __half g_q   [TOK_ * H_  * HD_];   // fp16 now
__device__ __half g_k   [TOK_ * HK_ * HD_];   // fp16 now
__device__ float  g_v   [TOK_ * HK_ * HD_];
__device__ float  g_gate[TOK_ * FF_];
__device__ float  g_up  [TOK_ * FF_];
// fp16 activation buffers
__device__ __half g_nh   [TOK_ * D_];
__device__ __half g_atth [TOK_ * H_ * HD_];
__device__ __half g_gateh[TOK_ * FF_];
// fp16 transposed weights [N][K]
__device__ __half g_wqt[L_ * D_ * H_ * HD_];
__device__ __half g_wkt[L_ * D_ * HK_ * HD_];
__device__ __half g_wvt[L_ * D_ * HK_ * HD_];
__device__ __half g_wot[L_ * H_ * HD_ * D_];
__device__ __half g_wgt[L_ * D_ * FF_];
__device__ __half g_wut[L_ * D_ * FF_];
__device__ __half g_wdt[L_ * FF_ * D_];

// ---------------- helpers ----------------
__device__ __forceinline__ unsigned f2tf(float x) {
    unsigned r;
    asm("cvt.rna.tf32.f32 %0, %1;" : "=r"(r) : "f"(x));
    return r;
}
__device__ __forceinline__ float tfr(float x) { return __uint_as_float(f2tf(x)); }
__device__ __forceinline__ void cpa16(void* dst_smem, const void* src_gmem) {
    unsigned d = (unsigned)__cvta_generic_to_shared(dst_smem);
    asm volatile("cp.async.cg.shared.global [%0], [%1], 16;"
                 :: "r"(d), "l"(src_gmem));
}
#define CP_COMMIT()  asm volatile("cp.async.commit_group;")
#define CP_WAIT0()   asm volatile("cp.async.wait_group 0;")
#define CP_WAIT1()   asm volatile("cp.async.wait_group 1;")

#define MMA_TF32(acc, a, b)                                              \
    asm volatile(                                                        \
        "mma.sync.aligned.m16n8k8.row.col.f32.tf32.tf32.f32 "            \
        "{%0,%1,%2,%3}, {%4,%5,%6,%7}, {%8,%9}, {%0,%1,%2,%3};"          \
        : "+f"((acc)[0]), "+f"((acc)[1]), "+f"((acc)[2]), "+f"((acc)[3]) \
        : "r"((a)[0]), "r"((a)[1]), "r"((a)[2]), "r"((a)[3]),            \
          "r"((b)[0]), "r"((b)[1]))

#define MMA_F16(acc, a, b)                                               \
    asm volatile(                                                        \
        "mma.sync.aligned.m16n8k16.row.col.f32.f16.f16.f32 "             \
        "{%0,%1,%2,%3}, {%4,%5,%6,%7}, {%8,%9}, {%0,%1,%2,%3};"          \
        : "+f"((acc)[0]), "+f"((acc)[1]), "+f"((acc)[2]), "+f"((acc)[3]) \
        : "r"((a)[0]), "r"((a)[1]), "r"((a)[2]), "r"((a)[3]),            \
          "r"((b)[0]), "r"((b)[1]))

#define LDSM4(r, addr)                                                   \
    asm volatile("ldmatrix.sync.aligned.m8n8.x4.shared.b16 "             \
                 "{%0,%1,%2,%3}, [%4];"                                  \
                 : "=r"((r)[0]), "=r"((r)[1]), "=r"((r)[2]), "=r"((r)[3])\
                 : "r"(addr))

// ---------------- weight fp32[K][N] -> fp16 transposed [N][K] ----------------
__global__ void convT_kernel(const float* __restrict__ src, __half* __restrict__ dst,
                             int K, int N) {
    __shared__ float tile[32][33];
    size_t lofs = (size_t)blockIdx.z * K * N;
    src += lofs; dst += lofs;
    int k0 = blockIdx.x * 32, n0 = blockIdx.y * 32;
    for (int i = threadIdx.y; i < 32; i += 8)
        tile[i][threadIdx.x] = src[(size_t)(k0 + i) * N + n0 + threadIdx.x];
    __syncthreads();
    for (int i = threadIdx.y; i < 32; i += 8)
        dst[(size_t)(n0 + i) * K + k0 + threadIdx.x] = __float2half(tile[threadIdx.x][i]);
}

// ---------------- rmsnorm (fp32 out, for final) ----------------
__global__ void rmsnorm_kernel(const float* __restrict__ x,
                               const float* __restrict__ w,
                               float* __restrict__ out) {
    int row = blockIdx.x;
    const float* xr = x + (size_t)row * D_;
    int t = threadIdx.x;
    float4 v = *(const float4*)(xr + t * 4);
    float ss = v.x * v.x + v.y * v.y + v.z * v.z + v.w * v.w;
    #pragma unroll
    for (int o = 16; o; o >>= 1) ss += __shfl_xor_sync(0xffffffffu, ss, o);
    __shared__ float sh[8];
    if ((t & 31) == 0) sh[t >> 5] = ss;
    __syncthreads();
    float tot = 0.f;
    #pragma unroll
    for (int i = 0; i < 8; i++) tot += sh[i];
    float scale = rsqrtf(tot * (1.0f / D_) + 1e-6f);
    float4 wv = *(const float4*)(w + t * 4);
    float4 o4;
    o4.x = v.x * scale * wv.x;
    o4.y = v.y * scale * wv.y;
    o4.z = v.z * scale * wv.z;
    o4.w = v.w * scale * wv.w;
    *(float4*)(out + (size_t)row * D_ + t * 4) = o4;
}

// ---------------- rmsnorm (fp16 out, feeds GEMMs) ----------------
__global__ void rmsnorm_h_kernel(const float* __restrict__ x,
                                 const float* __restrict__ w,
                                 __half* __restrict__ out) {
    int row = blockIdx.x;
    const float* xr = x + (size_t)row * D_;
    int t = threadIdx.x;
    float4 v = *(const float4*)(xr + t * 4);
    float ss = v.x * v.x + v.y * v.y + v.z * v.z + v.w * v.w;
    #pragma unroll
    for (int o = 16; o; o >>= 1) ss += __shfl_xor_sync(0xffffffffu, ss, o);
    __shared__ float sh[8];
    if ((t & 31) == 0) sh[t >> 5] = ss;
    __syncthreads();
    float tot = 0.f;
    #pragma unroll
    for (int i = 0; i < 8; i++) tot += sh[i];
    float scale = rsqrtf(tot * (1.0f / D_) + 1e-6f);
    float4 wv = *(const float4*)(w + t * 4);
    __half2 h0 = __floats2half2_rn(v.x * scale * wv.x, v.y * scale * wv.y);
    __half2 h1 = __floats2half2_rn(v.z * scale * wv.z, v.w * scale * wv.w);
    __half2* dst = (__half2*)(out + (size_t)row * D_ + t * 4);
    dst[0] = h0; dst[1] = h1;
}

// ---------------- FP16 tensor-core GEMM (2-stage cp.async, BK=32, ldmatrix) ----------------
// HOUT=false: fp32 C (optional ACC). HOUT=true: fp16 C (no ACC).
#define HAW 20                       // words per smem row
#define HSTG_B (128 * HAW * 4)       // bytes per stage per matrix
template <bool ACC, bool HOUT>
__device__ __forceinline__ void gemm_h_core(const __half* __restrict__ A,
                                            const __half* __restrict__ BT,
                                            void* __restrict__ Cv,
                                            int N, int K, int bx, int by) {
    __shared__ unsigned As[2][128 * HAW];
    __shared__ unsigned Bs[2][128 * HAW];

    int tid = threadIdx.x;
    int lane = tid & 31, wid = tid >> 5;
    int wr = wid >> 2;          // 0..1
    int wc = wid & 3;           // 0..3
    int tg = lane & 3;
    int grp = lane >> 2;

    const __half* Ag = A + (size_t)(by * 128) * K;
    const __half* Bg = BT + (size_t)(bx * 128) * K;

    int c0 = tid * 2, c1 = c0 + 1;
    int r0 = c0 >> 2, kc0 = (c0 & 3) << 3;
    int r1 = c1 >> 2, kc1 = (c1 & 3) << 3;
    int w0 = kc0 >> 1, w1 = kc1 >> 1;

    unsigned aSm = (unsigned)__cvta_generic_to_shared(&As[0][0]);
    unsigned bSm = (unsigned)__cvta_generic_to_shared(&Bs[0][0]);
    int lrow = lane & 15;
    int lkof = (lane >> 4) * 16;
    unsigned aAddr[4], bAddr[2];
    #pragma unroll
    for (int mt = 0; mt < 4; mt++)
        aAddr[mt] = aSm + (unsigned)((wr * 64 + mt * 16 + lrow) * 80 + lkof);
    #pragma unroll
    for (int np = 0; np < 2; np++)
        bAddr[np] = bSm + (unsigned)((wc * 32 + np * 16 + lrow) * 80 + lkof);

    float acc[4][4][4];
    #pragma unroll
    for (int i = 0; i < 4; i++)
        #pragma unroll
        for (int j = 0; j < 4; j++)
            #pragma unroll
            for (int c = 0; c < 4; c++) acc[i][j][c] = 0.f;

    cpa16(&As[0][r0 * HAW + w0], Ag + (size_t)r0 * K + kc0);
    cpa16(&As[0][r1 * HAW + w1], Ag + (size_t)r1 * K + kc1);
    cpa16(&Bs[0][r0 * HAW + w0], Bg + (size_t)r0 * K + kc0);
    cpa16(&Bs[0][r1 * HAW + w1], Bg + (size_t)r1 * K + kc1);
    CP_COMMIT();

    int nIter = K >> 5;
    for (int it = 0; it < nIter; it++) {
        int cur = it & 1;
        CP_WAIT0();
        __syncthreads();
        if (it + 1 < nIter) {
            int nxt = cur ^ 1;
            int k0n = (it + 1) << 5;
            cpa16(&As[nxt][r0 * HAW + w0], Ag + (size_t)r0 * K + k0n + kc0);
            cpa16(&As[nxt][r1 * HAW + w1], Ag + (size_t)r1 * K + k0n + kc1);
            cpa16(&Bs[nxt][r0 * HAW + w0], Bg + (size_t)r0 * K + k0n + kc0);
            cpa16(&Bs[nxt][r1 * HAW + w1], Bg + (size_t)r1 * K + k0n + kc1);
            CP_COMMIT();
        }

        unsigned stOfs = (unsigned)(cur * HSTG_B);
        #pragma unroll
        for (int kk8 = 0; kk8 < 16; kk8 += 8) {
            unsigned kOfs = stOfs + (unsigned)(kk8 * 4);
            unsigned afr[4][4], bq[2][4], bfr[4][2];
            #pragma unroll
            for (int mt = 0; mt < 4; mt++)
                LDSM4(afr[mt], aAddr[mt] + kOfs);
            #pragma unroll
            for (int np = 0; np < 2; np++)
                LDSM4(bq[np], bAddr[np] + kOfs);
            #pragma unroll
            for (int np = 0; np < 2; np++) {
                bfr[np * 2][0]     = bq[np][0];
                bfr[np * 2][1]     = bq[np][2];
                bfr[np * 2 + 1][0] = bq[np][1];
                bfr[np * 2 + 1][1] = bq[np][3];
            }
            #pragma unroll
            for (int mt = 0; mt < 4; mt++)
                #pragma unroll
                for (int nt = 0; nt < 4; nt++)
                    MMA_F16(acc[mt][nt], afr[mt], bfr[nt]);
        }
        __syncthreads();
    }

    #pragma unroll
    for (int mt = 0; mt < 4; mt++) {
        int row0 = by * 128 + wr * 64 + mt * 16 + grp;
        #pragma unroll
        for (int nt = 0; nt < 4; nt++) {
            int col = bx * 128 + wc * 32 + nt * 8 + tg * 2;
            if (HOUT) {
                __half* C = (__half*)Cv;
                __half2* p0 = (__half2*)(C + (size_t)row0 * N + col);
                __half2* p1 = (__half2*)(C + (size_t)(row0 + 8) * N + col);
                *p0 = __floats2half2_rn(acc[mt][nt][0], acc[mt][nt][1]);
                *p1 = __floats2half2_rn(acc[mt][nt][2], acc[mt][nt][3]);
            } else {
                float* C = (float*)Cv;
                float* p0 = C + (size_t)row0 * N + col;
                float* p1 = C + (size_t)(row0 + 8) * N + col;
                if (ACC) {
                    float2 cc0 = *(float2*)p0, cc1 = *(float2*)p1;
                    cc0.x += acc[mt][nt][0]; cc0.y += acc[mt][nt][1];
                    cc1.x += acc[mt][nt][2]; cc1.y += acc[mt][nt][3];
                    *(float2*)p0 = cc0; *(float2*)p1 = cc1;
                } else {
                    *(float2*)p0 = make_float2(acc[mt][nt][0], acc[mt][nt][1]);
                    *(float2*)p1 = make_float2(acc[mt][nt][2], acc[mt][nt][3]);
                }
            }
        }
    }
}

template <bool ACC>
__global__ void __launch_bounds__(256, 2)
gemm_h(const __half* __restrict__ A, const __half* __restrict__ BT,
       float* __restrict__ C, int N, int K) {
    gemm_h_core<ACC, false>(A, BT, C, N, K, blockIdx.x, blockIdx.y);
}

// QKV: q,k written fp16; v written fp32
__global__ void __launch_bounds__(256, 2)
gemm_qkv_h(const __half* __restrict__ A,
           const __half* __restrict__ WqT, const __half* __restrict__ WkT,
           const __half* __restrict__ WvT,
           __half* __restrict__ q, __half* __restrict__ k, float* __restrict__ v) {
    int bx = blockIdx.x;
    if (bx < 8)       gemm_h_core<false, true >(A, WqT, q, 1024, D_, bx,      blockIdx.y);
    else if (bx < 12) gemm_h_core<false, true >(A, WkT, k,  512, D_, bx - 8,  blockIdx.y);
    else              gemm_h_core<false, false>(A, WvT, v,  512, D_, bx - 12, blockIdx.y);
}

__global__ void __launch_bounds__(256, 2)
gemm_gateup_h(const __half* __restrict__ A,
              const __half* __restrict__ WgT, const __half* __restrict__ WuT,
              float* __restrict__ gate, float* __restrict__ up) {
    int bx = blockIdx.x;
    if (bx < 24) gemm_h_core<false, false>(A, WgT, gate, FF_, D_, bx,      blockIdx.y);
    else         gemm_h_core<false, false>(A, WuT, up,   FF_, D_, bx - 24, blockIdx.y);
}

// ---------------- fused per-head rmsnorm + RoPE for q AND k (fp16 data) ----------------
#define LOG2_THETA 19.9315685693241741f
__global__ void qknorm_rope_kernel(__half* __restrict__ q, __half* __restrict__ k,
                                   const float* __restrict__ qw,
                                   const float* __restrict__ kw) {
    int warp = (blockIdx.x * blockDim.x + threadIdx.x) >> 5;
    int lane = threadIdx.x & 31;
    __half* p; const float* w; int token;
    if (warp < TOK_ * H_) {
        p = q + (size_t)warp * HD_; w = qw; token = warp / H_;
    } else {
        int w2 = warp - TOK_ * H_;
        p = k + (size_t)w2 * HD_; w = kw; token = w2 / HK_;
    }
    int s = token & (S_ - 1);
    float a = __half2float(p[lane]), b = __half2float(p[lane + 32]);
    float ss = a * a + b * b;
    #pragma unroll
    for (int o = 16; o; o >>= 1) ss += __shfl_xor_sync(0xffffffffu, ss, o);
    float scale = rsqrtf(ss * (1.0f / HD_) + 1e-6f);
    a *= scale * w[lane];
    b *= scale * w[lane + 32];
    float inv = exp2f(-(float)lane * (LOG2_THETA / 32.0f));
    float ang = (float)s * inv;
    float c = cosf(ang), sn = sinf(ang);
    p[lane]      = __float2half(a * c - b * sn);
    p[lane + 32] = __float2half(b * c + a * sn);
}

// ---------------- flash attention: fp16 QK^T, tf32 PV, 2 heads/CTA, cp.async K/V ----------------
#define QSH 72    // halves per Q row
#define KSH 72    // halves per K row
#define VST 72    // floats per V row
#define PST 36    // floats per P row
#define ATT_SMEM ((2 * 64 * PST) * 4 + (2 * 64 * QSH + 2 * 32 * KSH) * 2 + (2 * 32 * VST) * 4)
__global__ void __launch_bounds__(256, 2)
attn_mma_kernel(const __half* __restrict__ q, const __half* __restrict__ k,
                const float* __restrict__ v, const int* __restrict__ amask,
                __half* __restrict__ out, int win) {
    extern __shared__ float asm_[];
    float*  Ps  = asm_;                              // 2 x 64 x PST floats
    __half* Qs  = (__half*)(Ps + 2 * 64 * PST);      // 2 x 64 x QSH halves
    __half* KH0 = Qs + 2 * 64 * QSH;                 // 32 x KSH halves
    __half* KH1 = KH0 + 32 * KSH;
    float*  VF0 = (float*)(KH1 + 32 * KSH);          // 32 x VST floats
    float*  VF1 = VF0 + 32 * VST;

    int b = blockIdx.z, kh = blockIdx.y;
    int q0 = blockIdx.x * 64;
    int tid = threadIdx.x;
    int lane = tid & 31, wid = tid >> 5;
    int hg = wid >> 2;
    int h = kh * 2 + hg;
    int m0 = (wid & 3) * 16;
    int tg = lane & 3, grp = lane >> 2;
    int qpos0 = q0 + m0 + grp;
    int qpos1 = qpos0 + 8;

    __half* Qsh = Qs + hg * 64 * QSH;
    float*  Psh = Ps + hg * 64 * PST;

    // cooperative Q load for BOTH heads (half2 copies)
    for (int i = tid; i < 128 * 32; i += 256) {
        int r = i >> 5;                      // 0..127
        int hgi = r >> 6, rr = r & 63;
        int c2 = (i & 31) * 2;               // half offset, even
        unsigned val = *(const unsigned*)(q + (size_t)(b * S_ + q0 + rr) * (H_ * HD_)
                                            + (kh * 2 + hgi) * HD_ + c2);
        *(unsigned*)&Qs[(hgi * 64 + rr) * QSH + c2] = val;
    }
    __syncthreads();

    // hoist Q fragments: 4 k16-slices x 4 half2 regs
    unsigned qfr[4][4];
    #pragma unroll
    for (int s = 0; s < 4; s++) {
        int kb = s * 16 + 2 * tg;
        qfr[s][0] = *(unsigned*)&Qsh[(m0 + grp) * QSH + kb];
        qfr[s][1] = *(unsigned*)&Qsh[(m0 + grp + 8) * QSH + kb];
        qfr[s][2] = *(unsigned*)&Qsh[(m0 + grp) * QSH + kb + 8];
        qfr[s][3] = *(unsigned*)&Qsh[(m0 + grp + 8) * QSH + kb + 8];
    }

    float oacc[8][4];
    #pragma unroll
    for (int i = 0; i < 8; i++)
        #pragma unroll
        for (int j = 0; j < 4; j++) oacc[i][j] = 0.f;
    float mr0 = -1e30f, mr1 = -1e30f, l0 = 0.f, l1 = 0.f;

    int kt_lo = 0, kt_hi = (S_ / 32) - 1;
    if (win >= 0) {
        int lo = q0 - win; if (lo < 0) lo = 0;
        int hi = q0 + 63 + win; if (hi > S_ - 1) hi = S_ - 1;
        kt_lo = lo >> 5; kt_hi = hi >> 5;
    }
    const float scale = 0.125f;

    // cp.async K (half): 256 chunks of 8 halves, 1/thread.
    int krow = tid >> 3, koff = (tid & 7) * 8;
    // cp.async V (float): 512 chunks of 4 floats, 2/thread.
    int vr0 = tid >> 4,          vo0 = (tid & 15) * 4;
    int vr1 = (tid + 256) >> 4,  vo1 = ((tid + 256) & 15) * 4;

    #define ISSUE_KV(kt_, buf_) {                                                     \
        __half* kb_ = (buf_) ? KH1 : KH0;                                             \
        float*  vb_ = (buf_) ? VF1 : VF0;                                             \
        cpa16(&kb_[krow * KSH + koff],                                                \
              k + (size_t)(b * S_ + (kt_) * 32 + krow) * (HK_ * HD_) + kh * HD_ + koff); \
        cpa16(&vb_[vr0 * VST + vo0],                                                  \
              v + (size_t)(b * S_ + (kt_) * 32 + vr0) * (HK_ * HD_) + kh * HD_ + vo0);   \
        cpa16(&vb_[vr1 * VST + vo1],                                                  \
              v + (size_t)(b * S_ + (kt_) * 32 + vr1) * (HK_ * HD_) + kh * HD_ + vo1);   \
        CP_COMMIT();                                                                  \
    }

    ISSUE_KV(kt_lo, 0);

    for (int kt = kt_lo; kt <= kt_hi; kt++) {
        int cur = (kt - kt_lo) & 1;
        __syncthreads();
        if (kt + 1 <= kt_hi) {
            ISSUE_KV(kt + 1, cur ^ 1);
            CP_WAIT1();
        } else {
            CP_WAIT0();
        }
        __syncthreads();

        const __half* Kc = (cur ? KH1 : KH0);
        const float*  Vc = (cur ? VF1 : VF0);

        // ---- QK^T (fp16 MMA, k16) ----
        float sc[4][4];
        #pragma unroll
        for (int i = 0; i < 4; i++)
            #pragma unroll
            for (int j = 0; j < 4; j++) sc[i][j] = 0.f;
        #pragma unroll
        for (int s = 0; s < 4; s++) {
            int kb = s * 16 + 2 * tg;
            #pragma unroll
            for (int nt = 0; nt < 4; nt++) {
                unsigned bb[2];
                bb[0] = *(const unsigned*)&Kc[(nt * 8 + grp) * KSH + kb];
                bb[1] = *(const unsigned*)&Kc[(nt * 8 + grp) * KSH + kb + 8];
                MMA_F16(sc[nt], qfr[s], bb);
            }
        }

        // ---- mask + online softmax ----
        const int* am = amask + b * S_ + kt * 32;
        float v0[8], v1[8];
        #pragma unroll
        for (int nt = 0; nt < 4; nt++) {
            int kc0 = nt * 8 + 2 * tg, kc1 = kc0 + 1;
            int kp0 = kt * 32 + kc0, kp1 = kt * 32 + kc1;
            float mk0 = (am[kc0] != 0) ? 0.f : -1e30f;
            float mk1 = (am[kc1] != 0) ? 0.f : -1e30f;
            float a0 = sc[nt][0] * scale + mk0;
            float a1 = sc[nt][1] * scale + mk1;
            float b0 = sc[nt][2] * scale + mk0;
            float b1 = sc[nt][3] * scale + mk1;
            if (win >= 0) {
                if (abs(qpos0 - kp0) > win) a0 = -1e30f;
                if (abs(qpos0 - kp1) > win) a1 = -1e30f;
                if (abs(qpos1 - kp0) > win) b0 = -1e30f;
                if (abs(qpos1 - kp1) > win) b1 = -1e30f;
            }
            v0[nt * 2] = a0; v0[nt * 2 + 1] = a1;
            v1[nt * 2] = b0; v1[nt * 2 + 1] = b1;
        }
        float tm0 = -1e30f, tm1 = -1e30f;
        #pragma unroll
        for (int j = 0; j < 8; j++) { tm0 = fmaxf(tm0, v0[j]); tm1 = fmaxf(tm1, v1[j]); }
        tm0 = fmaxf(tm0, __shfl_xor_sync(0xffffffffu, tm0, 1));
        tm0 = fmaxf(tm0, __shfl_xor_sync(0xffffffffu, tm0, 2));
        tm1 = fmaxf(tm1, __shfl_xor_sync(0xffffffffu, tm1, 1));
        tm1 = fmaxf(tm1, __shfl_xor_sync(0xffffffffu, tm1, 2));
        float nm0 = fmaxf(mr0, tm0), nm1 = fmaxf(mr1, tm1);
        float al0 = __expf(mr0 - nm0), al1 = __expf(mr1 - nm1);
        mr0 = nm0; mr1 = nm1;
        float ps0 = 0.f, ps1 = 0.f;
        #pragma unroll
        for (int nt = 0; nt < 4; nt++) {
            float p00 = __expf(v0[nt * 2]     - nm0);
            float p01 = __expf(v0[nt * 2 + 1] - nm0);
            float p10 = __expf(v1[nt * 2]     - nm1);
            float p11 = __expf(v1[nt * 2 + 1] - nm1);
            ps0 += p00 + p01; ps1 += p10 + p11;
            int col = nt * 8 + 2 * tg;
            *(float2*)&Psh[(m0 + grp) * PST + col]     = make_float2(tfr(p00), tfr(p01));
            *(float2*)&Psh[(m0 + grp + 8) * PST + col] = make_float2(tfr(p10), tfr(p11));
        }
        ps0 += __shfl_xor_sync(0xffffffffu, ps0, 1);
        ps0 += __shfl_xor_sync(0xffffffffu, ps0, 2);
        ps1 += __shfl_xor_sync(0xffffffffu, ps1, 1);
        ps1 += __shfl_xor_sync(0xffffffffu, ps1, 2);
        l0 = l0 * al0 + ps0;
        l1 = l1 * al1 + ps1;
        #pragma unroll
        for (int nt = 0; nt < 8; nt++) {
            oacc[nt][0] *= al0; oacc[nt][1] *= al0;
            oacc[nt][2] *= al1; oacc[nt][3] *= al1;
        }
        __syncwarp();

        // ---- P @ V (tf32) ----
        #pragma unroll
        for (int k8 = 0; k8 < 32; k8 += 8) {
            unsigned a[4];
            a[0] = __float_as_uint(Psh[(m0 + grp) * PST + k8 + tg]);
            a[1] = __float_as_uint(Psh[(m0 + grp + 8) * PST + k8 + tg]);
            a[2] = __float_as_uint(Psh[(m0 + grp) * PST + k8 + tg + 4]);
            a[3] = __float_as_uint(Psh[(m0 + grp + 8) * PST + k8 + tg + 4]);
            #pragma unroll
            for (int nt = 0; nt < 8; nt++) {
                unsigned bb[2];
                bb[0] = f2tf(Vc[(k8 + tg) * VST + nt * 8 + grp]);
                bb[1] = f2tf(Vc[(k8 + tg + 4) * VST + nt * 8 + grp]);
                MMA_TF32(oacc[nt], a, bb);
            }
        }
    }

    float il0 = 1.0f / l0, il1 = 1.0f / l1;
    #pragma unroll
    for (int nt = 0; nt < 8; nt++) {
        int col = h * HD_ + nt * 8 + 2 * tg;
        __half2* p0 = (__half2*)(out + (size_t)(b * S_ + qpos0) * (H_ * HD_) + col);
        __half2* p1 = (__half2*)(out + (size_t)(b * S_ + qpos1) * (H_ * HD_) + col);
        *p0 = __floats2half2_rn(oacc[nt][0] * il0, oacc[nt][1] * il0);
        *p1 = __floats2half2_rn(oacc[nt][2] * il1, oacc[nt][3] * il1);
    }
}

// ---------------- SwiGLU elementwise: gateh = fp16(silu(gate) * up) ----------------
__global__ void silu_mul_kernel(const float* __restrict__ gate,
                                const float* __restrict__ up,
                                __half* __restrict__ outh, int n4) {
    int i = blockIdx.x * blockDim.x + threadIdx.x;
    if (i < n4) {
        float4 g = *(const float4*)(gate + i * 4);
        float4 u = *(const float4*)(up + i * 4);
        float r0 = g.x / (1.0f + __expf(-g.x)) * u.x;
        float r1 = g.y / (1.0f + __expf(-g.y)) * u.y;
        float r2 = g.z / (1.0f + __expf(-g.z)) * u.z;
        float r3 = g.w / (1.0f + __expf(-g.w)) * u.w;
        __half2* dst = (__half2*)(outh + (size_t)i * 4);
        dst[0] = __floats2half2_rn(r0, r1);
        dst[1] = __floats2half2_rn(r2, r3);
    }
}

// ---------------- host orchestration ----------------
extern "C" void kernel_launch(void* const* d_in, const int* in_sizes, int n_in,
                              void* d_out, int out_size) {
    const float* x      = (const float*)d_in[0];
    const float* wq     = (const float*)d_in[1];
    const float* wk     = (const float*)d_in[2];
    const float* wv     = (const float*)d_in[3];
    const float* wo     = (const float*)d_in[4];
    const float* qnw    = (const float*)d_in[5];
    const float* knw    = (const float*)d_in[6];
    const float* ln1    = (const float*)d_in[7];
    const float* ln2    = (const float*)d_in[8];
    const float* wg     = (const float*)d_in[9];
    const float* wu     = (const float*)d_in[10];
    const float* wd     = (const float*)d_in[11];
    const float* normw  = (const float*)d_in[12];
    const int*   amask  = (const int*)d_in[13];

    float *h, *v, *gate, *up;
    __half *q, *k, *nh, *atth, *gateh;
    __half *wqt, *wkt, *wvt, *wot, *wgt, *wut, *wdt;
    cudaGetSymbolAddress((void**)&h,     g_h);
    cudaGetSymbolAddress((void**)&q,     g_q);
    cudaGetSymbolAddress((void**)&k,     g_k);
    cudaGetSymbolAddress((void**)&v,     g_v);
    cudaGetSymbolAddress((void**)&gate,  g_gate);
    cudaGetSymbolAddress((void**)&up,    g_up);
    cudaGetSymbolAddress((void**)&nh,    g_nh);
    cudaGetSymbolAddress((void**)&atth,  g_atth);
    cudaGetSymbolAddress((void**)&gateh, g_gateh);
    cudaGetSymbolAddress((void**)&wqt,   g_wqt);
    cudaGetSymbolAddress((void**)&wkt,   g_wkt);
    cudaGetSymbolAddress((void**)&wvt,   g_wvt);
    cudaGetSymbolAddress((void**)&wot,   g_wot);
    cudaGetSymbolAddress((void**)&wgt,   g_wgt);
    cudaGetSymbolAddress((void**)&wut,   g_wut);
    cudaGetSymbolAddress((void**)&wdt,   g_wdt);

    cudaFuncSetAttribute(attn_mma_kernel,
        cudaFuncAttributeMaxDynamicSharedMemorySize, ATT_SMEM);

    dim3 tb(32, 8);
    convT_kernel<<<dim3(D_ / 32, (H_ * HD_) / 32, L_), tb>>>(wq, wqt, D_, H_ * HD_);
    convT_kernel<<<dim3(D_ / 32, (HK_ * HD_) / 32, L_), tb>>>(wk, wkt, D_, HK_ * HD_);
    convT_kernel<<<dim3(D_ / 32, (HK_ * HD_) / 32, L_), tb>>>(wv, wvt, D_, HK_ * HD_);
    convT_kernel<<<dim3((H_ * HD_) / 32, D_ / 32, L_), tb>>>(wo, wot, H_ * HD_, D_);
    convT_kernel<<<dim3(D_ / 32, FF_ / 32, L_), tb>>>(wg, wgt, D_, FF_);
    convT_kernel<<<dim3(D_ / 32, FF_ / 32, L_), tb>>>(wu, wut, D_, FF_);
    convT_kernel<<<dim3(FF_ / 32, D_ / 32, L_), tb>>>(wd, wdt, FF_, D_);

    cudaMemcpyAsync(h, x, (size_t)TOK_ * D_ * sizeof(float),
                    cudaMemcpyDeviceToDevice, 0);

    dim3 gQKV (16, TOK_ / 128);
    dim3 gGU  (48, TOK_ / 128);
    dim3 g1024(D_ / 128, TOK_ / 128);
    int ropeWarps = TOK_ * (H_ + HK_);

    for (int l = 0; l < L_; l++) {
        const __half* wqt_l = wqt + (size_t)l * D_ * H_ * HD_;
        const __half* wkt_l = wkt + (size_t)l * D_ * HK_ * HD_;
        const __half* wvt_l = wvt + (size_t)l * D_ * HK_ * HD_;
        const __half* wot_l = wot + (size_t)l * H_ * HD_ * D_;
        const __half* wgt_l = wgt + (size_t)l * D_ * FF_;
        const __half* wut_l = wut + (size_t)l * D_ * FF_;
        const __half* wdt_l = wdt + (size_t)l * FF_ * D_;

        rmsnorm_h_kernel<<<TOK_, 256>>>(h, ln1 + l * D_, nh);

        gemm_qkv_h<<<gQKV, 256>>>(nh, wqt_l, wkt_l, wvt_l, q, k, v);

        qknorm_rope_kernel<<<ropeWarps / 4, 128>>>(q, k, qnw + l * HD_, knw + l * HD_);

        attn_mma_kernel<<<dim3(S_ / 64, HK_, B_), 256, ATT_SMEM>>>(
            q, k, v, amask, atth, (l & 1) ? WIN_ : -1);

        gemm_h<true><<<g1024, 256>>>(atth, wot_l, h, D_, H_ * HD_);

        rmsnorm_h_kernel<<<TOK_, 256>>>(h, ln2 + l * D_, nh);

        gemm_gateup_h<<<gGU, 256>>>(nh, wgt_l, wut_l, gate, up);

        int n4 = TOK_ * FF_ / 4;
        silu_mul_kernel<<<(n4 + 255) / 256, 256>>>(gate, up, gateh, n4);

        gemm_h<true><<<g1024, 256>>>(gateh, wdt_l, h, D_, FF_);
    }

    rmsnorm_kernel<<<TOK_, 256>>>(h, normw, (float*)d_out);
}

// round 16
// speedup vs baseline: 1.8017x; 1.0486x over previous
#include <cuda_runtime.h>
#include <cuda_fp16.h>
#include <math.h>
#include <float.h>

#define D_    1024
#define H_    16
#define HK_   8
#define HD_   64
#define FF_   3072
#define S_    1024
#define B_    4
#define TOK_  4096   // B*S
#define L_    4
#define WIN_  12

// ---------------- scratch (no allocations allowed) ----------------
__device__ float  g_h   [TOK_ * D_];
__device__ __half g_q   [TOK_ * H_  * HD_];
__device__ __half g_k   [TOK_ * HK_ * HD_];
__device__ __half g_v   [TOK_ * HK_ * HD_];   // fp16 now
__device__ float  g_gate[TOK_ * FF_];
__device__ float  g_up  [TOK_ * FF_];
// fp16 activation buffers
__device__ __half g_nh   [TOK_ * D_];
__device__ __half g_atth [TOK_ * H_ * HD_];
__device__ __half g_gateh[TOK_ * FF_];
// fp16 transposed weights [N][K]
__device__ __half g_wqt[L_ * D_ * H_ * HD_];
__device__ __half g_wkt[L_ * D_ * HK_ * HD_];
__device__ __half g_wvt[L_ * D_ * HK_ * HD_];
__device__ __half g_wot[L_ * H_ * HD_ * D_];
__device__ __half g_wgt[L_ * D_ * FF_];
__device__ __half g_wut[L_ * D_ * FF_];
__device__ __half g_wdt[L_ * FF_ * D_];

// ---------------- helpers ----------------
__device__ __forceinline__ void cpa16(void* dst_smem, const void* src_gmem) {
    unsigned d = (unsigned)__cvta_generic_to_shared(dst_smem);
    asm volatile("cp.async.cg.shared.global [%0], [%1], 16;"
                 :: "r"(d), "l"(src_gmem));
}
#define CP_COMMIT()  asm volatile("cp.async.commit_group;")
#define CP_WAIT0()   asm volatile("cp.async.wait_group 0;")
#define CP_WAIT1()   asm volatile("cp.async.wait_group 1;")

#define MMA_F16(acc, a, b)                                               \
    asm volatile(                                                        \
        "mma.sync.aligned.m16n8k16.row.col.f32.f16.f16.f32 "             \
        "{%0,%1,%2,%3}, {%4,%5,%6,%7}, {%8,%9}, {%0,%1,%2,%3};"          \
        : "+f"((acc)[0]), "+f"((acc)[1]), "+f"((acc)[2]), "+f"((acc)[3]) \
        : "r"((a)[0]), "r"((a)[1]), "r"((a)[2]), "r"((a)[3]),            \
          "r"((b)[0]), "r"((b)[1]))

#define LDSM4(r, addr)                                                   \
    asm volatile("ldmatrix.sync.aligned.m8n8.x4.shared.b16 "             \
                 "{%0,%1,%2,%3}, [%4];"                                  \
                 : "=r"((r)[0]), "=r"((r)[1]), "=r"((r)[2]), "=r"((r)[3])\
                 : "r"(addr))

#define LDSM4T(r, addr)                                                  \
    asm volatile("ldmatrix.sync.aligned.m8n8.x4.trans.shared.b16 "       \
                 "{%0,%1,%2,%3}, [%4];"                                  \
                 : "=r"((r)[0]), "=r"((r)[1]), "=r"((r)[2]), "=r"((r)[3])\
                 : "r"(addr))

// ---------------- weight fp32[K][N] -> fp16 transposed [N][K] ----------------
__global__ void convT_kernel(const float* __restrict__ src, __half* __restrict__ dst,
                             int K, int N) {
    __shared__ float tile[32][33];
    size_t lofs = (size_t)blockIdx.z * K * N;
    src += lofs; dst += lofs;
    int k0 = blockIdx.x * 32, n0 = blockIdx.y * 32;
    for (int i = threadIdx.y; i < 32; i += 8)
        tile[i][threadIdx.x] = src[(size_t)(k0 + i) * N + n0 + threadIdx.x];
    __syncthreads();
    for (int i = threadIdx.y; i < 32; i += 8)
        dst[(size_t)(n0 + i) * K + k0 + threadIdx.x] = __float2half(tile[threadIdx.x][i]);
}

// ---------------- rmsnorm (fp32 out, for final) ----------------
__global__ void rmsnorm_kernel(const float* __restrict__ x,
                               const float* __restrict__ w,
                               float* __restrict__ out) {
    int row = blockIdx.x;
    const float* xr = x + (size_t)row * D_;
    int t = threadIdx.x;
    float4 v = *(const float4*)(xr + t * 4);
    float ss = v.x * v.x + v.y * v.y + v.z * v.z + v.w * v.w;
    #pragma unroll
    for (int o = 16; o; o >>= 1) ss += __shfl_xor_sync(0xffffffffu, ss, o);
    __shared__ float sh[8];
    if ((t & 31) == 0) sh[t >> 5] = ss;
    __syncthreads();
    float tot = 0.f;
    #pragma unroll
    for (int i = 0; i < 8; i++) tot += sh[i];
    float scale = rsqrtf(tot * (1.0f / D_) + 1e-6f);
    float4 wv = *(const float4*)(w + t * 4);
    float4 o4;
    o4.x = v.x * scale * wv.x;
    o4.y = v.y * scale * wv.y;
    o4.z = v.z * scale * wv.z;
    o4.w = v.w * scale * wv.w;
    *(float4*)(out + (size_t)row * D_ + t * 4) = o4;
}

// ---------------- rmsnorm (fp16 out, feeds GEMMs) ----------------
__global__ void rmsnorm_h_kernel(const float* __restrict__ x,
                                 const float* __restrict__ w,
                                 __half* __restrict__ out) {
    int row = blockIdx.x;
    const float* xr = x + (size_t)row * D_;
    int t = threadIdx.x;
    float4 v = *(const float4*)(xr + t * 4);
    float ss = v.x * v.x + v.y * v.y + v.z * v.z + v.w * v.w;
    #pragma unroll
    for (int o = 16; o; o >>= 1) ss += __shfl_xor_sync(0xffffffffu, ss, o);
    __shared__ float sh[8];
    if ((t & 31) == 0) sh[t >> 5] = ss;
    __syncthreads();
    float tot = 0.f;
    #pragma unroll
    for (int i = 0; i < 8; i++) tot += sh[i];
    float scale = rsqrtf(tot * (1.0f / D_) + 1e-6f);
    float4 wv = *(const float4*)(w + t * 4);
    __half2 h0 = __floats2half2_rn(v.x * scale * wv.x, v.y * scale * wv.y);
    __half2 h1 = __floats2half2_rn(v.z * scale * wv.z, v.w * scale * wv.w);
    __half2* dst = (__half2*)(out + (size_t)row * D_ + t * 4);
    dst[0] = h0; dst[1] = h1;
}

// ---------------- FP16 tensor-core GEMM (2-stage cp.async, BK=32, ldmatrix) ----------------
#define HAW 20                       // words per smem row
#define HSTG_B (128 * HAW * 4)       // bytes per stage per matrix
template <bool ACC, bool HOUT>
__device__ __forceinline__ void gemm_h_core(const __half* __restrict__ A,
                                            const __half* __restrict__ BT,
                                            void* __restrict__ Cv,
                                            int N, int K, int bx, int by) {
    __shared__ unsigned As[2][128 * HAW];
    __shared__ unsigned Bs[2][128 * HAW];

    int tid = threadIdx.x;
    int lane = tid & 31, wid = tid >> 5;
    int wr = wid >> 2;
    int wc = wid & 3;
    int tg = lane & 3;
    int grp = lane >> 2;

    const __half* Ag = A + (size_t)(by * 128) * K;
    const __half* Bg = BT + (size_t)(bx * 128) * K;

    int c0 = tid * 2, c1 = c0 + 1;
    int r0 = c0 >> 2, kc0 = (c0 & 3) << 3;
    int r1 = c1 >> 2, kc1 = (c1 & 3) << 3;
    int w0 = kc0 >> 1, w1 = kc1 >> 1;

    unsigned aSm = (unsigned)__cvta_generic_to_shared(&As[0][0]);
    unsigned bSm = (unsigned)__cvta_generic_to_shared(&Bs[0][0]);
    int lrow = lane & 15;
    int lkof = (lane >> 4) * 16;
    unsigned aAddr[4], bAddr[2];
    #pragma unroll
    for (int mt = 0; mt < 4; mt++)
        aAddr[mt] = aSm + (unsigned)((wr * 64 + mt * 16 + lrow) * 80 + lkof);
    #pragma unroll
    for (int np = 0; np < 2; np++)
        bAddr[np] = bSm + (unsigned)((wc * 32 + np * 16 + lrow) * 80 + lkof);

    float acc[4][4][4];
    #pragma unroll
    for (int i = 0; i < 4; i++)
        #pragma unroll
        for (int j = 0; j < 4; j++)
            #pragma unroll
            for (int c = 0; c < 4; c++) acc[i][j][c] = 0.f;

    cpa16(&As[0][r0 * HAW + w0], Ag + (size_t)r0 * K + kc0);
    cpa16(&As[0][r1 * HAW + w1], Ag + (size_t)r1 * K + kc1);
    cpa16(&Bs[0][r0 * HAW + w0], Bg + (size_t)r0 * K + kc0);
    cpa16(&Bs[0][r1 * HAW + w1], Bg + (size_t)r1 * K + kc1);
    CP_COMMIT();

    int nIter = K >> 5;
    for (int it = 0; it < nIter; it++) {
        int cur = it & 1;
        CP_WAIT0();
        __syncthreads();
        if (it + 1 < nIter) {
            int nxt = cur ^ 1;
            int k0n = (it + 1) << 5;
            cpa16(&As[nxt][r0 * HAW + w0], Ag + (size_t)r0 * K + k0n + kc0);
            cpa16(&As[nxt][r1 * HAW + w1], Ag + (size_t)r1 * K + k0n + kc1);
            cpa16(&Bs[nxt][r0 * HAW + w0], Bg + (size_t)r0 * K + k0n + kc0);
            cpa16(&Bs[nxt][r1 * HAW + w1], Bg + (size_t)r1 * K + k0n + kc1);
            CP_COMMIT();
        }

        unsigned stOfs = (unsigned)(cur * HSTG_B);
        #pragma unroll
        for (int kk8 = 0; kk8 < 16; kk8 += 8) {
            unsigned kOfs = stOfs + (unsigned)(kk8 * 4);
            unsigned afr[4][4], bq[2][4], bfr[4][2];
            #pragma unroll
            for (int mt = 0; mt < 4; mt++)
                LDSM4(afr[mt], aAddr[mt] + kOfs);
            #pragma unroll
            for (int np = 0; np < 2; np++)
                LDSM4(bq[np], bAddr[np] + kOfs);
            #pragma unroll
            for (int np = 0; np < 2; np++) {
                bfr[np * 2][0]     = bq[np][0];
                bfr[np * 2][1]     = bq[np][2];
                bfr[np * 2 + 1][0] = bq[np][1];
                bfr[np * 2 + 1][1] = bq[np][3];
            }
            #pragma unroll
            for (int mt = 0; mt < 4; mt++)
                #pragma unroll
                for (int nt = 0; nt < 4; nt++)
                    MMA_F16(acc[mt][nt], afr[mt], bfr[nt]);
        }
        __syncthreads();
    }

    #pragma unroll
    for (int mt = 0; mt < 4; mt++) {
        int row0 = by * 128 + wr * 64 + mt * 16 + grp;
        #pragma unroll
        for (int nt = 0; nt < 4; nt++) {
            int col = bx * 128 + wc * 32 + nt * 8 + tg * 2;
            if (HOUT) {
                __half* C = (__half*)Cv;
                __half2* p0 = (__half2*)(C + (size_t)row0 * N + col);
                __half2* p1 = (__half2*)(C + (size_t)(row0 + 8) * N + col);
                *p0 = __floats2half2_rn(acc[mt][nt][0], acc[mt][nt][1]);
                *p1 = __floats2half2_rn(acc[mt][nt][2], acc[mt][nt][3]);
            } else {
                float* C = (float*)Cv;
                float* p0 = C + (size_t)row0 * N + col;
                float* p1 = C + (size_t)(row0 + 8) * N + col;
                if (ACC) {
                    float2 cc0 = *(float2*)p0, cc1 = *(float2*)p1;
                    cc0.x += acc[mt][nt][0]; cc0.y += acc[mt][nt][1];
                    cc1.x += acc[mt][nt][2]; cc1.y += acc[mt][nt][3];
                    *(float2*)p0 = cc0; *(float2*)p1 = cc1;
                } else {
                    *(float2*)p0 = make_float2(acc[mt][nt][0], acc[mt][nt][1]);
                    *(float2*)p1 = make_float2(acc[mt][nt][2], acc[mt][nt][3]);
                }
            }
        }
    }
}

template <bool ACC>
__global__ void __launch_bounds__(256, 2)
gemm_h(const __half* __restrict__ A, const __half* __restrict__ BT,
       float* __restrict__ C, int N, int K) {
    gemm_h_core<ACC, false>(A, BT, C, N, K, blockIdx.x, blockIdx.y);
}

// QKV: q,k,v all written fp16
__global__ void __launch_bounds__(256, 2)
gemm_qkv_h(const __half* __restrict__ A,
           const __half* __restrict__ WqT, const __half* __restrict__ WkT,
           const __half* __restrict__ WvT,
           __half* __restrict__ q, __half* __restrict__ k, __half* __restrict__ v) {
    int bx = blockIdx.x;
    if (bx < 8)       gemm_h_core<false, true>(A, WqT, q, 1024, D_, bx,      blockIdx.y);
    else if (bx < 12) gemm_h_core<false, true>(A, WkT, k,  512, D_, bx - 8,  blockIdx.y);
    else              gemm_h_core<false, true>(A, WvT, v,  512, D_, bx - 12, blockIdx.y);
}

__global__ void __launch_bounds__(256, 2)
gemm_gateup_h(const __half* __restrict__ A,
              const __half* __restrict__ WgT, const __half* __restrict__ WuT,
              float* __restrict__ gate, float* __restrict__ up) {
    int bx = blockIdx.x;
    if (bx < 24) gemm_h_core<false, false>(A, WgT, gate, FF_, D_, bx,      blockIdx.y);
    else         gemm_h_core<false, false>(A, WuT, up,   FF_, D_, bx - 24, blockIdx.y);
}

// ---------------- fused per-head rmsnorm + RoPE for q AND k (fp16 data) ----------------
#define LOG2_THETA 19.9315685693241741f
__global__ void qknorm_rope_kernel(__half* __restrict__ q, __half* __restrict__ k,
                                   const float* __restrict__ qw,
                                   const float* __restrict__ kw) {
    int warp = (blockIdx.x * blockDim.x + threadIdx.x) >> 5;
    int lane = threadIdx.x & 31;
    __half* p; const float* w; int token;
    if (warp < TOK_ * H_) {
        p = q + (size_t)warp * HD_; w = qw; token = warp / H_;
    } else {
        int w2 = warp - TOK_ * H_;
        p = k + (size_t)w2 * HD_; w = kw; token = w2 / HK_;
    }
    int s = token & (S_ - 1);
    float a = __half2float(p[lane]), b = __half2float(p[lane + 32]);
    float ss = a * a + b * b;
    #pragma unroll
    for (int o = 16; o; o >>= 1) ss += __shfl_xor_sync(0xffffffffu, ss, o);
    float scale = rsqrtf(ss * (1.0f / HD_) + 1e-6f);
    a *= scale * w[lane];
    b *= scale * w[lane + 32];
    float inv = exp2f(-(float)lane * (LOG2_THETA / 32.0f));
    float ang = (float)s * inv;
    float c = cosf(ang), sn = sinf(ang);
    p[lane]      = __float2half(a * c - b * sn);
    p[lane + 32] = __float2half(b * c + a * sn);
}

// ---------------- flash attention: full fp16 MMAs, 2 heads/CTA, cp.async K/V ----------------
#define QSH 72    // halves per Q row
#define KSH 72    // halves per K row
#define VSH 72    // halves per V row
#define PSH 40    // halves per P row
#define ATT_SMEM ((2 * 64 * QSH + 2 * 32 * KSH + 2 * 32 * VSH + 2 * 64 * PSH) * 2)
__global__ void __launch_bounds__(256, 2)
attn_mma_kernel(const __half* __restrict__ q, const __half* __restrict__ k,
                const __half* __restrict__ v, const int* __restrict__ amask,
                __half* __restrict__ out, int win) {
    extern __shared__ __half hsm[];
    __half* Qs  = hsm;                       // 2 x 64 x QSH
    __half* KH0 = Qs + 2 * 64 * QSH;         // 32 x KSH
    __half* KH1 = KH0 + 32 * KSH;
    __half* VH0 = KH1 + 32 * KSH;            // 32 x VSH
    __half* VH1 = VH0 + 32 * VSH;
    __half* Ps  = VH1 + 32 * VSH;            // 2 x 64 x PSH

    int b = blockIdx.z, kh = blockIdx.y;
    int q0 = blockIdx.x * 64;
    int tid = threadIdx.x;
    int lane = tid & 31, wid = tid >> 5;
    int hg = wid >> 2;
    int h = kh * 2 + hg;
    int m0 = (wid & 3) * 16;
    int tg = lane & 3, grp = lane >> 2;
    int qpos0 = q0 + m0 + grp;
    int qpos1 = qpos0 + 8;

    __half* Qsh = Qs + hg * 64 * QSH;
    __half* Psh = Ps + hg * 64 * PSH;

    // cooperative Q load for BOTH heads
    for (int i = tid; i < 128 * 32; i += 256) {
        int r = i >> 5;
        int hgi = r >> 6, rr = r & 63;
        int c2 = (i & 31) * 2;
        unsigned val = *(const unsigned*)(q + (size_t)(b * S_ + q0 + rr) * (H_ * HD_)
                                            + (kh * 2 + hgi) * HD_ + c2);
        *(unsigned*)&Qs[(hgi * 64 + rr) * QSH + c2] = val;
    }
    __syncthreads();

    // hoist Q fragments: 4 k16-slices x 4 half2 regs
    unsigned qfr[4][4];
    #pragma unroll
    for (int s = 0; s < 4; s++) {
        int kb = s * 16 + 2 * tg;
        qfr[s][0] = *(unsigned*)&Qsh[(m0 + grp) * QSH + kb];
        qfr[s][1] = *(unsigned*)&Qsh[(m0 + grp + 8) * QSH + kb];
        qfr[s][2] = *(unsigned*)&Qsh[(m0 + grp) * QSH + kb + 8];
        qfr[s][3] = *(unsigned*)&Qsh[(m0 + grp + 8) * QSH + kb + 8];
    }

    // ldmatrix.trans V base address (per lane): row = lane&15, col = nblk*16 + (lane>>4)*8
    unsigned vSm0 = (unsigned)__cvta_generic_to_shared(VH0);
    unsigned vlocal = (unsigned)(((lane & 15) * VSH + (lane >> 4) * 8) * 2);

    float oacc[8][4];
    #pragma unroll
    for (int i = 0; i < 8; i++)
        #pragma unroll
        for (int j = 0; j < 4; j++) oacc[i][j] = 0.f;
    float mr0 = -1e30f, mr1 = -1e30f, l0 = 0.f, l1 = 0.f;

    int kt_lo = 0, kt_hi = (S_ / 32) - 1;
    if (win >= 0) {
        int lo = q0 - win; if (lo < 0) lo = 0;
        int hi = q0 + 63 + win; if (hi > S_ - 1) hi = S_ - 1;
        kt_lo = lo >> 5; kt_hi = hi >> 5;
    }
    const float scale = 0.125f;

    // cp.async: K and V each 32 rows x 64 halves = 256 chunks of 8 halves; 1 K + 1 V per thread
    int krow = tid >> 3, koff = (tid & 7) * 8;

    #define ISSUE_KV(kt_, buf_) {                                                     \
        __half* kb_ = (buf_) ? KH1 : KH0;                                             \
        __half* vb_ = (buf_) ? VH1 : VH0;                                             \
        size_t go = (size_t)(b * S_ + (kt_) * 32 + krow) * (HK_ * HD_) + kh * HD_ + koff; \
        cpa16(&kb_[krow * KSH + koff], k + go);                                       \
        cpa16(&vb_[krow * VSH + koff], v + go);                                       \
        CP_COMMIT();                                                                  \
    }

    ISSUE_KV(kt_lo, 0);

    for (int kt = kt_lo; kt <= kt_hi; kt++) {
        int cur = (kt - kt_lo) & 1;
        __syncthreads();
        if (kt + 1 <= kt_hi) {
            ISSUE_KV(kt + 1, cur ^ 1);
            CP_WAIT1();
        } else {
            CP_WAIT0();
        }
        __syncthreads();

        const __half* Kc = (cur ? KH1 : KH0);
        unsigned vBase = vSm0 + (unsigned)(cur * 32 * VSH * 2) + vlocal;

        // ---- QK^T (fp16 MMA, k16) ----
        float sc[4][4];
        #pragma unroll
        for (int i = 0; i < 4; i++)
            #pragma unroll
            for (int j = 0; j < 4; j++) sc[i][j] = 0.f;
        #pragma unroll
        for (int s = 0; s < 4; s++) {
            int kb = s * 16 + 2 * tg;
            #pragma unroll
            for (int nt = 0; nt < 4; nt++) {
                unsigned bb[2];
                bb[0] = *(const unsigned*)&Kc[(nt * 8 + grp) * KSH + kb];
                bb[1] = *(const unsigned*)&Kc[(nt * 8 + grp) * KSH + kb + 8];
                MMA_F16(sc[nt], qfr[s], bb);
            }
        }

        // ---- mask + online softmax ----
        const int* am = amask + b * S_ + kt * 32;
        float v0[8], v1[8];
        #pragma unroll
        for (int nt = 0; nt < 4; nt++) {
            int kc0 = nt * 8 + 2 * tg, kc1 = kc0 + 1;
            int kp0 = kt * 32 + kc0, kp1 = kt * 32 + kc1;
            float mk0 = (am[kc0] != 0) ? 0.f : -1e30f;
            float mk1 = (am[kc1] != 0) ? 0.f : -1e30f;
            float a0 = sc[nt][0] * scale + mk0;
            float a1 = sc[nt][1] * scale + mk1;
            float b0 = sc[nt][2] * scale + mk0;
            float b1 = sc[nt][3] * scale + mk1;
            if (win >= 0) {
                if (abs(qpos0 - kp0) > win) a0 = -1e30f;
                if (abs(qpos0 - kp1) > win) a1 = -1e30f;
                if (abs(qpos1 - kp0) > win) b0 = -1e30f;
                if (abs(qpos1 - kp1) > win) b1 = -1e30f;
            }
            v0[nt * 2] = a0; v0[nt * 2 + 1] = a1;
            v1[nt * 2] = b0; v1[nt * 2 + 1] = b1;
        }
        float tm0 = -1e30f, tm1 = -1e30f;
        #pragma unroll
        for (int j = 0; j < 8; j++) { tm0 = fmaxf(tm0, v0[j]); tm1 = fmaxf(tm1, v1[j]); }
        tm0 = fmaxf(tm0, __shfl_xor_sync(0xffffffffu, tm0, 1));
        tm0 = fmaxf(tm0, __shfl_xor_sync(0xffffffffu, tm0, 2));
        tm1 = fmaxf(tm1, __shfl_xor_sync(0xffffffffu, tm1, 1));
        tm1 = fmaxf(tm1, __shfl_xor_sync(0xffffffffu, tm1, 2));
        float nm0 = fmaxf(mr0, tm0), nm1 = fmaxf(mr1, tm1);
        float al0 = __expf(mr0 - nm0), al1 = __expf(mr1 - nm1);
        mr0 = nm0; mr1 = nm1;
        float ps0 = 0.f, ps1 = 0.f;
        #pragma unroll
        for (int nt = 0; nt < 4; nt++) {
            float p00 = __expf(v0[nt * 2]     - nm0);
            float p01 = __expf(v0[nt * 2 + 1] - nm0);
            float p10 = __expf(v1[nt * 2]     - nm1);
            float p11 = __expf(v1[nt * 2 + 1] - nm1);
            ps0 += p00 + p01; ps1 += p10 + p11;
            int col = nt * 8 + 2 * tg;
            *(__half2*)&Psh[(m0 + grp) * PSH + col]     = __floats2half2_rn(p00, p01);
            *(__half2*)&Psh[(m0 + grp + 8) * PSH + col] = __floats2half2_rn(p10, p11);
        }
        ps0 += __shfl_xor_sync(0xffffffffu, ps0, 1);
        ps0 += __shfl_xor_sync(0xffffffffu, ps0, 2);
        ps1 += __shfl_xor_sync(0xffffffffu, ps1, 1);
        ps1 += __shfl_xor_sync(0xffffffffu, ps1, 2);
        l0 = l0 * al0 + ps0;
        l1 = l1 * al1 + ps1;
        #pragma unroll
        for (int nt = 0; nt < 8; nt++) {
            oacc[nt][0] *= al0; oacc[nt][1] *= al0;
            oacc[nt][2] *= al1; oacc[nt][3] *= al1;
        }
        __syncwarp();

        // ---- P @ V (fp16 MMA, ldmatrix.trans for V) ----
        #pragma unroll
        for (int s = 0; s < 2; s++) {               // k16 slices over 32 keys
            unsigned a[4];
            int kb = s * 16 + 2 * tg;
            a[0] = *(unsigned*)&Psh[(m0 + grp) * PSH + kb];
            a[1] = *(unsigned*)&Psh[(m0 + grp + 8) * PSH + kb];
            a[2] = *(unsigned*)&Psh[(m0 + grp) * PSH + kb + 8];
            a[3] = *(unsigned*)&Psh[(m0 + grp + 8) * PSH + kb + 8];
            unsigned sOfs = (unsigned)(s * 16 * VSH * 2);
            #pragma unroll
            for (int nb = 0; nb < 4; nb++) {        // n16 blocks over 64 dims
                unsigned bq[4];
                LDSM4T(bq, vBase + sOfs + (unsigned)(nb * 32));
                unsigned bb0[2] = { bq[0], bq[1] };
                unsigned bb1[2] = { bq[2], bq[3] };
                MMA_F16(oacc[2 * nb],     a, bb0);
                MMA_F16(oacc[2 * nb + 1], a, bb1);
            }
        }
    }

    float il0 = 1.0f / l0, il1 = 1.0f / l1;
    #pragma unroll
    for (int nt = 0; nt < 8; nt++) {
        int col = h * HD_ + nt * 8 + 2 * tg;
        __half2* p0 = (__half2*)(out + (size_t)(b * S_ + qpos0) * (H_ * HD_) + col);
        __half2* p1 = (__half2*)(out + (size_t)(b * S_ + qpos1) * (H_ * HD_) + col);
        *p0 = __floats2half2_rn(oacc[nt][0] * il0, oacc[nt][1] * il0);
        *p1 = __floats2half2_rn(oacc[nt][2] * il1, oacc[nt][3] * il1);
    }
}

// ---------------- SwiGLU elementwise: gateh = fp16(silu(gate) * up) ----------------
__global__ void silu_mul_kernel(const float* __restrict__ gate,
                                const float* __restrict__ up,
                                __half* __restrict__ outh, int n4) {
    int i = blockIdx.x * blockDim.x + threadIdx.x;
    if (i < n4) {
        float4 g = *(const float4*)(gate + i * 4);
        float4 u = *(const float4*)(up + i * 4);
        float r0 = g.x / (1.0f + __expf(-g.x)) * u.x;
        float r1 = g.y / (1.0f + __expf(-g.y)) * u.y;
        float r2 = g.z / (1.0f + __expf(-g.z)) * u.z;
        float r3 = g.w / (1.0f + __expf(-g.w)) * u.w;
        __half2* dst = (__half2*)(outh + (size_t)i * 4);
        dst[0] = __floats2half2_rn(r0, r1);
        dst[1] = __floats2half2_rn(r2, r3);
    }
}

// ---------------- host orchestration ----------------
extern "C" void kernel_launch(void* const* d_in, const int* in_sizes, int n_in,
                              void* d_out, int out_size) {
    const float* x      = (const float*)d_in[0];
    const float* wq     = (const float*)d_in[1];
    const float* wk     = (const float*)d_in[2];
    const float* wv     = (const float*)d_in[3];
    const float* wo     = (const float*)d_in[4];
    const float* qnw    = (const float*)d_in[5];
    const float* knw    = (const float*)d_in[6];
    const float* ln1    = (const float*)d_in[7];
    const float* ln2    = (const float*)d_in[8];
    const float* wg     = (const float*)d_in[9];
    const float* wu     = (const float*)d_in[10];
    const float* wd     = (const float*)d_in[11];
    const float* normw  = (const float*)d_in[12];
    const int*   amask  = (const int*)d_in[13];

    float *h, *gate, *up;
    __half *q, *k, *v, *nh, *atth, *gateh;
    __half *wqt, *wkt, *wvt, *wot, *wgt, *wut, *wdt;
    cudaGetSymbolAddress((void**)&h,     g_h);
    cudaGetSymbolAddress((void**)&q,     g_q);
    cudaGetSymbolAddress((void**)&k,     g_k);
    cudaGetSymbolAddress((void**)&v,     g_v);
    cudaGetSymbolAddress((void**)&gate,  g_gate);
    cudaGetSymbolAddress((void**)&up,    g_up);
    cudaGetSymbolAddress((void**)&nh,    g_nh);
    cudaGetSymbolAddress((void**)&atth,  g_atth);
    cudaGetSymbolAddress((void**)&gateh, g_gateh);
    cudaGetSymbolAddress((void**)&wqt,   g_wqt);
    cudaGetSymbolAddress((void**)&wkt,   g_wkt);
    cudaGetSymbolAddress((void**)&wvt,   g_wvt);
    cudaGetSymbolAddress((void**)&wot,   g_wot);
    cudaGetSymbolAddress((void**)&wgt,   g_wgt);
    cudaGetSymbolAddress((void**)&wut,   g_wut);
    cudaGetSymbolAddress((void**)&wdt,   g_wdt);

    cudaFuncSetAttribute(attn_mma_kernel,
        cudaFuncAttributeMaxDynamicSharedMemorySize, ATT_SMEM);

    dim3 tb(32, 8);
    convT_kernel<<<dim3(D_ / 32, (H_ * HD_) / 32, L_), tb>>>(wq, wqt, D_, H_ * HD_);
    convT_kernel<<<dim3(D_ / 32, (HK_ * HD_) / 32, L_), tb>>>(wk, wkt, D_, HK_ * HD_);
    convT_kernel<<<dim3(D_ / 32, (HK_ * HD_) / 32, L_), tb>>>(wv, wvt, D_, HK_ * HD_);
    convT_kernel<<<dim3((H_ * HD_) / 32, D_ / 32, L_), tb>>>(wo, wot, H_ * HD_, D_);
    convT_kernel<<<dim3(D_ / 32, FF_ / 32, L_), tb>>>(wg, wgt, D_, FF_);
    convT_kernel<<<dim3(D_ / 32, FF_ / 32, L_), tb>>>(wu, wut, D_, FF_);
    convT_kernel<<<dim3(FF_ / 32, D_ / 32, L_), tb>>>(wd, wdt, FF_, D_);

    cudaMemcpyAsync(h, x, (size_t)TOK_ * D_ * sizeof(float),
                    cudaMemcpyDeviceToDevice, 0);

    dim3 gQKV (16, TOK_ / 128);
    dim3 gGU  (48, TOK_ / 128);
    dim3 g1024(D_ / 128, TOK_ / 128);
    int ropeWarps = TOK_ * (H_ + HK_);

    for (int l = 0; l < L_; l++) {
        const __half* wqt_l = wqt + (size_t)l * D_ * H_ * HD_;
        const __half* wkt_l = wkt + (size_t)l * D_ * HK_ * HD_;
        const __half* wvt_l = wvt + (size_t)l * D_ * HK_ * HD_;
        const __half* wot_l = wot + (size_t)l * H_ * HD_ * D_;
        const __half* wgt_l = wgt + (size_t)l * D_ * FF_;
        const __half* wut_l = wut + (size_t)l * D_ * FF_;
        const __half* wdt_l = wdt + (size_t)l * FF_ * D_;

        rmsnorm_h_kernel<<<TOK_, 256>>>(h, ln1 + l * D_, nh);

        gemm_qkv_h<<<gQKV, 256>>>(nh, wqt_l, wkt_l, wvt_l, q, k, v);

        qknorm_rope_kernel<<<ropeWarps / 4, 128>>>(q, k, qnw + l * HD_, knw + l * HD_);

        attn_mma_kernel<<<dim3(S_ / 64, HK_, B_), 256, ATT_SMEM>>>(
            q, k, v, amask, atth, (l & 1) ? WIN_ : -1);

        gemm_h<true><<<g1024, 256>>>(atth, wot_l, h, D_, H_ * HD_);

        rmsnorm_h_kernel<<<TOK_, 256>>>(h, ln2 + l * D_, nh);

        gemm_gateup_h<<<gGU, 256>>>(nh, wgt_l, wut_l, gate, up);

        int n4 = TOK_ * FF_ / 4;
        silu_mul_kernel<<<(n4 + 255) / 256, 256>>>(gate, up, gateh, n4);

        gemm_h<true><<<g1024, 256>>>(gateh, wdt_l, h, D_, FF_);
    }

    rmsnorm_kernel<<<TOK_, 256>>>(h, normw, (float*)d_out);
}

// round 17
// speedup vs baseline: 1.8918x; 1.0500x over previous
#include <cuda_runtime.h>
#include <cuda_fp16.h>
#include <math.h>
#include <float.h>

#define D_    1024
#define H_    16
#define HK_   8
#define HD_   64
#define FF_   3072
#define S_    1024
#define B_    4
#define TOK_  4096   // B*S
#define L_    4
#define WIN_  12

// ---------------- scratch (no allocations allowed) ----------------
__device__ float  g_h   [TOK_ * D_];
__device__ __half g_q   [TOK_ * H_  * HD_];
__device__ __half g_k   [TOK_ * HK_ * HD_];
__device__ __half g_v   [TOK_ * HK_ * HD_];
__device__ __half g_gate[TOK_ * FF_];         // fp16 now
__device__ __half g_up  [TOK_ * FF_];         // fp16 now
// fp16 activation buffers
__device__ __half g_nh   [TOK_ * D_];
__device__ __half g_atth [TOK_ * H_ * HD_];
__device__ __half g_gateh[TOK_ * FF_];
// fp16 transposed weights [N][K]
__device__ __half g_wqt[L_ * D_ * H_ * HD_];
__device__ __half g_wkt[L_ * D_ * HK_ * HD_];
__device__ __half g_wvt[L_ * D_ * HK_ * HD_];
__device__ __half g_wot[L_ * H_ * HD_ * D_];
__device__ __half g_wgt[L_ * D_ * FF_];
__device__ __half g_wut[L_ * D_ * FF_];
__device__ __half g_wdt[L_ * FF_ * D_];

// ---------------- helpers ----------------
__device__ __forceinline__ void cpa16(void* dst_smem, const void* src_gmem) {
    unsigned d = (unsigned)__cvta_generic_to_shared(dst_smem);
    asm volatile("cp.async.cg.shared.global [%0], [%1], 16;"
                 :: "r"(d), "l"(src_gmem));
}
#define CP_COMMIT()  asm volatile("cp.async.commit_group;")
#define CP_WAIT0()   asm volatile("cp.async.wait_group 0;")
#define CP_WAIT1()   asm volatile("cp.async.wait_group 1;")

#define MMA_F16(acc, a, b)                                               \
    asm volatile(                                                        \
        "mma.sync.aligned.m16n8k16.row.col.f32.f16.f16.f32 "             \
        "{%0,%1,%2,%3}, {%4,%5,%6,%7}, {%8,%9}, {%0,%1,%2,%3};"          \
        : "+f"((acc)[0]), "+f"((acc)[1]), "+f"((acc)[2]), "+f"((acc)[3]) \
        : "r"((a)[0]), "r"((a)[1]), "r"((a)[2]), "r"((a)[3]),            \
          "r"((b)[0]), "r"((b)[1]))

#define LDSM4(r, addr)                                                   \
    asm volatile("ldmatrix.sync.aligned.m8n8.x4.shared.b16 "             \
                 "{%0,%1,%2,%3}, [%4];"                                  \
                 : "=r"((r)[0]), "=r"((r)[1]), "=r"((r)[2]), "=r"((r)[3])\
                 : "r"(addr))

#define LDSM4T(r, addr)                                                  \
    asm volatile("ldmatrix.sync.aligned.m8n8.x4.trans.shared.b16 "       \
                 "{%0,%1,%2,%3}, [%4];"                                  \
                 : "=r"((r)[0]), "=r"((r)[1]), "=r"((r)[2]), "=r"((r)[3])\
                 : "r"(addr))

// ---------------- weight fp32[K][N] -> fp16 transposed [N][K] (coalesced both ways) ----
// 64k x 32n tile. Read: 128B lines along N. Write: half2/thread => 128B lines along K.
__global__ void convT_kernel(const float* __restrict__ src, __half* __restrict__ dst,
                             int K, int N) {
    __shared__ __half tile[32][66];     // [n][k], 66-half row stride (33 words, conflict-free)
    size_t lofs = (size_t)blockIdx.z * K * N;
    src += lofs; dst += lofs;
    int k0 = blockIdx.x * 64, n0 = blockIdx.y * 32;
    int tx = threadIdx.x;               // 32
    int ty = threadIdx.y;               // 8
    #pragma unroll
    for (int ki = 0; ki < 8; ki++) {
        int kk = ty + ki * 8;           // 0..63
        tile[tx][kk] = __float2half(src[(size_t)(k0 + kk) * N + n0 + tx]);
    }
    __syncthreads();
    #pragma unroll
    for (int ni = 0; ni < 4; ni++) {
        int nn = ty * 4 + ni;           // 0..31
        __half2 hv = *(__half2*)&tile[nn][tx * 2];
        *(__half2*)(dst + (size_t)(n0 + nn) * K + k0 + tx * 2) = hv;
    }
}

// ---------------- rmsnorm (fp32 out, for final) ----------------
__global__ void rmsnorm_kernel(const float* __restrict__ x,
                               const float* __restrict__ w,
                               float* __restrict__ out) {
    int row = blockIdx.x;
    const float* xr = x + (size_t)row * D_;
    int t = threadIdx.x;
    float4 v = *(const float4*)(xr + t * 4);
    float ss = v.x * v.x + v.y * v.y + v.z * v.z + v.w * v.w;
    #pragma unroll
    for (int o = 16; o; o >>= 1) ss += __shfl_xor_sync(0xffffffffu, ss, o);
    __shared__ float sh[8];
    if ((t & 31) == 0) sh[t >> 5] = ss;
    __syncthreads();
    float tot = 0.f;
    #pragma unroll
    for (int i = 0; i < 8; i++) tot += sh[i];
    float scale = rsqrtf(tot * (1.0f / D_) + 1e-6f);
    float4 wv = *(const float4*)(w + t * 4);
    float4 o4;
    o4.x = v.x * scale * wv.x;
    o4.y = v.y * scale * wv.y;
    o4.z = v.z * scale * wv.z;
    o4.w = v.w * scale * wv.w;
    *(float4*)(out + (size_t)row * D_ + t * 4) = o4;
}

// ---------------- rmsnorm (fp16 out, feeds GEMMs) ----------------
__global__ void rmsnorm_h_kernel(const float* __restrict__ x,
                                 const float* __restrict__ w,
                                 __half* __restrict__ out) {
    int row = blockIdx.x;
    const float* xr = x + (size_t)row * D_;
    int t = threadIdx.x;
    float4 v = *(const float4*)(xr + t * 4);
    float ss = v.x * v.x + v.y * v.y + v.z * v.z + v.w * v.w;
    #pragma unroll
    for (int o = 16; o; o >>= 1) ss += __shfl_xor_sync(0xffffffffu, ss, o);
    __shared__ float sh[8];
    if ((t & 31) == 0) sh[t >> 5] = ss;
    __syncthreads();
    float tot = 0.f;
    #pragma unroll
    for (int i = 0; i < 8; i++) tot += sh[i];
    float scale = rsqrtf(tot * (1.0f / D_) + 1e-6f);
    float4 wv = *(const float4*)(w + t * 4);
    __half2 h0 = __floats2half2_rn(v.x * scale * wv.x, v.y * scale * wv.y);
    __half2 h1 = __floats2half2_rn(v.z * scale * wv.z, v.w * scale * wv.w);
    __half2* dst = (__half2*)(out + (size_t)row * D_ + t * 4);
    dst[0] = h0; dst[1] = h1;
}

// ---------------- FP16 tensor-core GEMM (2-stage cp.async, BK=32, ldmatrix) ----------------
#define HAW 20                       // words per smem row
#define HSTG_B (128 * HAW * 4)       // bytes per stage per matrix
template <bool ACC, bool HOUT>
__device__ __forceinline__ void gemm_h_core(const __half* __restrict__ A,
                                            const __half* __restrict__ BT,
                                            void* __restrict__ Cv,
                                            int N, int K, int bx, int by) {
    __shared__ unsigned As[2][128 * HAW];
    __shared__ unsigned Bs[2][128 * HAW];

    int tid = threadIdx.x;
    int lane = tid & 31, wid = tid >> 5;
    int wr = wid >> 2;
    int wc = wid & 3;
    int tg = lane & 3;
    int grp = lane >> 2;

    const __half* Ag = A + (size_t)(by * 128) * K;
    const __half* Bg = BT + (size_t)(bx * 128) * K;

    int c0 = tid * 2, c1 = c0 + 1;
    int r0 = c0 >> 2, kc0 = (c0 & 3) << 3;
    int r1 = c1 >> 2, kc1 = (c1 & 3) << 3;
    int w0 = kc0 >> 1, w1 = kc1 >> 1;

    unsigned aSm = (unsigned)__cvta_generic_to_shared(&As[0][0]);
    unsigned bSm = (unsigned)__cvta_generic_to_shared(&Bs[0][0]);
    int lrow = lane & 15;
    int lkof = (lane >> 4) * 16;
    unsigned aAddr[4], bAddr[2];
    #pragma unroll
    for (int mt = 0; mt < 4; mt++)
        aAddr[mt] = aSm + (unsigned)((wr * 64 + mt * 16 + lrow) * 80 + lkof);
    #pragma unroll
    for (int np = 0; np < 2; np++)
        bAddr[np] = bSm + (unsigned)((wc * 32 + np * 16 + lrow) * 80 + lkof);

    float acc[4][4][4];
    #pragma unroll
    for (int i = 0; i < 4; i++)
        #pragma unroll
        for (int j = 0; j < 4; j++)
            #pragma unroll
            for (int c = 0; c < 4; c++) acc[i][j][c] = 0.f;

    cpa16(&As[0][r0 * HAW + w0], Ag + (size_t)r0 * K + kc0);
    cpa16(&As[0][r1 * HAW + w1], Ag + (size_t)r1 * K + kc1);
    cpa16(&Bs[0][r0 * HAW + w0], Bg + (size_t)r0 * K + kc0);
    cpa16(&Bs[0][r1 * HAW + w1], Bg + (size_t)r1 * K + kc1);
    CP_COMMIT();

    int nIter = K >> 5;
    for (int it = 0; it < nIter; it++) {
        int cur = it & 1;
        CP_WAIT0();
        __syncthreads();
        if (it + 1 < nIter) {
            int nxt = cur ^ 1;
            int k0n = (it + 1) << 5;
            cpa16(&As[nxt][r0 * HAW + w0], Ag + (size_t)r0 * K + k0n + kc0);
            cpa16(&As[nxt][r1 * HAW + w1], Ag + (size_t)r1 * K + k0n + kc1);
            cpa16(&Bs[nxt][r0 * HAW + w0], Bg + (size_t)r0 * K + k0n + kc0);
            cpa16(&Bs[nxt][r1 * HAW + w1], Bg + (size_t)r1 * K + k0n + kc1);
            CP_COMMIT();
        }

        unsigned stOfs = (unsigned)(cur * HSTG_B);
        #pragma unroll
        for (int kk8 = 0; kk8 < 16; kk8 += 8) {
            unsigned kOfs = stOfs + (unsigned)(kk8 * 4);
            unsigned afr[4][4], bq[2][4], bfr[4][2];
            #pragma unroll
            for (int mt = 0; mt < 4; mt++)
                LDSM4(afr[mt], aAddr[mt] + kOfs);
            #pragma unroll
            for (int np = 0; np < 2; np++)
                LDSM4(bq[np], bAddr[np] + kOfs);
            #pragma unroll
            for (int np = 0; np < 2; np++) {
                bfr[np * 2][0]     = bq[np][0];
                bfr[np * 2][1]     = bq[np][2];
                bfr[np * 2 + 1][0] = bq[np][1];
                bfr[np * 2 + 1][1] = bq[np][3];
            }
            #pragma unroll
            for (int mt = 0; mt < 4; mt++)
                #pragma unroll
                for (int nt = 0; nt < 4; nt++)
                    MMA_F16(acc[mt][nt], afr[mt], bfr[nt]);
        }
        __syncthreads();
    }

    #pragma unroll
    for (int mt = 0; mt < 4; mt++) {
        int row0 = by * 128 + wr * 64 + mt * 16 + grp;
        #pragma unroll
        for (int nt = 0; nt < 4; nt++) {
            int col = bx * 128 + wc * 32 + nt * 8 + tg * 2;
            if (HOUT) {
                __half* C = (__half*)Cv;
                __half2* p0 = (__half2*)(C + (size_t)row0 * N + col);
                __half2* p1 = (__half2*)(C + (size_t)(row0 + 8) * N + col);
                *p0 = __floats2half2_rn(acc[mt][nt][0], acc[mt][nt][1]);
                *p1 = __floats2half2_rn(acc[mt][nt][2], acc[mt][nt][3]);
            } else {
                float* C = (float*)Cv;
                float* p0 = C + (size_t)row0 * N + col;
                float* p1 = C + (size_t)(row0 + 8) * N + col;
                if (ACC) {
                    float2 cc0 = *(float2*)p0, cc1 = *(float2*)p1;
                    cc0.x += acc[mt][nt][0]; cc0.y += acc[mt][nt][1];
                    cc1.x += acc[mt][nt][2]; cc1.y += acc[mt][nt][3];
                    *(float2*)p0 = cc0; *(float2*)p1 = cc1;
                } else {
                    *(float2*)p0 = make_float2(acc[mt][nt][0], acc[mt][nt][1]);
                    *(float2*)p1 = make_float2(acc[mt][nt][2], acc[mt][nt][3]);
                }
            }
        }
    }
}

template <bool ACC>
__global__ void __launch_bounds__(256, 2)
gemm_h(const __half* __restrict__ A, const __half* __restrict__ BT,
       float* __restrict__ C, int N, int K) {
    gemm_h_core<ACC, false>(A, BT, C, N, K, blockIdx.x, blockIdx.y);
}

// QKV: q,k,v all written fp16
__global__ void __launch_bounds__(256, 2)
gemm_qkv_h(const __half* __restrict__ A,
           const __half* __restrict__ WqT, const __half* __restrict__ WkT,
           const __half* __restrict__ WvT,
           __half* __restrict__ q, __half* __restrict__ k, __half* __restrict__ v) {
    int bx = blockIdx.x;
    if (bx < 8)       gemm_h_core<false, true>(A, WqT, q, 1024, D_, bx,      blockIdx.y);
    else if (bx < 12) gemm_h_core<false, true>(A, WkT, k,  512, D_, bx - 8,  blockIdx.y);
    else              gemm_h_core<false, true>(A, WvT, v,  512, D_, bx - 12, blockIdx.y);
}

// gate/up written fp16 (silu consumes fp16)
__global__ void __launch_bounds__(256, 2)
gemm_gateup_h(const __half* __restrict__ A,
              const __half* __restrict__ WgT, const __half* __restrict__ WuT,
              __half* __restrict__ gate, __half* __restrict__ up) {
    int bx = blockIdx.x;
    if (bx < 24) gemm_h_core<false, true>(A, WgT, gate, FF_, D_, bx,      blockIdx.y);
    else         gemm_h_core<false, true>(A, WuT, up,   FF_, D_, bx - 24, blockIdx.y);
}

// ---------------- fused per-head rmsnorm + RoPE for q AND k (fp16 data) ----------------
#define LOG2_THETA 19.9315685693241741f
__global__ void qknorm_rope_kernel(__half* __restrict__ q, __half* __restrict__ k,
                                   const float* __restrict__ qw,
                                   const float* __restrict__ kw) {
    int warp = (blockIdx.x * blockDim.x + threadIdx.x) >> 5;
    int lane = threadIdx.x & 31;
    __half* p; const float* w; int token;
    if (warp < TOK_ * H_) {
        p = q + (size_t)warp * HD_; w = qw; token = warp / H_;
    } else {
        int w2 = warp - TOK_ * H_;
        p = k + (size_t)w2 * HD_; w = kw; token = w2 / HK_;
    }
    int s = token & (S_ - 1);
    float a = __half2float(p[lane]), b = __half2float(p[lane + 32]);
    float ss = a * a + b * b;
    #pragma unroll
    for (int o = 16; o; o >>= 1) ss += __shfl_xor_sync(0xffffffffu, ss, o);
    float scale = rsqrtf(ss * (1.0f / HD_) + 1e-6f);
    a *= scale * w[lane];
    b *= scale * w[lane + 32];
    float inv = exp2f(-(float)lane * (LOG2_THETA / 32.0f));
    float ang = (float)s * inv;
    float c = cosf(ang), sn = sinf(ang);
    p[lane]      = __float2half(a * c - b * sn);
    p[lane + 32] = __float2half(b * c + a * sn);
}

// ---------------- flash attention: full fp16 MMAs, 2 heads/CTA, cp.async K/V ----------------
#define QSH 72    // halves per Q row
#define KSH 72    // halves per K row
#define VSH 72    // halves per V row
#define PSH 40    // halves per P row
#define ATT_SMEM ((2 * 64 * QSH + 2 * 32 * KSH + 2 * 32 * VSH + 2 * 64 * PSH) * 2)
__global__ void __launch_bounds__(256, 2)
attn_mma_kernel(const __half* __restrict__ q, const __half* __restrict__ k,
                const __half* __restrict__ v, const int* __restrict__ amask,
                __half* __restrict__ out, int win) {
    extern __shared__ __half hsm[];
    __half* Qs  = hsm;                       // 2 x 64 x QSH
    __half* KH0 = Qs + 2 * 64 * QSH;         // 32 x KSH
    __half* KH1 = KH0 + 32 * KSH;
    __half* VH0 = KH1 + 32 * KSH;            // 32 x VSH
    __half* VH1 = VH0 + 32 * VSH;
    __half* Ps  = VH1 + 32 * VSH;            // 2 x 64 x PSH

    int b = blockIdx.z, kh = blockIdx.y;
    int q0 = blockIdx.x * 64;
    int tid = threadIdx.x;
    int lane = tid & 31, wid = tid >> 5;
    int hg = wid >> 2;
    int h = kh * 2 + hg;
    int m0 = (wid & 3) * 16;
    int tg = lane & 3, grp = lane >> 2;
    int qpos0 = q0 + m0 + grp;
    int qpos1 = qpos0 + 8;

    __half* Qsh = Qs + hg * 64 * QSH;
    __half* Psh = Ps + hg * 64 * PSH;

    // cooperative Q load for BOTH heads
    for (int i = tid; i < 128 * 32; i += 256) {
        int r = i >> 5;
        int hgi = r >> 6, rr = r & 63;
        int c2 = (i & 31) * 2;
        unsigned val = *(const unsigned*)(q + (size_t)(b * S_ + q0 + rr) * (H_ * HD_)
                                            + (kh * 2 + hgi) * HD_ + c2);
        *(unsigned*)&Qs[(hgi * 64 + rr) * QSH + c2] = val;
    }
    __syncthreads();

    // hoist Q fragments: 4 k16-slices x 4 half2 regs
    unsigned qfr[4][4];
    #pragma unroll
    for (int s = 0; s < 4; s++) {
        int kb = s * 16 + 2 * tg;
        qfr[s][0] = *(unsigned*)&Qsh[(m0 + grp) * QSH + kb];
        qfr[s][1] = *(unsigned*)&Qsh[(m0 + grp + 8) * QSH + kb];
        qfr[s][2] = *(unsigned*)&Qsh[(m0 + grp) * QSH + kb + 8];
        qfr[s][3] = *(unsigned*)&Qsh[(m0 + grp + 8) * QSH + kb + 8];
    }

    unsigned vSm0 = (unsigned)__cvta_generic_to_shared(VH0);
    unsigned vlocal = (unsigned)(((lane & 15) * VSH + (lane >> 4) * 8) * 2);

    float oacc[8][4];
    #pragma unroll
    for (int i = 0; i < 8; i++)
        #pragma unroll
        for (int j = 0; j < 4; j++) oacc[i][j] = 0.f;
    float mr0 = -1e30f, mr1 = -1e30f, l0 = 0.f, l1 = 0.f;

    int kt_lo = 0, kt_hi = (S_ / 32) - 1;
    if (win >= 0) {
        int lo = q0 - win; if (lo < 0) lo = 0;
        int hi = q0 + 63 + win; if (hi > S_ - 1) hi = S_ - 1;
        kt_lo = lo >> 5; kt_hi = hi >> 5;
    }
    const float scale = 0.125f;

    int krow = tid >> 3, koff = (tid & 7) * 8;

    #define ISSUE_KV(kt_, buf_) {                                                     \
        __half* kb_ = (buf_) ? KH1 : KH0;                                             \
        __half* vb_ = (buf_) ? VH1 : VH0;                                             \
        size_t go = (size_t)(b * S_ + (kt_) * 32 + krow) * (HK_ * HD_) + kh * HD_ + koff; \
        cpa16(&kb_[krow * KSH + koff], k + go);                                       \
        cpa16(&vb_[krow * VSH + koff], v + go);                                       \
        CP_COMMIT();                                                                  \
    }

    ISSUE_KV(kt_lo, 0);

    for (int kt = kt_lo; kt <= kt_hi; kt++) {
        int cur = (kt - kt_lo) & 1;
        __syncthreads();
        if (kt + 1 <= kt_hi) {
            ISSUE_KV(kt + 1, cur ^ 1);
            CP_WAIT1();
        } else {
            CP_WAIT0();
        }
        __syncthreads();

        const __half* Kc = (cur ? KH1 : KH0);
        unsigned vBase = vSm0 + (unsigned)(cur * 32 * VSH * 2) + vlocal;

        // ---- QK^T (fp16 MMA, k16) ----
        float sc[4][4];
        #pragma unroll
        for (int i = 0; i < 4; i++)
            #pragma unroll
            for (int j = 0; j < 4; j++) sc[i][j] = 0.f;
        #pragma unroll
        for (int s = 0; s < 4; s++) {
            int kb = s * 16 + 2 * tg;
            #pragma unroll
            for (int nt = 0; nt < 4; nt++) {
                unsigned bb[2];
                bb[0] = *(const unsigned*)&Kc[(nt * 8 + grp) * KSH + kb];
                bb[1] = *(const unsigned*)&Kc[(nt * 8 + grp) * KSH + kb + 8];
                MMA_F16(sc[nt], qfr[s], bb);
            }
        }

        // ---- mask + online softmax ----
        const int* am = amask + b * S_ + kt * 32;
        float v0[8], v1[8];
        #pragma unroll
        for (int nt = 0; nt < 4; nt++) {
            int kc0 = nt * 8 + 2 * tg, kc1 = kc0 + 1;
            int kp0 = kt * 32 + kc0, kp1 = kt * 32 + kc1;
            float mk0 = (am[kc0] != 0) ? 0.f : -1e30f;
            float mk1 = (am[kc1] != 0) ? 0.f : -1e30f;
            float a0 = sc[nt][0] * scale + mk0;
            float a1 = sc[nt][1] * scale + mk1;
            float b0 = sc[nt][2] * scale + mk0;
            float b1 = sc[nt][3] * scale + mk1;
            if (win >= 0) {
                if (abs(qpos0 - kp0) > win) a0 = -1e30f;
                if (abs(qpos0 - kp1) > win) a1 = -1e30f;
                if (abs(qpos1 - kp0) > win) b0 = -1e30f;
                if (abs(qpos1 - kp1) > win) b1 = -1e30f;
            }
            v0[nt * 2] = a0; v0[nt * 2 + 1] = a1;
            v1[nt * 2] = b0; v1[nt * 2 + 1] = b1;
        }
        float tm0 = -1e30f, tm1 = -1e30f;
        #pragma unroll
        for (int j = 0; j < 8; j++) { tm0 = fmaxf(tm0, v0[j]); tm1 = fmaxf(tm1, v1[j]); }
        tm0 = fmaxf(tm0, __shfl_xor_sync(0xffffffffu, tm0, 1));
        tm0 = fmaxf(tm0, __shfl_xor_sync(0xffffffffu, tm0, 2));
        tm1 = fmaxf(tm1, __shfl_xor_sync(0xffffffffu, tm1, 1));
        tm1 = fmaxf(tm1, __shfl_xor_sync(0xffffffffu, tm1, 2));
        float nm0 = fmaxf(mr0, tm0), nm1 = fmaxf(mr1, tm1);
        float al0 = __expf(mr0 - nm0), al1 = __expf(mr1 - nm1);
        mr0 = nm0; mr1 = nm1;
        float ps0 = 0.f, ps1 = 0.f;
        #pragma unroll
        for (int nt = 0; nt < 4; nt++) {
            float p00 = __expf(v0[nt * 2]     - nm0);
            float p01 = __expf(v0[nt * 2 + 1] - nm0);
            float p10 = __expf(v1[nt * 2]     - nm1);
            float p11 = __expf(v1[nt * 2 + 1] - nm1);
            ps0 += p00 + p01; ps1 += p10 + p11;
            int col = nt * 8 + 2 * tg;
            *(__half2*)&Psh[(m0 + grp) * PSH + col]     = __floats2half2_rn(p00, p01);
            *(__half2*)&Psh[(m0 + grp + 8) * PSH + col] = __floats2half2_rn(p10, p11);
        }
        ps0 += __shfl_xor_sync(0xffffffffu, ps0, 1);
        ps0 += __shfl_xor_sync(0xffffffffu, ps0, 2);
        ps1 += __shfl_xor_sync(0xffffffffu, ps1, 1);
        ps1 += __shfl_xor_sync(0xffffffffu, ps1, 2);
        l0 = l0 * al0 + ps0;
        l1 = l1 * al1 + ps1;
        #pragma unroll
        for (int nt = 0; nt < 8; nt++) {
            oacc[nt][0] *= al0; oacc[nt][1] *= al0;
            oacc[nt][2] *= al1; oacc[nt][3] *= al1;
        }
        __syncwarp();

        // ---- P @ V (fp16 MMA, ldmatrix.trans for V) ----
        #pragma unroll
        for (int s = 0; s < 2; s++) {
            unsigned a[4];
            int kb = s * 16 + 2 * tg;
            a[0] = *(unsigned*)&Psh[(m0 + grp) * PSH + kb];
            a[1] = *(unsigned*)&Psh[(m0 + grp + 8) * PSH + kb];
            a[2] = *(unsigned*)&Psh[(m0 + grp) * PSH + kb + 8];
            a[3] = *(unsigned*)&Psh[(m0 + grp + 8) * PSH + kb + 8];
            unsigned sOfs = (unsigned)(s * 16 * VSH * 2);
            #pragma unroll
            for (int nb = 0; nb < 4; nb++) {
                unsigned bq[4];
                LDSM4T(bq, vBase + sOfs + (unsigned)(nb * 32));
                unsigned bb0[2] = { bq[0], bq[1] };
                unsigned bb1[2] = { bq[2], bq[3] };
                MMA_F16(oacc[2 * nb],     a, bb0);
                MMA_F16(oacc[2 * nb + 1], a, bb1);
            }
        }
    }

    float il0 = 1.0f / l0, il1 = 1.0f / l1;
    #pragma unroll
    for (int nt = 0; nt < 8; nt++) {
        int col = h * HD_ + nt * 8 + 2 * tg;
        __half2* p0 = (__half2*)(out + (size_t)(b * S_ + qpos0) * (H_ * HD_) + col);
        __half2* p1 = (__half2*)(out + (size_t)(b * S_ + qpos1) * (H_ * HD_) + col);
        *p0 = __floats2half2_rn(oacc[nt][0] * il0, oacc[nt][1] * il0);
        *p1 = __floats2half2_rn(oacc[nt][2] * il1, oacc[nt][3] * il1);
    }
}

// ---------------- SwiGLU elementwise: gateh = fp16(silu(gate) * up), all fp16 I/O ------
__global__ void silu_mul_kernel(const __half* __restrict__ gate,
                                const __half* __restrict__ up,
                                __half* __restrict__ outh, int n4) {
    int i = blockIdx.x * blockDim.x + threadIdx.x;
    if (i < n4) {
        __half2 g0 = *(const __half2*)(gate + (size_t)i * 4);
        __half2 g1 = *(const __half2*)(gate + (size_t)i * 4 + 2);
        __half2 u0 = *(const __half2*)(up + (size_t)i * 4);
        __half2 u1 = *(const __half2*)(up + (size_t)i * 4 + 2);
        float gx = __half2float(g0.x), gy = __half2float(g0.y);
        float gz = __half2float(g1.x), gw = __half2float(g1.y);
        float r0 = gx / (1.0f + __expf(-gx)) * __half2float(u0.x);
        float r1 = gy / (1.0f + __expf(-gy)) * __half2float(u0.y);
        float r2 = gz / (1.0f + __expf(-gz)) * __half2float(u1.x);
        float r3 = gw / (1.0f + __expf(-gw)) * __half2float(u1.y);
        __half2* dst = (__half2*)(outh + (size_t)i * 4);
        dst[0] = __floats2half2_rn(r0, r1);
        dst[1] = __floats2half2_rn(r2, r3);
    }
}

// ---------------- host orchestration ----------------
extern "C" void kernel_launch(void* const* d_in, const int* in_sizes, int n_in,
                              void* d_out, int out_size) {
    const float* x      = (const float*)d_in[0];
    const float* wq     = (const float*)d_in[1];
    const float* wk     = (const float*)d_in[2];
    const float* wv     = (const float*)d_in[3];
    const float* wo     = (const float*)d_in[4];
    const float* qnw    = (const float*)d_in[5];
    const float* knw    = (const float*)d_in[6];
    const float* ln1    = (const float*)d_in[7];
    const float* ln2    = (const float*)d_in[8];
    const float* wg     = (const float*)d_in[9];
    const float* wu     = (const float*)d_in[10];
    const float* wd     = (const float*)d_in[11];
    const float* normw  = (const float*)d_in[12];
    const int*   amask  = (const int*)d_in[13];

    float *h;
    __half *q, *k, *v, *gate, *up, *nh, *atth, *gateh;
    __half *wqt, *wkt, *wvt, *wot, *wgt, *wut, *wdt;
    cudaGetSymbolAddress((void**)&h,     g_h);
    cudaGetSymbolAddress((void**)&q,     g_q);
    cudaGetSymbolAddress((void**)&k,     g_k);
    cudaGetSymbolAddress((void**)&v,     g_v);
    cudaGetSymbolAddress((void**)&gate,  g_gate);
    cudaGetSymbolAddress((void**)&up,    g_up);
    cudaGetSymbolAddress((void**)&nh,    g_nh);
    cudaGetSymbolAddress((void**)&atth,  g_atth);
    cudaGetSymbolAddress((void**)&gateh, g_gateh);
    cudaGetSymbolAddress((void**)&wqt,   g_wqt);
    cudaGetSymbolAddress((void**)&wkt,   g_wkt);
    cudaGetSymbolAddress((void**)&wvt,   g_wvt);
    cudaGetSymbolAddress((void**)&wot,   g_wot);
    cudaGetSymbolAddress((void**)&wgt,   g_wgt);
    cudaGetSymbolAddress((void**)&wut,   g_wut);
    cudaGetSymbolAddress((void**)&wdt,   g_wdt);

    cudaFuncSetAttribute(attn_mma_kernel,
        cudaFuncAttributeMaxDynamicSharedMemorySize, ATT_SMEM);

    // weight convert+transpose (coalesced): grid (K/64, N/32, L)
    dim3 tb(32, 8);
    convT_kernel<<<dim3(D_ / 64, (H_ * HD_) / 32, L_), tb>>>(wq, wqt, D_, H_ * HD_);
    convT_kernel<<<dim3(D_ / 64, (HK_ * HD_) / 32, L_), tb>>>(wk, wkt, D_, HK_ * HD_);
    convT_kernel<<<dim3(D_ / 64, (HK_ * HD_) / 32, L_), tb>>>(wv, wvt, D_, HK_ * HD_);
    convT_kernel<<<dim3((H_ * HD_) / 64, D_ / 32, L_), tb>>>(wo, wot, H_ * HD_, D_);
    convT_kernel<<<dim3(D_ / 64, FF_ / 32, L_), tb>>>(wg, wgt, D_, FF_);
    convT_kernel<<<dim3(D_ / 64, FF_ / 32, L_), tb>>>(wu, wut, D_, FF_);
    convT_kernel<<<dim3(FF_ / 64, D_ / 32, L_), tb>>>(wd, wdt, FF_, D_);

    cudaMemcpyAsync(h, x, (size_t)TOK_ * D_ * sizeof(float),
                    cudaMemcpyDeviceToDevice, 0);

    dim3 gQKV (16, TOK_ / 128);
    dim3 gGU  (48, TOK_ / 128);
    dim3 g1024(D_ / 128, TOK_ / 128);
    int ropeWarps = TOK_ * (H_ + HK_);

    for (int l = 0; l < L_; l++) {
        const __half* wqt_l = wqt + (size_t)l * D_ * H_ * HD_;
        const __half* wkt_l = wkt + (size_t)l * D_ * HK_ * HD_;
        const __half* wvt_l = wvt + (size_t)l * D_ * HK_ * HD_;
        const __half* wot_l = wot + (size_t)l * H_ * HD_ * D_;
        const __half* wgt_l = wgt + (size_t)l * D_ * FF_;
        const __half* wut_l = wut + (size_t)l * D_ * FF_;
        const __half* wdt_l = wdt + (size_t)l * FF_ * D_;

        rmsnorm_h_kernel<<<TOK_, 256>>>(h, ln1 + l * D_, nh);

        gemm_qkv_h<<<gQKV, 256>>>(nh, wqt_l, wkt_l, wvt_l, q, k, v);

        qknorm_rope_kernel<<<ropeWarps / 4, 128>>>(q, k, qnw + l * HD_, knw + l * HD_);

        attn_mma_kernel<<<dim3(S_ / 64, HK_, B_), 256, ATT_SMEM>>>(
            q, k, v, amask, atth, (l & 1) ? WIN_ : -1);

        gemm_h<true><<<g1024, 256>>>(atth, wot_l, h, D_, H_ * HD_);

        rmsnorm_h_kernel<<<TOK_, 256>>>(h, ln2 + l * D_, nh);

        gemm_gateup_h<<<gGU, 256>>>(nh, wgt_l, wut_l, gate, up);

        int n4 = TOK_ * FF_ / 4;
        silu_mul_kernel<<<(n4 + 255) / 256, 256>>>(gate, up, gateh, n4);

        gemm_h<true><<<g1024, 256>>>(gateh, wdt_l, h, D_, FF_);
    }

    rmsnorm_kernel<<<TOK_, 256>>>(h, normw, (float*)d_out);
}